// round 1
// baseline (speedup 1.0000x reference)
#include <cuda_runtime.h>
#include <math.h>

#define Bb   4
#define Ll   1024
#define DIN_ 768
#define Ww   12288
#define Hh   8
#define NLAY 2
#define DBb  192
#define HDd  24
#define TOPK 32
#define NROWS (Bb*Ll)          /* 4096 */
#define LAMBDA (1.0f/(4.0f*768.0f))

/* ---------------- scratch (device globals; no allocation allowed) -------- */
__device__ float g_x[NROWS*DIN_];
__device__ float g_z[NROWS*Ww];      /* z_in, later reused as z_pred_ */
__device__ float g_zpred[NROWS*Ww];
__device__ float g_q[NROWS*DBb];
__device__ float g_k[NROWS*DBb];
__device__ float g_v[NROWS*DBb];
__device__ float g_o[NROWS*DBb];
__device__ float g_Dz[NROWS*DIN_];
__device__ float g_s[NROWS];
__device__ float g_tv[NROWS*TOPK];
__device__ int   g_ti[NROWS*TOPK];

/* ---------------- generic tiled GEMM ------------------------------------ */
/* C[M,N] = epilogue(alpha * A x B)
   BLAYOUT 0: B is [K,N] row-major (ldb = N stride)   ("NN")
   BLAYOUT 1: B is [N,K] row-major (ldb = K stride)   ("NT")
   flags: bit0 = relu, bit1 = add bias[gn]
   shiftA: row gm of A reads A[gm-1] (zeros when gm % Ll == 0)  (z_ctx shift) */
template<int BLAYOUT>
__global__ __launch_bounds__(256)
void gemm_kernel(const float* __restrict__ A, const float* __restrict__ B,
                 const float* __restrict__ bias, float* __restrict__ C,
                 int M, int N, int K, int lda, int ldb,
                 float alpha, int flags, int shiftA)
{
    const int tid = threadIdx.x;
    const int m0 = blockIdx.y * 128;
    const int n0 = blockIdx.x * 128;

    __shared__ float As[16][128];
    __shared__ float Bs[16][132];

    float acc[8][8];
#pragma unroll
    for (int i = 0; i < 8; i++)
#pragma unroll
        for (int j = 0; j < 8; j++) acc[i][j] = 0.f;

    const int ty = tid >> 4, tx = tid & 15;
    const int lr = tid >> 2;          /* 0..63 */
    const int lk = (tid & 3) * 4;     /* 0,4,8,12 */

    for (int k0 = 0; k0 < K; k0 += 16) {
        /* ---- A tile: [128 rows][16 k], scatter-transpose into As[k][m] */
#pragma unroll
        for (int i = 0; i < 2; i++) {
            int m  = lr + i * 64;
            int gm = m0 + m;
            float4 av = make_float4(0.f, 0.f, 0.f, 0.f);
            if (shiftA) {
                if ((gm & (Ll - 1)) != 0)
                    av = *reinterpret_cast<const float4*>(&A[(size_t)(gm - 1) * lda + k0 + lk]);
            } else {
                av = *reinterpret_cast<const float4*>(&A[(size_t)gm * lda + k0 + lk]);
            }
            As[lk + 0][m] = av.x; As[lk + 1][m] = av.y;
            As[lk + 2][m] = av.z; As[lk + 3][m] = av.w;
        }
        /* ---- B tile */
        if (BLAYOUT == 0) {
#pragma unroll
            for (int i = 0; i < 2; i++) {
                int r  = (tid >> 5) + i * 8;   /* 0..15 */
                int c  = (tid & 31) * 4;       /* 0..124 */
                int gn = n0 + c;
                float4 bv;
                if (gn + 3 < N) {
                    bv = *reinterpret_cast<const float4*>(&B[(size_t)(k0 + r) * ldb + gn]);
                } else {
                    bv.x = (gn + 0 < N) ? B[(size_t)(k0 + r) * ldb + gn + 0] : 0.f;
                    bv.y = (gn + 1 < N) ? B[(size_t)(k0 + r) * ldb + gn + 1] : 0.f;
                    bv.z = (gn + 2 < N) ? B[(size_t)(k0 + r) * ldb + gn + 2] : 0.f;
                    bv.w = (gn + 3 < N) ? B[(size_t)(k0 + r) * ldb + gn + 3] : 0.f;
                }
                *reinterpret_cast<float4*>(&Bs[r][c]) = bv;
            }
        } else {
#pragma unroll
            for (int i = 0; i < 2; i++) {
                int n  = lr + i * 64;
                int gn = n0 + n;
                float4 bv = make_float4(0.f, 0.f, 0.f, 0.f);
                if (gn < N)
                    bv = *reinterpret_cast<const float4*>(&B[(size_t)gn * ldb + k0 + lk]);
                Bs[lk + 0][n] = bv.x; Bs[lk + 1][n] = bv.y;
                Bs[lk + 2][n] = bv.z; Bs[lk + 3][n] = bv.w;
            }
        }
        __syncthreads();

#pragma unroll
        for (int kk = 0; kk < 16; kk++) {
            float ra[8], rb[8];
            float4 t0 = *reinterpret_cast<const float4*>(&As[kk][ty * 8]);
            float4 t1 = *reinterpret_cast<const float4*>(&As[kk][ty * 8 + 4]);
            ra[0]=t0.x; ra[1]=t0.y; ra[2]=t0.z; ra[3]=t0.w;
            ra[4]=t1.x; ra[5]=t1.y; ra[6]=t1.z; ra[7]=t1.w;
            float4 u0 = *reinterpret_cast<const float4*>(&Bs[kk][tx * 8]);
            float4 u1 = *reinterpret_cast<const float4*>(&Bs[kk][tx * 8 + 4]);
            rb[0]=u0.x; rb[1]=u0.y; rb[2]=u0.z; rb[3]=u0.w;
            rb[4]=u1.x; rb[5]=u1.y; rb[6]=u1.z; rb[7]=u1.w;
#pragma unroll
            for (int i = 0; i < 8; i++)
#pragma unroll
                for (int j = 0; j < 8; j++)
                    acc[i][j] += ra[i] * rb[j];
        }
        __syncthreads();
    }

#pragma unroll
    for (int i = 0; i < 8; i++) {
        int gm = m0 + ty * 8 + i;
#pragma unroll
        for (int j = 0; j < 8; j++) {
            int gn = n0 + tx * 8 + j;
            if (gn < N) {
                float v = acc[i][j] * alpha;
                if (flags & 2) v += bias[gn];
                if (flags & 1) v = fmaxf(v, 0.f);
                C[(size_t)gm * N + gn] = v;
            }
        }
    }
}

/* ---------------- causal flash attention (HD=24) ------------------------- */
__global__ __launch_bounds__(128)
void attn_kernel(const float* __restrict__ qb, const float* __restrict__ kb,
                 const float* __restrict__ vb, float* __restrict__ ob)
{
    const int qt  = blockIdx.x, h = blockIdx.y, bz = blockIdx.z;
    const int tid = threadIdx.x;
    const int qi  = qt * 128 + tid;
    const size_t rowbase = ((size_t)bz * Ll) * DBb + (size_t)h * HDd;

    float qreg[HDd];
    const float* qp = qb + rowbase + (size_t)qi * DBb;
#pragma unroll
    for (int d = 0; d < HDd; d++) qreg[d] = qp[d];

    const float scale = rsqrtf((float)HDd);
    float m = -1e30f, l = 0.f, o[HDd];
#pragma unroll
    for (int d = 0; d < HDd; d++) o[d] = 0.f;

    __shared__ float Ks[128][HDd + 1];
    __shared__ float Vs[128][HDd + 1];

    for (int kt = 0; kt <= qt; kt++) {
        for (int e = tid; e < 128 * HDd; e += 128) {
            int j = e / HDd, d = e - j * HDd;
            size_t g = rowbase + (size_t)(kt * 128 + j) * DBb + d;
            Ks[j][d] = kb[g];
            Vs[j][d] = vb[g];
        }
        __syncthreads();
        int jmax = min(128, qi - kt * 128 + 1);
        for (int j = 0; j < jmax; j++) {
            float sdot = 0.f;
#pragma unroll
            for (int d = 0; d < HDd; d++) sdot += qreg[d] * Ks[j][d];
            sdot *= scale;
            float mn = fmaxf(m, sdot);
            float c  = __expf(m - mn);
            float p  = __expf(sdot - mn);
            l = l * c + p;
#pragma unroll
            for (int d = 0; d < HDd; d++) o[d] = o[d] * c + p * Vs[j][d];
            m = mn;
        }
        __syncthreads();
    }
    float inv = 1.f / l;
    float* op = ob + rowbase + (size_t)qi * DBb;
#pragma unroll
    for (int d = 0; d < HDd; d++) op[d] = o[d] * inv;
}

/* ---------------- small element/row kernels ------------------------------ */
__global__ void sub_bias_kernel(const float* __restrict__ xin,
                                const float* __restrict__ b,
                                float* __restrict__ x)
{
    int n = blockIdx.y, d = blockIdx.x * 256 + threadIdx.x;
    x[(size_t)n * DIN_ + d] = xin[(size_t)n * DIN_ + d] - b[d];
}

__global__ void rowstats_kernel(const float* __restrict__ Dz,
                                const float* __restrict__ x,
                                float* __restrict__ s)
{
    int n = blockIdx.x, tid = threadIdx.x;
    const float* dzr = Dz + (size_t)n * DIN_;
    const float* xr  = x  + (size_t)n * DIN_;
    float ss = 0.f, dt = 0.f;
    for (int i = tid; i < DIN_; i += 256) {
        float d = dzr[i];
        ss += d * d;
        dt += d * xr[i];
    }
#pragma unroll
    for (int o = 16; o; o >>= 1) {
        ss += __shfl_down_sync(0xffffffffu, ss, o);
        dt += __shfl_down_sync(0xffffffffu, dt, o);
    }
    __shared__ float a1[8], a2[8];
    if ((tid & 31) == 0) { a1[tid >> 5] = ss; a2[tid >> 5] = dt; }
    __syncthreads();
    if (tid == 0) {
        float S = 0.f, T = 0.f;
#pragma unroll
        for (int i = 0; i < 8; i++) { S += a1[i]; T += a2[i]; }
        float nrm = sqrtf(S) + 1e-6f;
        s[n] = T / (nrm * nrm);
    }
}

__global__ void zpred_update_kernel(const float* __restrict__ zp_,
                                    const float* __restrict__ s,
                                    float* __restrict__ zpred, int first)
{
    int n = blockIdx.y;
    int w = blockIdx.x * 256 + threadIdx.x;
    size_t idx = (size_t)n * Ww + w;
    float v = s[n] * zp_[idx];
    zpred[idx] = first ? v : (zpred[idx] + v);
}

__global__ void x_update_kernel(const float* __restrict__ Dz,
                                const float* __restrict__ s,
                                float* __restrict__ x)
{
    int n = blockIdx.y;
    int d = blockIdx.x * 256 + threadIdx.x;
    size_t idx = (size_t)n * DIN_ + d;
    x[idx] -= s[n] * Dz[idx];
}

/* ---------------- top-32 per row (iterative argmax over smem row) -------- */
__global__ void topk_kernel(const float* __restrict__ z,
                            float* __restrict__ tv, int* __restrict__ ti)
{
    extern __shared__ float sh[];            /* Ww floats */
    __shared__ float rv[256];
    __shared__ int   ri[256];
    int row = blockIdx.x, tid = threadIdx.x;
    const float* zr = z + (size_t)row * Ww;
    for (int i = tid; i < Ww; i += 256) sh[i] = zr[i];
    __syncthreads();
    for (int it = 0; it < TOPK; it++) {
        float bm = -1.f; int bi = 0;
        for (int i = tid; i < Ww; i += 256) {
            float v = sh[i];
            if (v > bm) { bm = v; bi = i; }
        }
        rv[tid] = bm; ri[tid] = bi;
        __syncthreads();
        for (int sred = 128; sred > 0; sred >>= 1) {
            if (tid < sred) {
                float v2 = rv[tid + sred]; int i2 = ri[tid + sred];
                if (v2 > rv[tid] || (v2 == rv[tid] && i2 < ri[tid])) {
                    rv[tid] = v2; ri[tid] = i2;
                }
            }
            __syncthreads();
        }
        if (tid == 0) {
            tv[row * TOPK + it] = rv[0];
            ti[row * TOPK + it] = ri[0];
            sh[ri[0]] = -2.f;
        }
        __syncthreads();
    }
}

/* ---------------- sparse rank-32 add into recon output ------------------- */
__global__ void sparse_add_kernel(const float* __restrict__ tv,
                                  const int* __restrict__ ti,
                                  const float* __restrict__ D,
                                  float* __restrict__ out)
{
    __shared__ float sv[TOPK];
    __shared__ int   si[TOPK];
    int row = blockIdx.x, tid = threadIdx.x;
    if (tid < TOPK) { sv[tid] = tv[row * TOPK + tid]; si[tid] = ti[row * TOPK + tid]; }
    __syncthreads();
    for (int d = tid; d < DIN_; d += 256) {
        float a = out[(size_t)row * DIN_ + d];
#pragma unroll
        for (int j = 0; j < TOPK; j++)
            a += sv[j] * D[(size_t)si[j] * DIN_ + d];
        out[(size_t)row * DIN_ + d] = a;
    }
}

/* ---------------- driver -------------------------------------------------- */
extern "C" void kernel_launch(void* const* d_in, const int* in_sizes, int n_in,
                              void* d_out, int out_size)
{
    const float* x_in = (const float*)d_in[0];
    const float* D    = (const float*)d_in[1];
    const float* b    = (const float*)d_in[2];
    const float* Wq   = (const float*)d_in[3];
    const float* bq   = (const float*)d_in[4];
    const float* Wk   = (const float*)d_in[5];
    const float* bk   = (const float*)d_in[6];
    const float* Wv   = (const float*)d_in[7];
    const float* bv   = (const float*)d_in[8];
    const float* Wo   = (const float*)d_in[9];
    const float* bo   = (const float*)d_in[10];
    float* out = (float*)d_out;

    float *px, *pz, *pzp, *pq, *pk, *pv, *po, *pdz, *ps, *ptv;
    int* pti;
    cudaGetSymbolAddress((void**)&px,  g_x);
    cudaGetSymbolAddress((void**)&pz,  g_z);
    cudaGetSymbolAddress((void**)&pzp, g_zpred);
    cudaGetSymbolAddress((void**)&pq,  g_q);
    cudaGetSymbolAddress((void**)&pk,  g_k);
    cudaGetSymbolAddress((void**)&pv,  g_v);
    cudaGetSymbolAddress((void**)&po,  g_o);
    cudaGetSymbolAddress((void**)&pdz, g_Dz);
    cudaGetSymbolAddress((void**)&ps,  g_s);
    cudaGetSymbolAddress((void**)&ptv, g_tv);
    cudaGetSymbolAddress((void**)&pti, g_ti);

    cudaFuncSetAttribute(topk_kernel,
                         cudaFuncAttributeMaxDynamicSharedMemorySize,
                         Ww * (int)sizeof(float));

    dim3 blk(256);

    /* x = x_input - b */
    sub_bias_kernel<<<dim3(DIN_ / 256, NROWS), blk>>>(x_in, b, px);

    for (int i = 0; i < NLAY; i++) {
        /* z_in = relu(LAM * x @ D^T) */
        gemm_kernel<1><<<dim3(Ww / 128, NROWS / 128), blk>>>(
            px, D, nullptr, pz, NROWS, Ww, DIN_, DIN_, DIN_, LAMBDA, 1, 0);

        /* q / k / v (k,v read shifted rows of z_in) */
        gemm_kernel<0><<<dim3((DBb + 127) / 128, NROWS / 128), blk>>>(
            pz, Wq + (size_t)i * Ww * DBb, bq + (size_t)i * DBb, pq,
            NROWS, DBb, Ww, Ww, DBb, 1.f, 2, 0);
        gemm_kernel<0><<<dim3((DBb + 127) / 128, NROWS / 128), blk>>>(
            pz, Wk + (size_t)i * Ww * DBb, bk + (size_t)i * DBb, pk,
            NROWS, DBb, Ww, Ww, DBb, 1.f, 2, 1);
        gemm_kernel<0><<<dim3((DBb + 127) / 128, NROWS / 128), blk>>>(
            pz, Wv + (size_t)i * Ww * DBb, bv + (size_t)i * DBb, pv,
            NROWS, DBb, Ww, Ww, DBb, 1.f, 2, 1);

        attn_kernel<<<dim3(Ll / 128, Hh, Bb), dim3(128)>>>(pq, pk, pv, po);

        /* z_pred_ = relu(o @ Wo + bo)  (overwrites z_in buffer) */
        gemm_kernel<0><<<dim3(Ww / 128, NROWS / 128), blk>>>(
            po, Wo + (size_t)i * DBb * Ww, bo + (size_t)i * Ww, pz,
            NROWS, Ww, DBb, DBb, Ww, 1.f, 3, 0);

        /* Dz = z_pred_ @ D */
        gemm_kernel<0><<<dim3(DIN_ / 128, NROWS / 128), blk>>>(
            pz, D, nullptr, pdz, NROWS, DIN_, Ww, Ww, DIN_, 1.f, 0, 0);

        rowstats_kernel<<<NROWS, 256>>>(pdz, px, ps);
        zpred_update_kernel<<<dim3(Ww / 256, NROWS), blk>>>(pz, ps, pzp, i == 0);
        x_update_kernel<<<dim3(DIN_ / 256, NROWS), blk>>>(pdz, ps, px);
    }

    /* z_novel = relu(LAM * x @ D^T) */
    gemm_kernel<1><<<dim3(Ww / 128, NROWS / 128), blk>>>(
        px, D, nullptr, pz, NROWS, Ww, DIN_, DIN_, DIN_, LAMBDA, 1, 0);

    topk_kernel<<<NROWS, 256, Ww * (int)sizeof(float)>>>(pz, ptv, pti);

    /* out = z_pred @ D + b, then add top-32 sparse codes */
    gemm_kernel<0><<<dim3(DIN_ / 128, NROWS / 128), blk>>>(
        pzp, D, b, out, NROWS, DIN_, Ww, Ww, DIN_, 1.f, 2, 0);

    sparse_add_kernel<<<NROWS, 256>>>(ptv, pti, D, out);
}

// round 7
// speedup vs baseline: 2.0005x; 2.0005x over previous
#include <cuda_runtime.h>
#include <math.h>
#include <stdint.h>

#define Bb   4
#define Ll   1024
#define DIN_ 768
#define Ww   12288
#define Hh   8
#define NLAY 2
#define DBb  192
#define HDd  24
#define TOPK 32
#define NROWS (Bb*Ll)          /* 4096 */
#define LAMBDA (1.0f/(4.0f*768.0f))

/* ---------------- scratch (device globals; no allocation allowed) -------- */
__device__ float g_x[NROWS*DIN_];
__device__ float g_z[NROWS*Ww];      /* z_in, later reused as z_pred_ */
__device__ float g_zpred[NROWS*Ww];
__device__ float g_q[NROWS*DBb];
__device__ float g_k[NROWS*DBb];
__device__ float g_v[NROWS*DBb];
__device__ float g_o[NROWS*DBb];
__device__ float g_Dz[NROWS*DIN_];
__device__ float g_s[NROWS];
__device__ float g_tv[NROWS*TOPK];
__device__ int   g_ti[NROWS*TOPK];

/* ---------------- tf32 helpers ------------------------------------------ */
__device__ __forceinline__ uint32_t f2tf(float f)
{
    uint32_t r;
    asm("cvt.rna.tf32.f32 %0, %1;" : "=r"(r) : "f"(f));
    return r;
}

__device__ __forceinline__ void mma8(float* c,
                                     uint32_t a0, uint32_t a1, uint32_t a2, uint32_t a3,
                                     uint32_t b0, uint32_t b1)
{
    asm volatile(
        "mma.sync.aligned.m16n8k8.row.col.f32.tf32.tf32.f32 "
        "{%0,%1,%2,%3},{%4,%5,%6,%7},{%8,%9},{%0,%1,%2,%3};"
        : "+f"(c[0]), "+f"(c[1]), "+f"(c[2]), "+f"(c[3])
        : "r"(a0), "r"(a1), "r"(a2), "r"(a3), "r"(b0), "r"(b1));
}

/* ---------------- tensor-core GEMM --------------------------------------
   C[M,N] = epilogue(alpha * A x B)
   BLAYOUT 0: B is [K,N] row-major ("NN")  -> Bs staged [k][n], stride 132
   BLAYOUT 1: B is [N,K] row-major ("NT")  -> Bs staged [n][p(k)], stride 36
   A staged [m][p(k)], stride 36, p(k) = (k>>2) + 8*(k&3)
   flags: bit0 = relu, bit1 = add bias[gn]
   shiftA: row gm of A reads A[gm-1] (zeros when gm % Ll == 0)               */
template<int BLAYOUT>
__global__ __launch_bounds__(256, 2)
void gemm_tc(const float* __restrict__ A, const float* __restrict__ B,
             const float* __restrict__ bias, float* __restrict__ C,
             int M, int N, int K, int lda, int ldb,
             float alpha, int flags, int shiftA)
{
    __shared__ uint32_t As[128 * 36];
    __shared__ uint32_t Bs[128 * 36];   /* covers 32*132 for BLAYOUT 0 too */

    const int tid  = threadIdx.x;
    const int m0   = blockIdx.y * 128;
    const int n0   = blockIdx.x * 128;
    const int warp = tid >> 5, lane = tid & 31;
    const int g    = lane >> 2, tg = lane & 3;
    const int wm0  = (warp & 1) * 64;
    const int wn0  = (warp >> 1) * 32;

    float acc[4][4][4];
#pragma unroll
    for (int mf = 0; mf < 4; mf++)
#pragma unroll
        for (int nf = 0; nf < 4; nf++)
#pragma unroll
            for (int e = 0; e < 4; e++) acc[mf][nf][e] = 0.f;

    /* staging decomposition: 32 k-cols per tile
       lr2 = row stepper (0..31), lt covers k = 4*lt .. 4*lt+3 */
    const int lr2 = tid >> 3;         /* 0..31 */
    const int lt  = tid & 7;          /* 0..7  */

    for (int k0 = 0; k0 < K; k0 += 32) {
        /* ---- stage A: 128 x 32, permuted cols (full k coverage) ---- */
#pragma unroll
        for (int i = 0; i < 4; i++) {
            int m  = lr2 + i * 32;
            int gm = m0 + m;
            float4 av = make_float4(0.f, 0.f, 0.f, 0.f);
            if (shiftA) {
                if ((gm & (Ll - 1)) != 0)
                    av = *reinterpret_cast<const float4*>(&A[(size_t)(gm - 1) * lda + k0 + lt * 4]);
            } else {
                av = *reinterpret_cast<const float4*>(&A[(size_t)gm * lda + k0 + lt * 4]);
            }
            uint32_t* dst = &As[m * 36 + lt];
            dst[0]  = f2tf(av.x);
            dst[8]  = f2tf(av.y);
            dst[16] = f2tf(av.z);
            dst[24] = f2tf(av.w);
        }

        /* ---- stage B ---- */
        if (BLAYOUT == 1) {
#pragma unroll
            for (int i = 0; i < 4; i++) {
                int n  = lr2 + i * 32;
                int gn = n0 + n;
                float4 bv = make_float4(0.f, 0.f, 0.f, 0.f);
                if (gn < N)
                    bv = *reinterpret_cast<const float4*>(&B[(size_t)gn * ldb + k0 + lt * 4]);
                uint32_t* dst = &Bs[n * 36 + lt];
                dst[0]  = f2tf(bv.x);
                dst[8]  = f2tf(bv.y);
                dst[16] = f2tf(bv.z);
                dst[24] = f2tf(bv.w);
            }
        } else {
#pragma unroll
            for (int i = 0; i < 4; i++) {
                int r  = (tid >> 5) + i * 8;   /* k row 0..31 */
                int c  = (tid & 31) * 4;       /* n 0..124 */
                int gn = n0 + c;
                float4 bv;
                const float* bp = &B[(size_t)(k0 + r) * ldb + gn];
                if (gn + 3 < N) {
                    bv = *reinterpret_cast<const float4*>(bp);
                } else {
                    bv.x = (gn + 0 < N) ? bp[0] : 0.f;
                    bv.y = (gn + 1 < N) ? bp[1] : 0.f;
                    bv.z = (gn + 2 < N) ? bp[2] : 0.f;
                    bv.w = (gn + 3 < N) ? bp[3] : 0.f;
                }
                uint32_t* dst = &Bs[r * 132 + c];
                dst[0] = f2tf(bv.x);
                dst[1] = f2tf(bv.y);
                dst[2] = f2tf(bv.z);
                dst[3] = f2tf(bv.w);
            }
        }
        __syncthreads();

        /* ---- compute: 64 mmas / warp / k-chunk ---- */
#pragma unroll
        for (int h = 0; h < 2; h++) {
            uint4 Av[4][2];
#pragma unroll
            for (int mf = 0; mf < 4; mf++) {
                int r0 = wm0 + mf * 16 + g;
                Av[mf][0] = *reinterpret_cast<const uint4*>(&As[r0 * 36 + tg * 8 + h * 4]);
                Av[mf][1] = *reinterpret_cast<const uint4*>(&As[(r0 + 8) * 36 + tg * 8 + h * 4]);
            }
            if (BLAYOUT == 1) {
                uint4 Bv[4];
#pragma unroll
                for (int nf = 0; nf < 4; nf++)
                    Bv[nf] = *reinterpret_cast<const uint4*>(
                        &Bs[(wn0 + nf * 8 + g) * 36 + tg * 8 + h * 4]);
#pragma unroll
                for (int kk = 0; kk < 2; kk++) {
#pragma unroll
                    for (int mf = 0; mf < 4; mf++)
#pragma unroll
                        for (int nf = 0; nf < 4; nf++) {
                            uint32_t a0 = kk ? Av[mf][0].z : Av[mf][0].x;
                            uint32_t a2 = kk ? Av[mf][0].w : Av[mf][0].y;
                            uint32_t a1 = kk ? Av[mf][1].z : Av[mf][1].x;
                            uint32_t a3 = kk ? Av[mf][1].w : Av[mf][1].y;
                            uint32_t b0 = kk ? Bv[nf].z : Bv[nf].x;
                            uint32_t b1 = kk ? Bv[nf].w : Bv[nf].y;
                            mma8(acc[mf][nf], a0, a1, a2, a3, b0, b1);
                        }
                }
            } else {
#pragma unroll
                for (int kk = 0; kk < 2; kk++) {
                    int kg = 2 * h + kk;
#pragma unroll
                    for (int nf = 0; nf < 4; nf++) {
                        int nn = wn0 + nf * 8 + g;
                        uint32_t b0 = Bs[(kg * 8 + tg) * 132 + nn];
                        uint32_t b1 = Bs[(kg * 8 + tg + 4) * 132 + nn];
#pragma unroll
                        for (int mf = 0; mf < 4; mf++) {
                            uint32_t a0 = kk ? Av[mf][0].z : Av[mf][0].x;
                            uint32_t a2 = kk ? Av[mf][0].w : Av[mf][0].y;
                            uint32_t a1 = kk ? Av[mf][1].z : Av[mf][1].x;
                            uint32_t a3 = kk ? Av[mf][1].w : Av[mf][1].y;
                            mma8(acc[mf][nf], a0, a1, a2, a3, b0, b1);
                        }
                    }
                }
            }
        }
        __syncthreads();
    }

    /* ---- epilogue ---- */
#pragma unroll
    for (int mf = 0; mf < 4; mf++) {
#pragma unroll
        for (int nf = 0; nf < 4; nf++) {
            int gm = m0 + wm0 + mf * 16 + g;
            int gn = n0 + wn0 + nf * 8 + 2 * tg;
            if (gn < N) {
                float bsum  = (flags & 2) ? bias[gn] : 0.f;
                float bsum1 = (flags & 2) ? bias[gn + 1] : 0.f;
                float v0 = acc[mf][nf][0] * alpha + bsum;
                float v1 = acc[mf][nf][1] * alpha + bsum1;
                float v2 = acc[mf][nf][2] * alpha + bsum;
                float v3 = acc[mf][nf][3] * alpha + bsum1;
                if (flags & 1) {
                    v0 = fmaxf(v0, 0.f); v1 = fmaxf(v1, 0.f);
                    v2 = fmaxf(v2, 0.f); v3 = fmaxf(v3, 0.f);
                }
                *reinterpret_cast<float2*>(&C[(size_t)gm * N + gn])       = make_float2(v0, v1);
                *reinterpret_cast<float2*>(&C[(size_t)(gm + 8) * N + gn]) = make_float2(v2, v3);
            }
        }
    }
}

/* ---------------- causal flash attention (HD=24) ------------------------- */
__global__ __launch_bounds__(128)
void attn_kernel(const float* __restrict__ qb, const float* __restrict__ kb,
                 const float* __restrict__ vb, float* __restrict__ ob)
{
    const int qt  = blockIdx.x, h = blockIdx.y, bz = blockIdx.z;
    const int tid = threadIdx.x;
    const int qi  = qt * 128 + tid;
    const size_t rowbase = ((size_t)bz * Ll) * DBb + (size_t)h * HDd;

    float qreg[HDd];
    const float* qp = qb + rowbase + (size_t)qi * DBb;
#pragma unroll
    for (int d = 0; d < HDd; d++) qreg[d] = qp[d];

    const float scale = rsqrtf((float)HDd);
    float m = -1e30f, l = 0.f, o[HDd];
#pragma unroll
    for (int d = 0; d < HDd; d++) o[d] = 0.f;

    __shared__ float Ks[128][HDd + 1];
    __shared__ float Vs[128][HDd + 1];

    for (int kt = 0; kt <= qt; kt++) {
        for (int e = tid; e < 128 * HDd; e += 128) {
            int j = e / HDd, d = e - j * HDd;
            size_t gidx = rowbase + (size_t)(kt * 128 + j) * DBb + d;
            Ks[j][d] = kb[gidx];
            Vs[j][d] = vb[gidx];
        }
        __syncthreads();
        int jmax = min(128, qi - kt * 128 + 1);
        for (int j = 0; j < jmax; j++) {
            float sdot = 0.f;
#pragma unroll
            for (int d = 0; d < HDd; d++) sdot += qreg[d] * Ks[j][d];
            sdot *= scale;
            float mn = fmaxf(m, sdot);
            float c  = __expf(m - mn);
            float p  = __expf(sdot - mn);
            l = l * c + p;
#pragma unroll
            for (int d = 0; d < HDd; d++) o[d] = o[d] * c + p * Vs[j][d];
            m = mn;
        }
        __syncthreads();
    }
    float inv = 1.f / l;
    float* op = ob + rowbase + (size_t)qi * DBb;
#pragma unroll
    for (int d = 0; d < HDd; d++) op[d] = o[d] * inv;
}

/* ---------------- small element/row kernels ------------------------------ */
__global__ void sub_bias_kernel(const float* __restrict__ xin,
                                const float* __restrict__ b,
                                float* __restrict__ x)
{
    int n = blockIdx.y, d = blockIdx.x * 256 + threadIdx.x;
    x[(size_t)n * DIN_ + d] = xin[(size_t)n * DIN_ + d] - b[d];
}

__global__ void rowstats_kernel(const float* __restrict__ Dz,
                                const float* __restrict__ x,
                                float* __restrict__ s)
{
    int n = blockIdx.x, tid = threadIdx.x;
    const float* dzr = Dz + (size_t)n * DIN_;
    const float* xr  = x  + (size_t)n * DIN_;
    float ss = 0.f, dt = 0.f;
    for (int i = tid; i < DIN_; i += 256) {
        float d = dzr[i];
        ss += d * d;
        dt += d * xr[i];
    }
#pragma unroll
    for (int o = 16; o; o >>= 1) {
        ss += __shfl_down_sync(0xffffffffu, ss, o);
        dt += __shfl_down_sync(0xffffffffu, dt, o);
    }
    __shared__ float a1[8], a2[8];
    if ((tid & 31) == 0) { a1[tid >> 5] = ss; a2[tid >> 5] = dt; }
    __syncthreads();
    if (tid == 0) {
        float S = 0.f, T = 0.f;
#pragma unroll
        for (int i = 0; i < 8; i++) { S += a1[i]; T += a2[i]; }
        float nrm = sqrtf(S) + 1e-6f;
        s[n] = T / (nrm * nrm);
    }
}

__global__ void zpred_update_kernel(const float* __restrict__ zp_,
                                    const float* __restrict__ s,
                                    float* __restrict__ zpred, int first)
{
    int n = blockIdx.y;
    int w = blockIdx.x * 256 + threadIdx.x;
    size_t idx = (size_t)n * Ww + w;
    float v = s[n] * zp_[idx];
    zpred[idx] = first ? v : (zpred[idx] + v);
}

__global__ void x_update_kernel(const float* __restrict__ Dz,
                                const float* __restrict__ s,
                                float* __restrict__ x)
{
    int n = blockIdx.y;
    int d = blockIdx.x * 256 + threadIdx.x;
    size_t idx = (size_t)n * DIN_ + d;
    x[idx] -= s[n] * Dz[idx];
}

/* ---------------- top-32 per row (iterative argmax over smem row) -------- */
__global__ void topk_kernel(const float* __restrict__ z,
                            float* __restrict__ tv, int* __restrict__ ti)
{
    extern __shared__ float sh[];            /* Ww floats */
    __shared__ float rv[256];
    __shared__ int   ri[256];
    int row = blockIdx.x, tid = threadIdx.x;
    const float* zr = z + (size_t)row * Ww;
    for (int i = tid; i < Ww; i += 256) sh[i] = zr[i];
    __syncthreads();
    for (int it = 0; it < TOPK; it++) {
        float bm = -1.f; int bi = 0;
        for (int i = tid; i < Ww; i += 256) {
            float v = sh[i];
            if (v > bm) { bm = v; bi = i; }
        }
        rv[tid] = bm; ri[tid] = bi;
        __syncthreads();
        for (int sred = 128; sred > 0; sred >>= 1) {
            if (tid < sred) {
                float v2 = rv[tid + sred]; int i2 = ri[tid + sred];
                if (v2 > rv[tid] || (v2 == rv[tid] && i2 < ri[tid])) {
                    rv[tid] = v2; ri[tid] = i2;
                }
            }
            __syncthreads();
        }
        if (tid == 0) {
            tv[row * TOPK + it] = rv[0];
            ti[row * TOPK + it] = ri[0];
            sh[ri[0]] = -2.f;
        }
        __syncthreads();
    }
}

/* ---------------- sparse rank-32 add into recon output ------------------- */
__global__ void sparse_add_kernel(const float* __restrict__ tv,
                                  const int* __restrict__ ti,
                                  const float* __restrict__ D,
                                  float* __restrict__ out)
{
    __shared__ float sv[TOPK];
    __shared__ int   si[TOPK];
    int row = blockIdx.x, tid = threadIdx.x;
    if (tid < TOPK) { sv[tid] = tv[row * TOPK + tid]; si[tid] = ti[row * TOPK + tid]; }
    __syncthreads();
    for (int d = tid; d < DIN_; d += 256) {
        float a = out[(size_t)row * DIN_ + d];
#pragma unroll
        for (int j = 0; j < TOPK; j++)
            a += sv[j] * D[(size_t)si[j] * DIN_ + d];
        out[(size_t)row * DIN_ + d] = a;
    }
}

/* ---------------- driver -------------------------------------------------- */
extern "C" void kernel_launch(void* const* d_in, const int* in_sizes, int n_in,
                              void* d_out, int out_size)
{
    const float* x_in = (const float*)d_in[0];
    const float* D    = (const float*)d_in[1];
    const float* b    = (const float*)d_in[2];
    const float* Wq   = (const float*)d_in[3];
    const float* bq   = (const float*)d_in[4];
    const float* Wk   = (const float*)d_in[5];
    const float* bk   = (const float*)d_in[6];
    const float* Wv   = (const float*)d_in[7];
    const float* bv   = (const float*)d_in[8];
    const float* Wo   = (const float*)d_in[9];
    const float* bo   = (const float*)d_in[10];
    float* out = (float*)d_out;

    float *px, *pz, *pzp, *pq, *pk, *pv, *po, *pdz, *ps, *ptv;
    int* pti;
    cudaGetSymbolAddress((void**)&px,  g_x);
    cudaGetSymbolAddress((void**)&pz,  g_z);
    cudaGetSymbolAddress((void**)&pzp, g_zpred);
    cudaGetSymbolAddress((void**)&pq,  g_q);
    cudaGetSymbolAddress((void**)&pk,  g_k);
    cudaGetSymbolAddress((void**)&pv,  g_v);
    cudaGetSymbolAddress((void**)&po,  g_o);
    cudaGetSymbolAddress((void**)&pdz, g_Dz);
    cudaGetSymbolAddress((void**)&ps,  g_s);
    cudaGetSymbolAddress((void**)&ptv, g_tv);
    cudaGetSymbolAddress((void**)&pti, g_ti);

    cudaFuncSetAttribute(topk_kernel,
                         cudaFuncAttributeMaxDynamicSharedMemorySize,
                         Ww * (int)sizeof(float));

    dim3 blk(256);

    /* x = x_input - b */
    sub_bias_kernel<<<dim3(DIN_ / 256, NROWS), blk>>>(x_in, b, px);

    for (int i = 0; i < NLAY; i++) {
        /* z_in = relu(LAM * x @ D^T) */
        gemm_tc<1><<<dim3(Ww / 128, NROWS / 128), blk>>>(
            px, D, nullptr, pz, NROWS, Ww, DIN_, DIN_, DIN_, LAMBDA, 1, 0);

        /* q / k / v (k,v read shifted rows of z_in) */
        gemm_tc<0><<<dim3((DBb + 127) / 128, NROWS / 128), blk>>>(
            pz, Wq + (size_t)i * Ww * DBb, bq + (size_t)i * DBb, pq,
            NROWS, DBb, Ww, Ww, DBb, 1.f, 2, 0);
        gemm_tc<0><<<dim3((DBb + 127) / 128, NROWS / 128), blk>>>(
            pz, Wk + (size_t)i * Ww * DBb, bk + (size_t)i * DBb, pk,
            NROWS, DBb, Ww, Ww, DBb, 1.f, 2, 1);
        gemm_tc<0><<<dim3((DBb + 127) / 128, NROWS / 128), blk>>>(
            pz, Wv + (size_t)i * Ww * DBb, bv + (size_t)i * DBb, pv,
            NROWS, DBb, Ww, Ww, DBb, 1.f, 2, 1);

        attn_kernel<<<dim3(Ll / 128, Hh, Bb), dim3(128)>>>(pq, pk, pv, po);

        /* z_pred_ = relu(o @ Wo + bo)  (overwrites z_in buffer) */
        gemm_tc<0><<<dim3(Ww / 128, NROWS / 128), blk>>>(
            po, Wo + (size_t)i * DBb * Ww, bo + (size_t)i * Ww, pz,
            NROWS, Ww, DBb, DBb, Ww, 1.f, 3, 0);

        /* Dz = z_pred_ @ D */
        gemm_tc<0><<<dim3(DIN_ / 128, NROWS / 128), blk>>>(
            pz, D, nullptr, pdz, NROWS, DIN_, Ww, Ww, DIN_, 1.f, 0, 0);

        rowstats_kernel<<<NROWS, 256>>>(pdz, px, ps);
        zpred_update_kernel<<<dim3(Ww / 256, NROWS), blk>>>(pz, ps, pzp, i == 0);
        x_update_kernel<<<dim3(DIN_ / 256, NROWS), blk>>>(pdz, ps, px);
    }

    /* z_novel = relu(LAM * x @ D^T) */
    gemm_tc<1><<<dim3(Ww / 128, NROWS / 128), blk>>>(
        px, D, nullptr, pz, NROWS, Ww, DIN_, DIN_, DIN_, LAMBDA, 1, 0);

    topk_kernel<<<NROWS, 256, Ww * (int)sizeof(float)>>>(pz, ptv, pti);

    /* out = z_pred @ D + b, then add top-32 sparse codes */
    gemm_tc<0><<<dim3(DIN_ / 128, NROWS / 128), blk>>>(
        pzp, D, b, out, NROWS, DIN_, Ww, Ww, DIN_, 1.f, 2, 0);

    sparse_add_kernel<<<NROWS, 256>>>(ptv, pti, D, out);
}

// round 8
// speedup vs baseline: 3.3338x; 1.6665x over previous
#include <cuda_runtime.h>
#include <math.h>
#include <stdint.h>

#define Bb   4
#define Ll   1024
#define DIN_ 768
#define Ww   12288
#define Hh   8
#define NLAY 2
#define DBb  192
#define HDd  24
#define TOPK 32
#define NROWS (Bb*Ll)          /* 4096 */
#define LAMBDA (1.0f/(4.0f*768.0f))

/* pipelined GEMM smem: 2 A buffers + 2 B buffers */
#define AB_WORDS 4608          /* 128*36 */
#define BB_WORDS 4608          /* >= max(128*36, 32*136=4352) */
#define SMEM_GEMM ((2*AB_WORDS + 2*BB_WORDS) * 4)   /* 73728 B */

/* ---------------- scratch (device globals; no allocation allowed) -------- */
__device__ float g_x[NROWS*DIN_];
__device__ float g_z[NROWS*Ww];      /* z_in, later reused as z_pred_ */
__device__ float g_zpred[NROWS*Ww];
__device__ float g_q[NROWS*DBb];
__device__ float g_k[NROWS*DBb];
__device__ float g_v[NROWS*DBb];
__device__ float g_o[NROWS*DBb];
__device__ float g_Dz[NROWS*DIN_];
__device__ float g_s[NROWS];
__device__ float g_tv[NROWS*TOPK];
__device__ int   g_ti[NROWS*TOPK];

/* ---------------- tf32 helpers ------------------------------------------ */
__device__ __forceinline__ uint32_t f2tf(float f)
{
    uint32_t r;
    asm("cvt.rna.tf32.f32 %0, %1;" : "=r"(r) : "f"(f));
    return r;
}

__device__ __forceinline__ void mma8(float* c,
                                     uint32_t a0, uint32_t a1, uint32_t a2, uint32_t a3,
                                     uint32_t b0, uint32_t b1)
{
    asm volatile(
        "mma.sync.aligned.m16n8k8.row.col.f32.tf32.tf32.f32 "
        "{%0,%1,%2,%3},{%4,%5,%6,%7},{%8,%9},{%0,%1,%2,%3};"
        : "+f"(c[0]), "+f"(c[1]), "+f"(c[2]), "+f"(c[3])
        : "r"(a0), "r"(a1), "r"(a2), "r"(a3), "r"(b0), "r"(b1));
}

/* ---------------- pipelined tensor-core GEMM core ------------------------
   C[M,N] = epilogue(alpha * A x B)
   BLAYOUT 0: B is [K,N] row-major ("NN")  -> Bs staged [k][n], stride 136
   BLAYOUT 1: B is [N,K] row-major ("NT")  -> Bs staged [n][p(k)], stride 36
   A staged [m][p(k)], stride 36, p(k) = (k>>2) + 8*(k&3)
   flags: bit0 = relu, bit1 = add bias[gn]
   shiftA: row gm of A reads A[gm-1] (zeros when gm % Ll == 0)               */
template<int BLAYOUT>
__device__ __forceinline__ void gemm_core(
    int m0, int n0,
    const float* __restrict__ A, const float* __restrict__ B,
    const float* __restrict__ bias, float* __restrict__ C,
    int N, int K, int lda, int ldb, float alpha, int flags, int shiftA)
{
    extern __shared__ uint32_t dsm[];

    const int tid  = threadIdx.x;
    const int warp = tid >> 5, lane = tid & 31;
    const int g    = lane >> 2, tg = lane & 3;
    const int wm0  = (warp & 1) * 64;
    const int wn0  = (warp >> 1) * 32;

    const int lr2 = tid >> 3;         /* 0..31 */
    const int lt  = tid & 7;          /* 0..7  */

    float acc[4][4][4];
#pragma unroll
    for (int mf = 0; mf < 4; mf++)
#pragma unroll
        for (int nf = 0; nf < 4; nf++)
#pragma unroll
            for (int e = 0; e < 4; e++) acc[mf][nf][e] = 0.f;

    float4 ra[4], rb[4];

    /* ---- load helpers (global -> regs) ---- */
    auto ldA = [&](int k0) {
#pragma unroll
        for (int i = 0; i < 4; i++) {
            int gm = m0 + lr2 + i * 32;
            float4 av = make_float4(0.f, 0.f, 0.f, 0.f);
            if (shiftA) {
                if ((gm & (Ll - 1)) != 0)
                    av = *reinterpret_cast<const float4*>(&A[(size_t)(gm - 1) * lda + k0 + lt * 4]);
            } else {
                av = *reinterpret_cast<const float4*>(&A[(size_t)gm * lda + k0 + lt * 4]);
            }
            ra[i] = av;
        }
    };
    auto ldB = [&](int k0) {
        if (BLAYOUT == 1) {
#pragma unroll
            for (int i = 0; i < 4; i++) {
                int gn = n0 + lr2 + i * 32;
                float4 bv = make_float4(0.f, 0.f, 0.f, 0.f);
                if (gn < N)
                    bv = *reinterpret_cast<const float4*>(&B[(size_t)gn * ldb + k0 + lt * 4]);
                rb[i] = bv;
            }
        } else {
#pragma unroll
            for (int i = 0; i < 4; i++) {
                int r  = (tid >> 5) + i * 8;   /* k row 0..31 */
                int c  = (tid & 31) * 4;       /* n 0..124 */
                int gn = n0 + c;
                float4 bv;
                const float* bp = &B[(size_t)(k0 + r) * ldb + gn];
                if (gn + 3 < N) {
                    bv = *reinterpret_cast<const float4*>(bp);
                } else {
                    bv.x = (gn + 0 < N) ? bp[0] : 0.f;
                    bv.y = (gn + 1 < N) ? bp[1] : 0.f;
                    bv.z = (gn + 2 < N) ? bp[2] : 0.f;
                    bv.w = (gn + 3 < N) ? bp[3] : 0.f;
                }
                rb[i] = bv;
            }
        }
    };
    /* ---- store helpers (regs -> smem, cvt to tf32) ---- */
    auto stA = [&](uint32_t* As) {
#pragma unroll
        for (int i = 0; i < 4; i++) {
            uint32_t* dst = &As[(lr2 + i * 32) * 36 + lt];
            dst[0]  = f2tf(ra[i].x);
            dst[8]  = f2tf(ra[i].y);
            dst[16] = f2tf(ra[i].z);
            dst[24] = f2tf(ra[i].w);
        }
    };
    auto stB = [&](uint32_t* Bs) {
        if (BLAYOUT == 1) {
#pragma unroll
            for (int i = 0; i < 4; i++) {
                uint32_t* dst = &Bs[(lr2 + i * 32) * 36 + lt];
                dst[0]  = f2tf(rb[i].x);
                dst[8]  = f2tf(rb[i].y);
                dst[16] = f2tf(rb[i].z);
                dst[24] = f2tf(rb[i].w);
            }
        } else {
#pragma unroll
            for (int i = 0; i < 4; i++) {
                int r = (tid >> 5) + i * 8;
                int c = (tid & 31) * 4;
                uint32_t* dst = &Bs[r * 136 + c];
                dst[0] = f2tf(rb[i].x);
                dst[1] = f2tf(rb[i].y);
                dst[2] = f2tf(rb[i].z);
                dst[3] = f2tf(rb[i].w);
            }
        }
    };
    /* ---- compute on one staged tile ---- */
    auto compute = [&](const uint32_t* As, const uint32_t* Bs) {
#pragma unroll
        for (int h = 0; h < 2; h++) {
            uint4 Av[4][2];
#pragma unroll
            for (int mf = 0; mf < 4; mf++) {
                int r0 = wm0 + mf * 16 + g;
                Av[mf][0] = *reinterpret_cast<const uint4*>(&As[r0 * 36 + tg * 8 + h * 4]);
                Av[mf][1] = *reinterpret_cast<const uint4*>(&As[(r0 + 8) * 36 + tg * 8 + h * 4]);
            }
            if (BLAYOUT == 1) {
                uint4 Bv[4];
#pragma unroll
                for (int nf = 0; nf < 4; nf++)
                    Bv[nf] = *reinterpret_cast<const uint4*>(
                        &Bs[(wn0 + nf * 8 + g) * 36 + tg * 8 + h * 4]);
#pragma unroll
                for (int kk = 0; kk < 2; kk++) {
#pragma unroll
                    for (int mf = 0; mf < 4; mf++)
#pragma unroll
                        for (int nf = 0; nf < 4; nf++) {
                            uint32_t a0 = kk ? Av[mf][0].z : Av[mf][0].x;
                            uint32_t a2 = kk ? Av[mf][0].w : Av[mf][0].y;
                            uint32_t a1 = kk ? Av[mf][1].z : Av[mf][1].x;
                            uint32_t a3 = kk ? Av[mf][1].w : Av[mf][1].y;
                            uint32_t b0 = kk ? Bv[nf].z : Bv[nf].x;
                            uint32_t b1 = kk ? Bv[nf].w : Bv[nf].y;
                            mma8(acc[mf][nf], a0, a1, a2, a3, b0, b1);
                        }
                }
            } else {
#pragma unroll
                for (int kk = 0; kk < 2; kk++) {
                    int kg = 2 * h + kk;
#pragma unroll
                    for (int nf = 0; nf < 4; nf++) {
                        int nn = wn0 + nf * 8 + g;
                        uint32_t b0 = Bs[(kg * 8 + tg) * 136 + nn];
                        uint32_t b1 = Bs[(kg * 8 + tg + 4) * 136 + nn];
#pragma unroll
                        for (int mf = 0; mf < 4; mf++) {
                            uint32_t a0 = kk ? Av[mf][0].z : Av[mf][0].x;
                            uint32_t a2 = kk ? Av[mf][0].w : Av[mf][0].y;
                            uint32_t a1 = kk ? Av[mf][1].z : Av[mf][1].x;
                            uint32_t a3 = kk ? Av[mf][1].w : Av[mf][1].y;
                            mma8(acc[mf][nf], a0, a1, a2, a3, b0, b1);
                        }
                    }
                }
            }
        }
    };

    /* ---- pipelined main loop: 1 sync / tile ---- */
    const int NTILES = K >> 5;                /* K % 32 == 0 for all our GEMMs */
    ldA(0); ldB(0);
    stA(dsm); stB(dsm + 2 * AB_WORDS);
    __syncthreads();
    for (int t = 0; t < NTILES; t++) {
        const int cur = t & 1, nxt = (t + 1) & 1;
        const bool more = (t + 1 < NTILES);
        if (more) { ldA((t + 1) << 5); ldB((t + 1) << 5); }
        compute(dsm + cur * AB_WORDS, dsm + 2 * AB_WORDS + cur * BB_WORDS);
        if (more) {
            stA(dsm + nxt * AB_WORDS);
            stB(dsm + 2 * AB_WORDS + nxt * BB_WORDS);
            __syncthreads();
        }
    }

    /* ---- epilogue ---- */
#pragma unroll
    for (int mf = 0; mf < 4; mf++) {
#pragma unroll
        for (int nf = 0; nf < 4; nf++) {
            int gm = m0 + wm0 + mf * 16 + g;
            int gn = n0 + wn0 + nf * 8 + 2 * tg;
            if (gn < N) {
                float bsum  = (flags & 2) ? bias[gn] : 0.f;
                float bsum1 = (flags & 2) ? bias[gn + 1] : 0.f;
                float v0 = acc[mf][nf][0] * alpha + bsum;
                float v1 = acc[mf][nf][1] * alpha + bsum1;
                float v2 = acc[mf][nf][2] * alpha + bsum;
                float v3 = acc[mf][nf][3] * alpha + bsum1;
                if (flags & 1) {
                    v0 = fmaxf(v0, 0.f); v1 = fmaxf(v1, 0.f);
                    v2 = fmaxf(v2, 0.f); v3 = fmaxf(v3, 0.f);
                }
                *reinterpret_cast<float2*>(&C[(size_t)gm * N + gn])       = make_float2(v0, v1);
                *reinterpret_cast<float2*>(&C[(size_t)(gm + 8) * N + gn]) = make_float2(v2, v3);
            }
        }
    }
}

template<int BLAYOUT>
__global__ __launch_bounds__(256)
void gemm_tc(const float* __restrict__ A, const float* __restrict__ B,
             const float* __restrict__ bias, float* __restrict__ C,
             int N, int K, int lda, int ldb,
             float alpha, int flags, int shiftA)
{
    gemm_core<BLAYOUT>(blockIdx.y * 128, blockIdx.x * 128,
                       A, B, bias, C, N, K, lda, ldb, alpha, flags, shiftA);
}

/* fused q/k/v: blockIdx.z selects the matrix; k,v read shifted A rows */
__global__ __launch_bounds__(256)
void gemm_qkv(const float* __restrict__ z,
              const float* __restrict__ Wq, const float* __restrict__ Wk,
              const float* __restrict__ Wv,
              const float* __restrict__ bq, const float* __restrict__ bk,
              const float* __restrict__ bv,
              float* __restrict__ q, float* __restrict__ k, float* __restrict__ v)
{
    const float* Bp; const float* bp; float* Cp; int shift;
    if (blockIdx.z == 0)      { Bp = Wq; bp = bq; Cp = q; shift = 0; }
    else if (blockIdx.z == 1) { Bp = Wk; bp = bk; Cp = k; shift = 1; }
    else                      { Bp = Wv; bp = bv; Cp = v; shift = 1; }
    gemm_core<0>(blockIdx.y * 128, blockIdx.x * 128,
                 z, Bp, bp, Cp, DBb, Ww, Ww, DBb, 1.f, 2, shift);
}

/* ---------------- causal flash attention (HD=24) ------------------------- */
__global__ __launch_bounds__(128)
void attn_kernel(const float* __restrict__ qb, const float* __restrict__ kb,
                 const float* __restrict__ vb, float* __restrict__ ob)
{
    const int qt  = blockIdx.x, h = blockIdx.y, bz = blockIdx.z;
    const int tid = threadIdx.x;
    const int qi  = qt * 128 + tid;
    const size_t rowbase = ((size_t)bz * Ll) * DBb + (size_t)h * HDd;

    float qreg[HDd];
    const float* qp = qb + rowbase + (size_t)qi * DBb;
#pragma unroll
    for (int d = 0; d < HDd; d++) qreg[d] = qp[d];

    const float scale = rsqrtf((float)HDd);
    float m = -1e30f, l = 0.f, o[HDd];
#pragma unroll
    for (int d = 0; d < HDd; d++) o[d] = 0.f;

    __shared__ float Ks[128][HDd + 1];
    __shared__ float Vs[128][HDd + 1];

    for (int kt = 0; kt <= qt; kt++) {
        for (int e = tid; e < 128 * HDd; e += 128) {
            int j = e / HDd, d = e - j * HDd;
            size_t gidx = rowbase + (size_t)(kt * 128 + j) * DBb + d;
            Ks[j][d] = kb[gidx];
            Vs[j][d] = vb[gidx];
        }
        __syncthreads();
        int jmax = min(128, qi - kt * 128 + 1);
        for (int j = 0; j < jmax; j++) {
            float sdot = 0.f;
#pragma unroll
            for (int d = 0; d < HDd; d++) sdot += qreg[d] * Ks[j][d];
            sdot *= scale;
            float mn = fmaxf(m, sdot);
            float c  = __expf(m - mn);
            float p  = __expf(sdot - mn);
            l = l * c + p;
#pragma unroll
            for (int d = 0; d < HDd; d++) o[d] = o[d] * c + p * Vs[j][d];
            m = mn;
        }
        __syncthreads();
    }
    float inv = 1.f / l;
    float* op = ob + rowbase + (size_t)qi * DBb;
#pragma unroll
    for (int d = 0; d < HDd; d++) op[d] = o[d] * inv;
}

/* ---------------- small element/row kernels ------------------------------ */
__global__ void sub_bias_kernel(const float* __restrict__ xin,
                                const float* __restrict__ b,
                                float* __restrict__ x)
{
    int n = blockIdx.y, d = blockIdx.x * 256 + threadIdx.x;
    x[(size_t)n * DIN_ + d] = xin[(size_t)n * DIN_ + d] - b[d];
}

__global__ void rowstats_kernel(const float* __restrict__ Dz,
                                const float* __restrict__ x,
                                float* __restrict__ s)
{
    int n = blockIdx.x, tid = threadIdx.x;
    const float* dzr = Dz + (size_t)n * DIN_;
    const float* xr  = x  + (size_t)n * DIN_;
    float ss = 0.f, dt = 0.f;
    for (int i = tid; i < DIN_; i += 256) {
        float d = dzr[i];
        ss += d * d;
        dt += d * xr[i];
    }
#pragma unroll
    for (int o = 16; o; o >>= 1) {
        ss += __shfl_down_sync(0xffffffffu, ss, o);
        dt += __shfl_down_sync(0xffffffffu, dt, o);
    }
    __shared__ float a1[8], a2[8];
    if ((tid & 31) == 0) { a1[tid >> 5] = ss; a2[tid >> 5] = dt; }
    __syncthreads();
    if (tid == 0) {
        float S = 0.f, T = 0.f;
#pragma unroll
        for (int i = 0; i < 8; i++) { S += a1[i]; T += a2[i]; }
        float nrm = sqrtf(S) + 1e-6f;
        s[n] = T / (nrm * nrm);
    }
}

__global__ void zpred_update_kernel(const float* __restrict__ zp_,
                                    const float* __restrict__ s,
                                    float* __restrict__ zpred, int first)
{
    int n = blockIdx.y;
    int w = blockIdx.x * 256 + threadIdx.x;
    size_t idx = (size_t)n * Ww + w;
    float v = s[n] * zp_[idx];
    zpred[idx] = first ? v : (zpred[idx] + v);
}

__global__ void x_update_kernel(const float* __restrict__ Dz,
                                const float* __restrict__ s,
                                float* __restrict__ x)
{
    int n = blockIdx.y;
    int d = blockIdx.x * 256 + threadIdx.x;
    size_t idx = (size_t)n * DIN_ + d;
    x[idx] -= s[n] * Dz[idx];
}

/* ---------------- top-32 per row (iterative argmax over smem row) -------- */
__global__ void topk_kernel(const float* __restrict__ z,
                            float* __restrict__ tv, int* __restrict__ ti)
{
    extern __shared__ float sh[];            /* Ww floats */
    __shared__ float rv[256];
    __shared__ int   ri[256];
    int row = blockIdx.x, tid = threadIdx.x;
    const float* zr = z + (size_t)row * Ww;
    for (int i = tid; i < Ww; i += 256) sh[i] = zr[i];
    __syncthreads();
    for (int it = 0; it < TOPK; it++) {
        float bm = -1.f; int bi = 0;
        for (int i = tid; i < Ww; i += 256) {
            float v = sh[i];
            if (v > bm) { bm = v; bi = i; }
        }
        rv[tid] = bm; ri[tid] = bi;
        __syncthreads();
        for (int sred = 128; sred > 0; sred >>= 1) {
            if (tid < sred) {
                float v2 = rv[tid + sred]; int i2 = ri[tid + sred];
                if (v2 > rv[tid] || (v2 == rv[tid] && i2 < ri[tid])) {
                    rv[tid] = v2; ri[tid] = i2;
                }
            }
            __syncthreads();
        }
        if (tid == 0) {
            tv[row * TOPK + it] = rv[0];
            ti[row * TOPK + it] = ri[0];
            sh[ri[0]] = -2.f;
        }
        __syncthreads();
    }
}

/* ---------------- sparse rank-32 add into recon output ------------------- */
__global__ void sparse_add_kernel(const float* __restrict__ tv,
                                  const int* __restrict__ ti,
                                  const float* __restrict__ D,
                                  float* __restrict__ out)
{
    __shared__ float sv[TOPK];
    __shared__ int   si[TOPK];
    int row = blockIdx.x, tid = threadIdx.x;
    if (tid < TOPK) { sv[tid] = tv[row * TOPK + tid]; si[tid] = ti[row * TOPK + tid]; }
    __syncthreads();
    for (int d = tid; d < DIN_; d += 256) {
        float a = out[(size_t)row * DIN_ + d];
#pragma unroll
        for (int j = 0; j < TOPK; j++)
            a += sv[j] * D[(size_t)si[j] * DIN_ + d];
        out[(size_t)row * DIN_ + d] = a;
    }
}

/* ---------------- driver -------------------------------------------------- */
extern "C" void kernel_launch(void* const* d_in, const int* in_sizes, int n_in,
                              void* d_out, int out_size)
{
    const float* x_in = (const float*)d_in[0];
    const float* D    = (const float*)d_in[1];
    const float* b    = (const float*)d_in[2];
    const float* Wq   = (const float*)d_in[3];
    const float* bq   = (const float*)d_in[4];
    const float* Wk   = (const float*)d_in[5];
    const float* bk   = (const float*)d_in[6];
    const float* Wv   = (const float*)d_in[7];
    const float* bv   = (const float*)d_in[8];
    const float* Wo   = (const float*)d_in[9];
    const float* bo   = (const float*)d_in[10];
    float* out = (float*)d_out;

    float *px, *pz, *pzp, *pq, *pk, *pv, *po, *pdz, *ps, *ptv;
    int* pti;
    cudaGetSymbolAddress((void**)&px,  g_x);
    cudaGetSymbolAddress((void**)&pz,  g_z);
    cudaGetSymbolAddress((void**)&pzp, g_zpred);
    cudaGetSymbolAddress((void**)&pq,  g_q);
    cudaGetSymbolAddress((void**)&pk,  g_k);
    cudaGetSymbolAddress((void**)&pv,  g_v);
    cudaGetSymbolAddress((void**)&po,  g_o);
    cudaGetSymbolAddress((void**)&pdz, g_Dz);
    cudaGetSymbolAddress((void**)&ps,  g_s);
    cudaGetSymbolAddress((void**)&ptv, g_tv);
    cudaGetSymbolAddress((void**)&pti, g_ti);

    cudaFuncSetAttribute(topk_kernel,
                         cudaFuncAttributeMaxDynamicSharedMemorySize,
                         Ww * (int)sizeof(float));
    cudaFuncSetAttribute(gemm_tc<0>,
                         cudaFuncAttributeMaxDynamicSharedMemorySize, SMEM_GEMM);
    cudaFuncSetAttribute(gemm_tc<1>,
                         cudaFuncAttributeMaxDynamicSharedMemorySize, SMEM_GEMM);
    cudaFuncSetAttribute(gemm_qkv,
                         cudaFuncAttributeMaxDynamicSharedMemorySize, SMEM_GEMM);

    dim3 blk(256);

    /* x = x_input - b */
    sub_bias_kernel<<<dim3(DIN_ / 256, NROWS), blk>>>(x_in, b, px);

    for (int i = 0; i < NLAY; i++) {
        /* z_in = relu(LAM * x @ D^T) */
        gemm_tc<1><<<dim3(Ww / 128, NROWS / 128), blk, SMEM_GEMM>>>(
            px, D, nullptr, pz, Ww, DIN_, DIN_, DIN_, LAMBDA, 1, 0);

        /* fused q / k / v (k,v read shifted rows of z_in) */
        gemm_qkv<<<dim3((DBb + 127) / 128, NROWS / 128, 3), blk, SMEM_GEMM>>>(
            pz,
            Wq + (size_t)i * Ww * DBb, Wk + (size_t)i * Ww * DBb, Wv + (size_t)i * Ww * DBb,
            bq + (size_t)i * DBb, bk + (size_t)i * DBb, bv + (size_t)i * DBb,
            pq, pk, pv);

        attn_kernel<<<dim3(Ll / 128, Hh, Bb), dim3(128)>>>(pq, pk, pv, po);

        /* z_pred_ = relu(o @ Wo + bo)  (overwrites z_in buffer) */
        gemm_tc<0><<<dim3(Ww / 128, NROWS / 128), blk, SMEM_GEMM>>>(
            po, Wo + (size_t)i * DBb * Ww, bo + (size_t)i * Ww, pz,
            Ww, DBb, DBb, Ww, 1.f, 3, 0);

        /* Dz = z_pred_ @ D */
        gemm_tc<0><<<dim3(DIN_ / 128, NROWS / 128), blk, SMEM_GEMM>>>(
            pz, D, nullptr, pdz, DIN_, Ww, Ww, DIN_, 1.f, 0, 0);

        rowstats_kernel<<<NROWS, 256>>>(pdz, px, ps);
        zpred_update_kernel<<<dim3(Ww / 256, NROWS), blk>>>(pz, ps, pzp, i == 0);
        x_update_kernel<<<dim3(DIN_ / 256, NROWS), blk>>>(pdz, ps, px);
    }

    /* z_novel = relu(LAM * x @ D^T) */
    gemm_tc<1><<<dim3(Ww / 128, NROWS / 128), blk, SMEM_GEMM>>>(
        px, D, nullptr, pz, Ww, DIN_, DIN_, DIN_, LAMBDA, 1, 0);

    topk_kernel<<<NROWS, 256, Ww * (int)sizeof(float)>>>(pz, ptv, pti);

    /* out = z_pred @ D + b, then add top-32 sparse codes */
    gemm_tc<0><<<dim3(DIN_ / 128, NROWS / 128), blk, SMEM_GEMM>>>(
        pzp, D, b, out, DIN_, Ww, Ww, DIN_, 1.f, 2, 0);

    sparse_add_kernel<<<NROWS, 256>>>(ptv, pti, D, out);
}

// round 11
// speedup vs baseline: 3.5082x; 1.0523x over previous
#include <cuda_runtime.h>
#include <math.h>
#include <stdint.h>

#define Bb   4
#define Ll   1024
#define DIN_ 768
#define Ww   12288
#define Hh   8
#define NLAY 2
#define DBb  192
#define HDd  24
#define TOPK 32
#define NROWS (Bb*Ll)          /* 4096 */
#define LAMBDA (1.0f/(4.0f*768.0f))

/* arch-feature gate: tcgen05 only exists on the sm_103a target */
#if defined(__CUDA_ARCH__) && (__CUDA_ARCH__ == 1030) && defined(__CUDA_ARCH_FEAT_SM103_ALL)
#define USE_TC5 1
#else
#define USE_TC5 0
#endif

/* fallback (mma.sync) smem layout: 2 A + 2 B tf32 buffers */
#define AB_WORDS 4608          /* 128*36 */
#define BB_WORDS 4608          /* >= max(128*36, 32*136) */
/* tcgen05 smem layout: 1024 hdr + 4 x 16KB SW128 tiles (+align slack) */
#define OFF_A0 1024
#define OFF_B0 (OFF_A0 + 16384)
#define OFF_A1 (OFF_B0 + 16384)
#define OFF_B1 (OFF_A1 + 16384)
/* one size for both paths */
#define SMEM_GEMM ((2*AB_WORDS + 2*BB_WORDS) * 4)   /* 73728 >= 67584 */

/* ---------------- scratch (device globals; no allocation allowed) -------- */
__device__ float g_x[NROWS*DIN_];
__device__ float g_z[NROWS*Ww];
__device__ float g_zpred[NROWS*Ww];
__device__ float g_q[NROWS*DBb];
__device__ float g_k[NROWS*DBb];
__device__ float g_v[NROWS*DBb];
__device__ float g_o[NROWS*DBb];
__device__ float g_Dz[NROWS*DIN_];
__device__ float g_s[NROWS];
__device__ float g_tv[NROWS*TOPK];
__device__ int   g_ti[NROWS*TOPK];

/* ---------------- common helpers ----------------------------------------- */
__device__ __forceinline__ uint32_t f2tf(float f)
{
    uint32_t r;
    asm("cvt.rna.tf32.f32 %0, %1;" : "=r"(r) : "f"(f));
    return r;
}

#if USE_TC5
/* ---------------- tcgen05 helpers (sm_103a only) -------------------------- */
__device__ __forceinline__ uint32_t sw128(uint32_t off)
{
    return off ^ ((off >> 3) & 0x70);
}
__device__ __forceinline__ uint32_t elect1()
{
    uint32_t p;
    asm volatile("{\n\t.reg .pred p;\n\telect.sync _|p, 0xFFFFFFFF;\n\tselp.b32 %0, 1, 0, p;\n\t}"
                 : "=r"(p));
    return p;
}
__device__ __forceinline__ uint64_t mk_desc(uint32_t addr)
{
    /* SW128, version=1 (Blackwell), SBO=64, LBO=1 */
    const uint64_t base = (2ull << 61) | (1ull << 46) | (64ull << 32) | (1ull << 16);
    return base | (uint64_t)((addr >> 4) & 0x3FFF);
}
__device__ __forceinline__ void mma_tf32(uint32_t d, uint64_t ad, uint64_t bd,
                                         uint32_t idesc, int en)
{
    asm volatile(
        "{\n\t.reg .pred p;\n\tsetp.ne.u32 p, %4, 0;\n\t"
        "tcgen05.mma.cta_group::1.kind::tf32 [%0], %1, %2, %3, {%5,%5,%5,%5}, p;\n\t}"
        :: "r"(d), "l"(ad), "l"(bd), "r"(idesc), "r"(en), "r"(0u) : "memory");
}
__device__ __forceinline__ void tc_commit(uint32_t mbar)
{
    asm volatile(
        "tcgen05.commit.cta_group::1.mbarrier::arrive::one.shared::cluster.b64 [%0];"
        :: "r"(mbar) : "memory");
}
__device__ __forceinline__ void mbar_init(uint32_t addr, uint32_t cnt)
{
    asm volatile("mbarrier.init.shared.b64 [%0], %1;" :: "r"(addr), "r"(cnt) : "memory");
}
__device__ __forceinline__ void mbar_wait(uint32_t addr, uint32_t phase)
{
    asm volatile(
        "{\n\t.reg .pred P;\n\t"
        "WL%=:\n\t"
        "mbarrier.try_wait.parity.acquire.cta.shared::cta.b64 P, [%0], %1, 0x989680;\n\t"
        "@P bra.uni WD%=;\n\t"
        "bra.uni WL%=;\n\t"
        "WD%=:\n\t}"
        :: "r"(addr), "r"(phase) : "memory");
}
__device__ __forceinline__ void fence_async_shared()
{
    asm volatile("fence.proxy.async.shared::cta;" ::: "memory");
}
__device__ __forceinline__ void tc_fence_after()
{
    asm volatile("tcgen05.fence::after_thread_sync;" ::: "memory");
}
__device__ __forceinline__ void tc_wait_ld()
{
    asm volatile("tcgen05.wait::ld.sync.aligned;" ::: "memory");
}
__device__ __forceinline__ void tc_alloc(uint32_t smem_dst, uint32_t ncols)
{
    asm volatile("tcgen05.alloc.cta_group::1.sync.aligned.shared::cta.b32 [%0], %1;"
                 :: "r"(smem_dst), "r"(ncols) : "memory");
}
__device__ __forceinline__ void tc_relinquish()
{
    asm volatile("tcgen05.relinquish_alloc_permit.cta_group::1.sync.aligned;");
}
__device__ __forceinline__ void tc_dealloc(uint32_t tmem, uint32_t ncols)
{
    asm volatile("tcgen05.dealloc.cta_group::1.sync.aligned.b32 %0, %1;"
                 :: "r"(tmem), "r"(ncols));
}
__device__ __forceinline__ void ldtm32(uint32_t* r, uint32_t tmem)
{
    asm volatile(
        "tcgen05.ld.sync.aligned.32x32b.x32.b32 "
        "{%0, %1, %2, %3, %4, %5, %6, %7, "
        " %8, %9, %10, %11, %12, %13, %14, %15, "
        " %16, %17, %18, %19, %20, %21, %22, %23, "
        " %24, %25, %26, %27, %28, %29, %30, %31}, [%32];"
        : "=r"(r[0]),  "=r"(r[1]),  "=r"(r[2]),  "=r"(r[3]),
          "=r"(r[4]),  "=r"(r[5]),  "=r"(r[6]),  "=r"(r[7]),
          "=r"(r[8]),  "=r"(r[9]),  "=r"(r[10]), "=r"(r[11]),
          "=r"(r[12]), "=r"(r[13]), "=r"(r[14]), "=r"(r[15]),
          "=r"(r[16]), "=r"(r[17]), "=r"(r[18]), "=r"(r[19]),
          "=r"(r[20]), "=r"(r[21]), "=r"(r[22]), "=r"(r[23]),
          "=r"(r[24]), "=r"(r[25]), "=r"(r[26]), "=r"(r[27]),
          "=r"(r[28]), "=r"(r[29]), "=r"(r[30]), "=r"(r[31])
        : "r"(tmem));
}

/* ---------------- tcgen05 tf32 SS GEMM core ------------------------------ */
template<int BLAYOUT>
__device__ __forceinline__ void gemm_core5(
    int m0, int n0,
    const float* __restrict__ A, const float* __restrict__ B,
    const float* __restrict__ bias, float* __restrict__ C,
    int N, int K, int lda, int ldb, float alpha, int flags, int shiftA)
{
    extern __shared__ uint32_t dsm[];
    char* dsm_c = reinterpret_cast<char*>(dsm);
    uint32_t sb = (uint32_t)__cvta_generic_to_shared(dsm_c);
    uint32_t sb0 = (sb + 1023u) & ~1023u;
    char* sm0 = dsm_c + (sb0 - sb);

    const int tid  = threadIdx.x;
    const int warp = tid >> 5;
    const int lane = tid & 31;
    const int NT   = min(128, N - n0);

    if (warp == 0) {
        tc_alloc(sb0, 128);
        tc_relinquish();
    }
    if (tid == 0) { mbar_init(sb0 + 16, 1); mbar_init(sb0 + 24, 1); }
    __syncthreads();
    uint32_t tmem;
    asm volatile("ld.shared.b32 %0, [%1];" : "=r"(tmem) : "r"(sb0));

    const uint32_t idesc = (1u << 4)            /* dtype f32 */
                         | (2u << 7)            /* atype tf32 */
                         | (2u << 10)           /* btype tf32 */
                         | ((uint32_t)(NT / 8) << 17)
                         | (8u << 24);          /* M=128 */

    auto stageA = [&](int k0, char* dst) {
        int r  = tid >> 1;
        int cb = (tid & 1) * 4;
        int gm = m0 + r;
        const float* src = nullptr;
        bool ok = true;
        if (shiftA) {
            if ((gm & (Ll - 1)) != 0) src = &A[(size_t)(gm - 1) * lda];
            else ok = false;
        } else {
            src = &A[(size_t)gm * lda];
        }
#pragma unroll
        for (int c = 0; c < 4; c++) {
            int ch = cb + c;
            float4 v = make_float4(0.f, 0.f, 0.f, 0.f);
            if (ok) v = *reinterpret_cast<const float4*>(&src[k0 + ch * 4]);
            uint4 w;
            w.x = f2tf(v.x); w.y = f2tf(v.y); w.z = f2tf(v.z); w.w = f2tf(v.w);
            *reinterpret_cast<uint4*>(dst + sw128(r * 128 + ch * 16)) = w;
        }
    };
    auto stageB = [&](int k0, char* dst) {
        if (BLAYOUT == 1) {
            int r  = tid >> 1;
            int cb = (tid & 1) * 4;
            int gn = n0 + r;
            bool ok = (gn < N);
#pragma unroll
            for (int c = 0; c < 4; c++) {
                int ch = cb + c;
                float4 v = make_float4(0.f, 0.f, 0.f, 0.f);
                if (ok) v = *reinterpret_cast<const float4*>(&B[(size_t)gn * ldb + k0 + ch * 4]);
                uint4 w;
                w.x = f2tf(v.x); w.y = f2tf(v.y); w.z = f2tf(v.z); w.w = f2tf(v.w);
                *reinterpret_cast<uint4*>(dst + sw128(r * 128 + ch * 16)) = w;
            }
        } else {
            int r  = tid >> 3;
            int c0 = (tid & 7) * 4;
#pragma unroll
            for (int stp = 0; stp < 4; stp++) {
                int nn = stp * 32 + c0;
                int gn = n0 + nn;
                float4 v;
                const float* bp = &B[(size_t)(k0 + r) * ldb + gn];
                if (gn + 3 < N) {
                    v = *reinterpret_cast<const float4*>(bp);
                } else {
                    v.x = (gn + 0 < N) ? bp[0] : 0.f;
                    v.y = (gn + 1 < N) ? bp[1] : 0.f;
                    v.z = (gn + 2 < N) ? bp[2] : 0.f;
                    v.w = (gn + 3 < N) ? bp[3] : 0.f;
                }
                *reinterpret_cast<uint32_t*>(dst + sw128((nn + 0) * 128 + r * 4)) = f2tf(v.x);
                *reinterpret_cast<uint32_t*>(dst + sw128((nn + 1) * 128 + r * 4)) = f2tf(v.y);
                *reinterpret_cast<uint32_t*>(dst + sw128((nn + 2) * 128 + r * 4)) = f2tf(v.z);
                *reinterpret_cast<uint32_t*>(dst + sw128((nn + 3) * 128 + r * 4)) = f2tf(v.w);
            }
        }
    };

    const int NTILES = K >> 5;
    stageA(0, sm0 + OFF_A0); stageB(0, sm0 + OFF_B0);
    fence_async_shared();
    __syncthreads();

    uint32_t ph[2] = {0u, 0u};
    for (int t = 0; t < NTILES; t++) {
        const int cur = t & 1;
        if (warp == 0 && elect1()) {
            uint64_t ad = mk_desc(sb0 + (cur ? OFF_A1 : OFF_A0));
            uint64_t bd = mk_desc(sb0 + (cur ? OFF_B1 : OFF_B0));
#pragma unroll
            for (int s = 0; s < 4; s++)
                mma_tf32(tmem, ad + 2 * s, bd + 2 * s, idesc, (t > 0) || (s > 0));
            tc_commit(sb0 + 16 + cur * 8);
        }
        if (t + 1 < NTILES) {
            const int nxt = cur ^ 1;
            if (t >= 1) { mbar_wait(sb0 + 16 + nxt * 8, ph[nxt]); ph[nxt] ^= 1; }
            stageA((t + 1) << 5, sm0 + (nxt ? OFF_A1 : OFF_A0));
            stageB((t + 1) << 5, sm0 + (nxt ? OFF_B1 : OFF_B0));
            fence_async_shared();
            __syncthreads();
        }
    }
    const int last = (NTILES - 1) & 1;
    mbar_wait(sb0 + 16 + last * 8, ph[last]);
    tc_fence_after();

    if (warp < 4) {
        int row = m0 + warp * 32 + lane;
        for (int cb = 0; cb < NT; cb += 32) {
            uint32_t dr[32];
            ldtm32(dr, tmem + cb);
            tc_wait_ld();
#pragma unroll
            for (int j = 0; j < 32; j += 4) {
                int gn = n0 + cb + j;
                float4 v;
                v.x = __uint_as_float(dr[j + 0]) * alpha;
                v.y = __uint_as_float(dr[j + 1]) * alpha;
                v.z = __uint_as_float(dr[j + 2]) * alpha;
                v.w = __uint_as_float(dr[j + 3]) * alpha;
                if (flags & 2) {
                    v.x += bias[gn + 0]; v.y += bias[gn + 1];
                    v.z += bias[gn + 2]; v.w += bias[gn + 3];
                }
                if (flags & 1) {
                    v.x = fmaxf(v.x, 0.f); v.y = fmaxf(v.y, 0.f);
                    v.z = fmaxf(v.z, 0.f); v.w = fmaxf(v.w, 0.f);
                }
                *reinterpret_cast<float4*>(&C[(size_t)row * N + gn]) = v;
            }
        }
    }
    __syncthreads();
    if (warp == 0) tc_dealloc(tmem, 128);
}
#endif  /* USE_TC5 */

/* ---------------- mma.sync fallback helpers ------------------------------ */
__device__ __forceinline__ void mma8(float* c,
                                     uint32_t a0, uint32_t a1, uint32_t a2, uint32_t a3,
                                     uint32_t b0, uint32_t b1)
{
    asm volatile(
        "mma.sync.aligned.m16n8k8.row.col.f32.tf32.tf32.f32 "
        "{%0,%1,%2,%3},{%4,%5,%6,%7},{%8,%9},{%0,%1,%2,%3};"
        : "+f"(c[0]), "+f"(c[1]), "+f"(c[2]), "+f"(c[3])
        : "r"(a0), "r"(a1), "r"(a2), "r"(a3), "r"(b0), "r"(b1));
}

/* pipelined mma.sync GEMM core (round-8 proven path) */
template<int BLAYOUT>
__device__ __forceinline__ void gemm_core_mma(
    int m0, int n0,
    const float* __restrict__ A, const float* __restrict__ B,
    const float* __restrict__ bias, float* __restrict__ C,
    int N, int K, int lda, int ldb, float alpha, int flags, int shiftA)
{
    extern __shared__ uint32_t dsm[];

    const int tid  = threadIdx.x;
    const int warp = tid >> 5, lane = tid & 31;
    const int g    = lane >> 2, tg = lane & 3;
    const int wm0  = (warp & 1) * 64;
    const int wn0  = (warp >> 1) * 32;

    const int lr2 = tid >> 3;
    const int lt  = tid & 7;

    float acc[4][4][4];
#pragma unroll
    for (int mf = 0; mf < 4; mf++)
#pragma unroll
        for (int nf = 0; nf < 4; nf++)
#pragma unroll
            for (int e = 0; e < 4; e++) acc[mf][nf][e] = 0.f;

    float4 ra[4], rb[4];

    auto ldA = [&](int k0) {
#pragma unroll
        for (int i = 0; i < 4; i++) {
            int gm = m0 + lr2 + i * 32;
            float4 av = make_float4(0.f, 0.f, 0.f, 0.f);
            if (shiftA) {
                if ((gm & (Ll - 1)) != 0)
                    av = *reinterpret_cast<const float4*>(&A[(size_t)(gm - 1) * lda + k0 + lt * 4]);
            } else {
                av = *reinterpret_cast<const float4*>(&A[(size_t)gm * lda + k0 + lt * 4]);
            }
            ra[i] = av;
        }
    };
    auto ldB = [&](int k0) {
        if (BLAYOUT == 1) {
#pragma unroll
            for (int i = 0; i < 4; i++) {
                int gn = n0 + lr2 + i * 32;
                float4 bv = make_float4(0.f, 0.f, 0.f, 0.f);
                if (gn < N)
                    bv = *reinterpret_cast<const float4*>(&B[(size_t)gn * ldb + k0 + lt * 4]);
                rb[i] = bv;
            }
        } else {
#pragma unroll
            for (int i = 0; i < 4; i++) {
                int r  = (tid >> 5) + i * 8;
                int c  = (tid & 31) * 4;
                int gn = n0 + c;
                float4 bv;
                const float* bp = &B[(size_t)(k0 + r) * ldb + gn];
                if (gn + 3 < N) {
                    bv = *reinterpret_cast<const float4*>(bp);
                } else {
                    bv.x = (gn + 0 < N) ? bp[0] : 0.f;
                    bv.y = (gn + 1 < N) ? bp[1] : 0.f;
                    bv.z = (gn + 2 < N) ? bp[2] : 0.f;
                    bv.w = (gn + 3 < N) ? bp[3] : 0.f;
                }
                rb[i] = bv;
            }
        }
    };
    auto stA = [&](uint32_t* As) {
#pragma unroll
        for (int i = 0; i < 4; i++) {
            uint32_t* dst = &As[(lr2 + i * 32) * 36 + lt];
            dst[0]  = f2tf(ra[i].x);
            dst[8]  = f2tf(ra[i].y);
            dst[16] = f2tf(ra[i].z);
            dst[24] = f2tf(ra[i].w);
        }
    };
    auto stB = [&](uint32_t* Bs) {
        if (BLAYOUT == 1) {
#pragma unroll
            for (int i = 0; i < 4; i++) {
                uint32_t* dst = &Bs[(lr2 + i * 32) * 36 + lt];
                dst[0]  = f2tf(rb[i].x);
                dst[8]  = f2tf(rb[i].y);
                dst[16] = f2tf(rb[i].z);
                dst[24] = f2tf(rb[i].w);
            }
        } else {
#pragma unroll
            for (int i = 0; i < 4; i++) {
                int r = (tid >> 5) + i * 8;
                int c = (tid & 31) * 4;
                uint32_t* dst = &Bs[r * 136 + c];
                dst[0] = f2tf(rb[i].x);
                dst[1] = f2tf(rb[i].y);
                dst[2] = f2tf(rb[i].z);
                dst[3] = f2tf(rb[i].w);
            }
        }
    };
    auto compute = [&](const uint32_t* As, const uint32_t* Bs) {
#pragma unroll
        for (int h = 0; h < 2; h++) {
            uint4 Av[4][2];
#pragma unroll
            for (int mf = 0; mf < 4; mf++) {
                int r0 = wm0 + mf * 16 + g;
                Av[mf][0] = *reinterpret_cast<const uint4*>(&As[r0 * 36 + tg * 8 + h * 4]);
                Av[mf][1] = *reinterpret_cast<const uint4*>(&As[(r0 + 8) * 36 + tg * 8 + h * 4]);
            }
            if (BLAYOUT == 1) {
                uint4 Bv[4];
#pragma unroll
                for (int nf = 0; nf < 4; nf++)
                    Bv[nf] = *reinterpret_cast<const uint4*>(
                        &Bs[(wn0 + nf * 8 + g) * 36 + tg * 8 + h * 4]);
#pragma unroll
                for (int kk = 0; kk < 2; kk++) {
#pragma unroll
                    for (int mf = 0; mf < 4; mf++)
#pragma unroll
                        for (int nf = 0; nf < 4; nf++) {
                            uint32_t a0 = kk ? Av[mf][0].z : Av[mf][0].x;
                            uint32_t a2 = kk ? Av[mf][0].w : Av[mf][0].y;
                            uint32_t a1 = kk ? Av[mf][1].z : Av[mf][1].x;
                            uint32_t a3 = kk ? Av[mf][1].w : Av[mf][1].y;
                            uint32_t b0 = kk ? Bv[nf].z : Bv[nf].x;
                            uint32_t b1 = kk ? Bv[nf].w : Bv[nf].y;
                            mma8(acc[mf][nf], a0, a1, a2, a3, b0, b1);
                        }
                }
            } else {
#pragma unroll
                for (int kk = 0; kk < 2; kk++) {
                    int kg = 2 * h + kk;
#pragma unroll
                    for (int nf = 0; nf < 4; nf++) {
                        int nn = wn0 + nf * 8 + g;
                        uint32_t b0 = Bs[(kg * 8 + tg) * 136 + nn];
                        uint32_t b1 = Bs[(kg * 8 + tg + 4) * 136 + nn];
#pragma unroll
                        for (int mf = 0; mf < 4; mf++) {
                            uint32_t a0 = kk ? Av[mf][0].z : Av[mf][0].x;
                            uint32_t a2 = kk ? Av[mf][0].w : Av[mf][0].y;
                            uint32_t a1 = kk ? Av[mf][1].z : Av[mf][1].x;
                            uint32_t a3 = kk ? Av[mf][1].w : Av[mf][1].y;
                            mma8(acc[mf][nf], a0, a1, a2, a3, b0, b1);
                        }
                    }
                }
            }
        }
    };

    const int NTILES = K >> 5;
    ldA(0); ldB(0);
    stA(dsm); stB(dsm + 2 * AB_WORDS);
    __syncthreads();
    for (int t = 0; t < NTILES; t++) {
        const int cur = t & 1, nxt = (t + 1) & 1;
        const bool more = (t + 1 < NTILES);
        if (more) { ldA((t + 1) << 5); ldB((t + 1) << 5); }
        compute(dsm + cur * AB_WORDS, dsm + 2 * AB_WORDS + cur * BB_WORDS);
        if (more) {
            stA(dsm + nxt * AB_WORDS);
            stB(dsm + 2 * AB_WORDS + nxt * BB_WORDS);
            __syncthreads();
        }
    }

#pragma unroll
    for (int mf = 0; mf < 4; mf++) {
#pragma unroll
        for (int nf = 0; nf < 4; nf++) {
            int gm = m0 + wm0 + mf * 16 + g;
            int gn = n0 + wn0 + nf * 8 + 2 * tg;
            if (gn < N) {
                float bsum  = (flags & 2) ? bias[gn] : 0.f;
                float bsum1 = (flags & 2) ? bias[gn + 1] : 0.f;
                float v0 = acc[mf][nf][0] * alpha + bsum;
                float v1 = acc[mf][nf][1] * alpha + bsum1;
                float v2 = acc[mf][nf][2] * alpha + bsum;
                float v3 = acc[mf][nf][3] * alpha + bsum1;
                if (flags & 1) {
                    v0 = fmaxf(v0, 0.f); v1 = fmaxf(v1, 0.f);
                    v2 = fmaxf(v2, 0.f); v3 = fmaxf(v3, 0.f);
                }
                *reinterpret_cast<float2*>(&C[(size_t)gm * N + gn])       = make_float2(v0, v1);
                *reinterpret_cast<float2*>(&C[(size_t)(gm + 8) * N + gn]) = make_float2(v2, v3);
            }
        }
    }
}

/* ---------------- unified dispatch --------------------------------------- */
template<int BLAYOUT>
__device__ __forceinline__ void gemm_core(
    int m0, int n0,
    const float* __restrict__ A, const float* __restrict__ B,
    const float* __restrict__ bias, float* __restrict__ C,
    int N, int K, int lda, int ldb, float alpha, int flags, int shiftA)
{
#if USE_TC5
    gemm_core5<BLAYOUT>(m0, n0, A, B, bias, C, N, K, lda, ldb, alpha, flags, shiftA);
#else
    gemm_core_mma<BLAYOUT>(m0, n0, A, B, bias, C, N, K, lda, ldb, alpha, flags, shiftA);
#endif
}

template<int BLAYOUT>
__global__ __launch_bounds__(256)
void gemm_tc(const float* __restrict__ A, const float* __restrict__ B,
             const float* __restrict__ bias, float* __restrict__ C,
             int N, int K, int lda, int ldb,
             float alpha, int flags, int shiftA)
{
    gemm_core<BLAYOUT>(blockIdx.y * 128, blockIdx.x * 128,
                       A, B, bias, C, N, K, lda, ldb, alpha, flags, shiftA);
}

__global__ __launch_bounds__(256)
void gemm_qkv(const float* __restrict__ z,
              const float* __restrict__ Wq, const float* __restrict__ Wk,
              const float* __restrict__ Wv,
              const float* __restrict__ bq, const float* __restrict__ bk,
              const float* __restrict__ bv,
              float* __restrict__ q, float* __restrict__ k, float* __restrict__ v)
{
    const float* Bp; const float* bp; float* Cp; int shift;
    if (blockIdx.z == 0)      { Bp = Wq; bp = bq; Cp = q; shift = 0; }
    else if (blockIdx.z == 1) { Bp = Wk; bp = bk; Cp = k; shift = 1; }
    else                      { Bp = Wv; bp = bv; Cp = v; shift = 1; }
    gemm_core<0>(blockIdx.y * 128, blockIdx.x * 128,
                 z, Bp, bp, Cp, DBb, Ww, Ww, DBb, 1.f, 2, shift);
}

/* ---------------- causal flash attention (HD=24) ------------------------- */
__global__ __launch_bounds__(128)
void attn_kernel(const float* __restrict__ qb, const float* __restrict__ kb,
                 const float* __restrict__ vb, float* __restrict__ ob)
{
    const int qt  = blockIdx.x, h = blockIdx.y, bz = blockIdx.z;
    const int tid = threadIdx.x;
    const int qi  = qt * 128 + tid;
    const size_t rowbase = ((size_t)bz * Ll) * DBb + (size_t)h * HDd;

    float qreg[HDd];
    const float* qp = qb + rowbase + (size_t)qi * DBb;
#pragma unroll
    for (int d = 0; d < HDd; d++) qreg[d] = qp[d];

    const float scale = rsqrtf((float)HDd);
    float m = -1e30f, l = 0.f, o[HDd];
#pragma unroll
    for (int d = 0; d < HDd; d++) o[d] = 0.f;

    __shared__ float Ks[128][HDd + 1];
    __shared__ float Vs[128][HDd + 1];

    for (int kt = 0; kt <= qt; kt++) {
        for (int e = tid; e < 128 * HDd; e += 128) {
            int j = e / HDd, d = e - j * HDd;
            size_t gidx = rowbase + (size_t)(kt * 128 + j) * DBb + d;
            Ks[j][d] = kb[gidx];
            Vs[j][d] = vb[gidx];
        }
        __syncthreads();
        int jmax = min(128, qi - kt * 128 + 1);
        for (int j = 0; j < jmax; j++) {
            float sdot = 0.f;
#pragma unroll
            for (int d = 0; d < HDd; d++) sdot += qreg[d] * Ks[j][d];
            sdot *= scale;
            float mn = fmaxf(m, sdot);
            float c  = __expf(m - mn);
            float p  = __expf(sdot - mn);
            l = l * c + p;
#pragma unroll
            for (int d = 0; d < HDd; d++) o[d] = o[d] * c + p * Vs[j][d];
            m = mn;
        }
        __syncthreads();
    }
    float inv = 1.f / l;
    float* op = ob + rowbase + (size_t)qi * DBb;
#pragma unroll
    for (int d = 0; d < HDd; d++) op[d] = o[d] * inv;
}

/* ---------------- small element/row kernels ------------------------------ */
__global__ void sub_bias_kernel(const float* __restrict__ xin,
                                const float* __restrict__ b,
                                float* __restrict__ x)
{
    int n = blockIdx.y, d = blockIdx.x * 256 + threadIdx.x;
    x[(size_t)n * DIN_ + d] = xin[(size_t)n * DIN_ + d] - b[d];
}

__global__ void rowstats_kernel(const float* __restrict__ Dz,
                                const float* __restrict__ x,
                                float* __restrict__ s)
{
    int n = blockIdx.x, tid = threadIdx.x;
    const float* dzr = Dz + (size_t)n * DIN_;
    const float* xr  = x  + (size_t)n * DIN_;
    float ss = 0.f, dt = 0.f;
    for (int i = tid; i < DIN_; i += 256) {
        float d = dzr[i];
        ss += d * d;
        dt += d * xr[i];
    }
#pragma unroll
    for (int o = 16; o; o >>= 1) {
        ss += __shfl_down_sync(0xffffffffu, ss, o);
        dt += __shfl_down_sync(0xffffffffu, dt, o);
    }
    __shared__ float a1[8], a2[8];
    if ((tid & 31) == 0) { a1[tid >> 5] = ss; a2[tid >> 5] = dt; }
    __syncthreads();
    if (tid == 0) {
        float S = 0.f, T = 0.f;
#pragma unroll
        for (int i = 0; i < 8; i++) { S += a1[i]; T += a2[i]; }
        float nrm = sqrtf(S) + 1e-6f;
        s[n] = T / (nrm * nrm);
    }
}

__global__ void zpred_update_kernel(const float* __restrict__ zp_,
                                    const float* __restrict__ s,
                                    float* __restrict__ zpred, int first)
{
    int n = blockIdx.y;
    int w = blockIdx.x * 256 + threadIdx.x;
    size_t idx = (size_t)n * Ww + w;
    float v = s[n] * zp_[idx];
    zpred[idx] = first ? v : (zpred[idx] + v);
}

__global__ void x_update_kernel(const float* __restrict__ Dz,
                                const float* __restrict__ s,
                                float* __restrict__ x)
{
    int n = blockIdx.y;
    int d = blockIdx.x * 256 + threadIdx.x;
    size_t idx = (size_t)n * DIN_ + d;
    x[idx] -= s[n] * Dz[idx];
}

/* ---------------- top-32 per row (iterative argmax over smem row) -------- */
__global__ void topk_kernel(const float* __restrict__ z,
                            float* __restrict__ tv, int* __restrict__ ti)
{
    extern __shared__ float sh[];
    __shared__ float rv[256];
    __shared__ int   ri[256];
    int row = blockIdx.x, tid = threadIdx.x;
    const float* zr = z + (size_t)row * Ww;
    for (int i = tid; i < Ww; i += 256) sh[i] = zr[i];
    __syncthreads();
    for (int it = 0; it < TOPK; it++) {
        float bm = -1.f; int bi = 0;
        for (int i = tid; i < Ww; i += 256) {
            float v = sh[i];
            if (v > bm) { bm = v; bi = i; }
        }
        rv[tid] = bm; ri[tid] = bi;
        __syncthreads();
        for (int sred = 128; sred > 0; sred >>= 1) {
            if (tid < sred) {
                float v2 = rv[tid + sred]; int i2 = ri[tid + sred];
                if (v2 > rv[tid] || (v2 == rv[tid] && i2 < ri[tid])) {
                    rv[tid] = v2; ri[tid] = i2;
                }
            }
            __syncthreads();
        }
        if (tid == 0) {
            tv[row * TOPK + it] = rv[0];
            ti[row * TOPK + it] = ri[0];
            sh[ri[0]] = -2.f;
        }
        __syncthreads();
    }
}

/* ---------------- sparse rank-32 add into recon output ------------------- */
__global__ void sparse_add_kernel(const float* __restrict__ tv,
                                  const int* __restrict__ ti,
                                  const float* __restrict__ D,
                                  float* __restrict__ out)
{
    __shared__ float sv[TOPK];
    __shared__ int   si[TOPK];
    int row = blockIdx.x, tid = threadIdx.x;
    if (tid < TOPK) { sv[tid] = tv[row * TOPK + tid]; si[tid] = ti[row * TOPK + tid]; }
    __syncthreads();
    for (int d = tid; d < DIN_; d += 256) {
        float a = out[(size_t)row * DIN_ + d];
#pragma unroll
        for (int j = 0; j < TOPK; j++)
            a += sv[j] * D[(size_t)si[j] * DIN_ + d];
        out[(size_t)row * DIN_ + d] = a;
    }
}

/* ---------------- driver -------------------------------------------------- */
extern "C" void kernel_launch(void* const* d_in, const int* in_sizes, int n_in,
                              void* d_out, int out_size)
{
    const float* x_in = (const float*)d_in[0];
    const float* D    = (const float*)d_in[1];
    const float* b    = (const float*)d_in[2];
    const float* Wq   = (const float*)d_in[3];
    const float* bq   = (const float*)d_in[4];
    const float* Wk   = (const float*)d_in[5];
    const float* bk   = (const float*)d_in[6];
    const float* Wv   = (const float*)d_in[7];
    const float* bv   = (const float*)d_in[8];
    const float* Wo   = (const float*)d_in[9];
    const float* bo   = (const float*)d_in[10];
    float* out = (float*)d_out;

    float *px, *pz, *pzp, *pq, *pk, *pv, *po, *pdz, *ps, *ptv;
    int* pti;
    cudaGetSymbolAddress((void**)&px,  g_x);
    cudaGetSymbolAddress((void**)&pz,  g_z);
    cudaGetSymbolAddress((void**)&pzp, g_zpred);
    cudaGetSymbolAddress((void**)&pq,  g_q);
    cudaGetSymbolAddress((void**)&pk,  g_k);
    cudaGetSymbolAddress((void**)&pv,  g_v);
    cudaGetSymbolAddress((void**)&po,  g_o);
    cudaGetSymbolAddress((void**)&pdz, g_Dz);
    cudaGetSymbolAddress((void**)&ps,  g_s);
    cudaGetSymbolAddress((void**)&ptv, g_tv);
    cudaGetSymbolAddress((void**)&pti, g_ti);

    cudaFuncSetAttribute(topk_kernel,
                         cudaFuncAttributeMaxDynamicSharedMemorySize,
                         Ww * (int)sizeof(float));
    cudaFuncSetAttribute(gemm_tc<0>,
                         cudaFuncAttributeMaxDynamicSharedMemorySize, SMEM_GEMM);
    cudaFuncSetAttribute(gemm_tc<1>,
                         cudaFuncAttributeMaxDynamicSharedMemorySize, SMEM_GEMM);
    cudaFuncSetAttribute(gemm_qkv,
                         cudaFuncAttributeMaxDynamicSharedMemorySize, SMEM_GEMM);

    dim3 blk(256);

    /* x = x_input - b */
    sub_bias_kernel<<<dim3(DIN_ / 256, NROWS), blk>>>(x_in, b, px);

    for (int i = 0; i < NLAY; i++) {
        /* z_in = relu(LAM * x @ D^T) */
        gemm_tc<1><<<dim3(Ww / 128, NROWS / 128), blk, SMEM_GEMM>>>(
            px, D, nullptr, pz, Ww, DIN_, DIN_, DIN_, LAMBDA, 1, 0);

        /* fused q / k / v (k,v read shifted rows of z_in) */
        gemm_qkv<<<dim3((DBb + 127) / 128, NROWS / 128, 3), blk, SMEM_GEMM>>>(
            pz,
            Wq + (size_t)i * Ww * DBb, Wk + (size_t)i * Ww * DBb, Wv + (size_t)i * Ww * DBb,
            bq + (size_t)i * DBb, bk + (size_t)i * DBb, bv + (size_t)i * DBb,
            pq, pk, pv);

        attn_kernel<<<dim3(Ll / 128, Hh, Bb), dim3(128)>>>(pq, pk, pv, po);

        /* z_pred_ = relu(o @ Wo + bo)  (overwrites z_in buffer) */
        gemm_tc<0><<<dim3(Ww / 128, NROWS / 128), blk, SMEM_GEMM>>>(
            po, Wo + (size_t)i * DBb * Ww, bo + (size_t)i * Ww, pz,
            Ww, DBb, DBb, Ww, 1.f, 3, 0);

        /* Dz = z_pred_ @ D */
        gemm_tc<0><<<dim3(DIN_ / 128, NROWS / 128), blk, SMEM_GEMM>>>(
            pz, D, nullptr, pdz, DIN_, Ww, Ww, DIN_, 1.f, 0, 0);

        rowstats_kernel<<<NROWS, 256>>>(pdz, px, ps);
        zpred_update_kernel<<<dim3(Ww / 256, NROWS), blk>>>(pz, ps, pzp, i == 0);
        x_update_kernel<<<dim3(DIN_ / 256, NROWS), blk>>>(pdz, ps, px);
    }

    /* z_novel = relu(LAM * x @ D^T) */
    gemm_tc<1><<<dim3(Ww / 128, NROWS / 128), blk, SMEM_GEMM>>>(
        px, D, nullptr, pz, Ww, DIN_, DIN_, DIN_, LAMBDA, 1, 0);

    topk_kernel<<<NROWS, 256, Ww * (int)sizeof(float)>>>(pz, ptv, pti);

    /* out = z_pred @ D + b, then add top-32 sparse codes */
    gemm_tc<0><<<dim3(DIN_ / 128, NROWS / 128), blk, SMEM_GEMM>>>(
        pzp, D, b, out, DIN_, Ww, Ww, DIN_, 1.f, 2, 0);

    sparse_add_kernel<<<NROWS, 256>>>(ptv, pti, D, out);
}

// round 12
// speedup vs baseline: 4.1820x; 1.1921x over previous
#include <cuda_runtime.h>
#include <cuda_fp16.h>
#include <math.h>
#include <stdint.h>

#define Bb   4
#define Ll   1024
#define DIN_ 768
#define Ww   12288
#define Hh   8
#define NLAY 2
#define DBb  192
#define HDd  24
#define TOPK 32
#define NROWS (Bb*Ll)          /* 4096 */
#define LAMBDA (1.0f/(4.0f*768.0f))

/* fp16 GEMM smem: rows of 32 halves stored as 16 u32 words + 2 pad = 18 */
#define RS16 18                 /* row stride in u32 words */
#define TW16 (128*RS16)         /* one 128-row tile = 2304 words = 9216 B */
#define SMEM_GEMM (4*TW16*4)    /* A0,A1,B0,B1 = 36864 B */

/* ---------------- scratch (device globals; no allocation allowed) -------- */
__device__ float g_x[NROWS*DIN_];
__device__ float g_z[NROWS*Ww];
__device__ float g_zpred[NROWS*Ww];
__device__ float g_q[NROWS*DBb];
__device__ float g_k[NROWS*DBb];
__device__ float g_v[NROWS*DBb];
__device__ float g_o[NROWS*DBb];
__device__ float g_Dz[NROWS*DIN_];
__device__ float g_s[NROWS];
__device__ float g_tv[NROWS*TOPK];
__device__ int   g_ti[NROWS*TOPK];

/* ---------------- helpers ------------------------------------------------ */
__device__ __forceinline__ uint32_t packh2(float lo, float hi)
{
    __half2 h = __floats2half2_rn(lo, hi);   /* .x = lo (low 16 bits) */
    return *reinterpret_cast<uint32_t*>(&h);
}

__device__ __forceinline__ void mma16(float* c,
                                      uint32_t a0, uint32_t a1, uint32_t a2, uint32_t a3,
                                      uint32_t b0, uint32_t b1)
{
    asm volatile(
        "mma.sync.aligned.m16n8k16.row.col.f32.f16.f16.f32 "
        "{%0,%1,%2,%3},{%4,%5,%6,%7},{%8,%9},{%0,%1,%2,%3};"
        : "+f"(c[0]), "+f"(c[1]), "+f"(c[2]), "+f"(c[3])
        : "r"(a0), "r"(a1), "r"(a2), "r"(a3), "r"(b0), "r"(b1));
}

/* pair-permutation within a k16 chunk: word for pair jj stored at
   pos(jj) = 2*(jj&3) + (jj>>2); reading LDS.64 at 2*tg returns pairs
   {tg, tg+4} = halves {2tg,2tg+1, 2tg+8,2tg+9} — the m16n8k16 fragment. */

/* ---------------- pipelined fp16 tensor-core GEMM core -------------------
   C[M,N] = epilogue(alpha * A x B)
   BLAYOUT 0: B is [K,N] row-major ("NN")
   BLAYOUT 1: B is [N,K] row-major ("NT")
   Both stage B into [n][perm(k)] half words -> unified compute path.
   flags: bit0 = relu, bit1 = add bias[gn]
   shiftA: row gm of A reads A[gm-1] (zeros when gm % Ll == 0)               */
template<int BLAYOUT>
__device__ __forceinline__ void gemm_core(
    int m0, int n0,
    const float* __restrict__ A, const float* __restrict__ B,
    const float* __restrict__ bias, float* __restrict__ C,
    int N, int K, int lda, int ldb, float alpha, int flags, int shiftA)
{
    extern __shared__ uint32_t dsm[];
    uint32_t* const A0 = dsm;
    uint32_t* const A1 = dsm + TW16;
    uint32_t* const B0 = dsm + 2 * TW16;
    uint32_t* const B1 = dsm + 3 * TW16;

    const int tid  = threadIdx.x;
    const int warp = tid >> 5, lane = tid & 31;
    const int g    = lane >> 2, tg = lane & 3;
    const int wm0  = (warp & 1) * 64;
    const int wn0  = (warp >> 1) * 32;

    /* row-major float4 staging decomposition (A and NT-B) */
    const int lr2 = tid >> 3;          /* 0..31 */
    const int lt  = tid & 7;           /* k = 4*lt .. 4*lt+3 */
    const int ltc   = lt & 3;
    const int wbase = 8 * (lt >> 2) + (ltc & 1) * 4 + (ltc >> 1);

    /* NN-B staging decomposition: one n column per thread */
    const int nnB = tid & 127;         /* local n */
    const int kbB = (tid >> 7) * 16;   /* k-half base: 0 or 16 */

    float acc[4][4][4];
#pragma unroll
    for (int mf = 0; mf < 4; mf++)
#pragma unroll
        for (int nf = 0; nf < 4; nf++)
#pragma unroll
            for (int e = 0; e < 4; e++) acc[mf][nf][e] = 0.f;

    float4 ra[4], rb4[4];
    float  rbn[16];

    auto ldA = [&](int k0) {
#pragma unroll
        for (int i = 0; i < 4; i++) {
            int gm = m0 + lr2 + i * 32;
            float4 av = make_float4(0.f, 0.f, 0.f, 0.f);
            if (shiftA) {
                if ((gm & (Ll - 1)) != 0)
                    av = *reinterpret_cast<const float4*>(&A[(size_t)(gm - 1) * lda + k0 + lt * 4]);
            } else {
                av = *reinterpret_cast<const float4*>(&A[(size_t)gm * lda + k0 + lt * 4]);
            }
            ra[i] = av;
        }
    };
    auto ldB = [&](int k0) {
        if (BLAYOUT == 1) {
#pragma unroll
            for (int i = 0; i < 4; i++) {
                int gn = n0 + lr2 + i * 32;
                float4 bv = make_float4(0.f, 0.f, 0.f, 0.f);
                if (gn < N)
                    bv = *reinterpret_cast<const float4*>(&B[(size_t)gn * ldb + k0 + lt * 4]);
                rb4[i] = bv;
            }
        } else {
            int gn = n0 + nnB;
            bool ok = (gn < N);
#pragma unroll
            for (int m = 0; m < 16; m++)
                rbn[m] = ok ? B[(size_t)(k0 + kbB + m) * ldb + gn] : 0.f;
        }
    };
    auto stA = [&](uint32_t* As) {
#pragma unroll
        for (int i = 0; i < 4; i++) {
            uint32_t* dst = &As[(lr2 + i * 32) * RS16 + wbase];
            dst[0] = packh2(ra[i].x, ra[i].y);
            dst[2] = packh2(ra[i].z, ra[i].w);
        }
    };
    auto stB = [&](uint32_t* Bs) {
        if (BLAYOUT == 1) {
#pragma unroll
            for (int i = 0; i < 4; i++) {
                uint32_t* dst = &Bs[(lr2 + i * 32) * RS16 + wbase];
                dst[0] = packh2(rb4[i].x, rb4[i].y);
                dst[2] = packh2(rb4[i].z, rb4[i].w);
            }
        } else {
            uint32_t* row = &Bs[nnB * RS16 + (kbB >> 1)];  /* chunk base 8*(kbB/16) */
#pragma unroll
            for (int t = 0; t < 8; t++) {
                int pos = 2 * (t & 3) + (t >> 2);
                row[pos] = packh2(rbn[2 * t], rbn[2 * t + 1]);
            }
        }
    };
    auto compute = [&](const uint32_t* As, const uint32_t* Bs) {
#pragma unroll
        for (int c = 0; c < 2; c++) {
            const int base = c * 8 + 2 * tg;
            uint2 Bv[4];
#pragma unroll
            for (int nf = 0; nf < 4; nf++)
                Bv[nf] = *reinterpret_cast<const uint2*>(&Bs[(wn0 + nf * 8 + g) * RS16 + base]);
            uint2 Alo[4], Ahi[4];
#pragma unroll
            for (int mf = 0; mf < 4; mf++) {
                int r0 = wm0 + mf * 16 + g;
                Alo[mf] = *reinterpret_cast<const uint2*>(&As[r0 * RS16 + base]);
                Ahi[mf] = *reinterpret_cast<const uint2*>(&As[(r0 + 8) * RS16 + base]);
            }
#pragma unroll
            for (int mf = 0; mf < 4; mf++)
#pragma unroll
                for (int nf = 0; nf < 4; nf++)
                    mma16(acc[mf][nf],
                          Alo[mf].x, Ahi[mf].x, Alo[mf].y, Ahi[mf].y,
                          Bv[nf].x, Bv[nf].y);
        }
    };

    const int NTILES = K >> 5;
    ldA(0); ldB(0);
    stA(A0); stB(B0);
    __syncthreads();
    for (int t = 0; t < NTILES; t++) {
        const bool cur = (t & 1) != 0;
        const bool more = (t + 1 < NTILES);
        if (more) { ldA((t + 1) << 5); ldB((t + 1) << 5); }
        compute(cur ? A1 : A0, cur ? B1 : B0);
        if (more) {
            stA(cur ? A0 : A1);
            stB(cur ? B0 : B1);
            __syncthreads();
        }
    }

    /* ---- epilogue (c-fragment layout identical to m16n8k8) ---- */
#pragma unroll
    for (int mf = 0; mf < 4; mf++) {
#pragma unroll
        for (int nf = 0; nf < 4; nf++) {
            int gm = m0 + wm0 + mf * 16 + g;
            int gn = n0 + wn0 + nf * 8 + 2 * tg;
            if (gn < N) {
                float bsum  = (flags & 2) ? bias[gn] : 0.f;
                float bsum1 = (flags & 2) ? bias[gn + 1] : 0.f;
                float v0 = acc[mf][nf][0] * alpha + bsum;
                float v1 = acc[mf][nf][1] * alpha + bsum1;
                float v2 = acc[mf][nf][2] * alpha + bsum;
                float v3 = acc[mf][nf][3] * alpha + bsum1;
                if (flags & 1) {
                    v0 = fmaxf(v0, 0.f); v1 = fmaxf(v1, 0.f);
                    v2 = fmaxf(v2, 0.f); v3 = fmaxf(v3, 0.f);
                }
                *reinterpret_cast<float2*>(&C[(size_t)gm * N + gn])       = make_float2(v0, v1);
                *reinterpret_cast<float2*>(&C[(size_t)(gm + 8) * N + gn]) = make_float2(v2, v3);
            }
        }
    }
}

template<int BLAYOUT>
__global__ __launch_bounds__(256)
void gemm_tc(const float* __restrict__ A, const float* __restrict__ B,
             const float* __restrict__ bias, float* __restrict__ C,
             int N, int K, int lda, int ldb,
             float alpha, int flags, int shiftA)
{
    gemm_core<BLAYOUT>(blockIdx.y * 128, blockIdx.x * 128,
                       A, B, bias, C, N, K, lda, ldb, alpha, flags, shiftA);
}

/* fused q/k/v: blockIdx.z selects the matrix; k,v read shifted A rows */
__global__ __launch_bounds__(256)
void gemm_qkv(const float* __restrict__ z,
              const float* __restrict__ Wq, const float* __restrict__ Wk,
              const float* __restrict__ Wv,
              const float* __restrict__ bq, const float* __restrict__ bk,
              const float* __restrict__ bv,
              float* __restrict__ q, float* __restrict__ k, float* __restrict__ v)
{
    const float* Bp; const float* bp; float* Cp; int shift;
    if (blockIdx.z == 0)      { Bp = Wq; bp = bq; Cp = q; shift = 0; }
    else if (blockIdx.z == 1) { Bp = Wk; bp = bk; Cp = k; shift = 1; }
    else                      { Bp = Wv; bp = bv; Cp = v; shift = 1; }
    gemm_core<0>(blockIdx.y * 128, blockIdx.x * 128,
                 z, Bp, bp, Cp, DBb, Ww, Ww, DBb, 1.f, 2, shift);
}

/* ---------------- causal flash attention (HD=24) ------------------------- */
__global__ __launch_bounds__(128)
void attn_kernel(const float* __restrict__ qb, const float* __restrict__ kb,
                 const float* __restrict__ vb, float* __restrict__ ob)
{
    const int qt  = blockIdx.x, h = blockIdx.y, bz = blockIdx.z;
    const int tid = threadIdx.x;
    const int qi  = qt * 128 + tid;
    const size_t rowbase = ((size_t)bz * Ll) * DBb + (size_t)h * HDd;

    float qreg[HDd];
    const float* qp = qb + rowbase + (size_t)qi * DBb;
#pragma unroll
    for (int d = 0; d < HDd; d++) qreg[d] = qp[d];

    const float scale = rsqrtf((float)HDd);
    float m = -1e30f, l = 0.f, o[HDd];
#pragma unroll
    for (int d = 0; d < HDd; d++) o[d] = 0.f;

    __shared__ float Ks[128][HDd + 1];
    __shared__ float Vs[128][HDd + 1];

    for (int kt = 0; kt <= qt; kt++) {
        for (int e = tid; e < 128 * HDd; e += 128) {
            int j = e / HDd, d = e - j * HDd;
            size_t gidx = rowbase + (size_t)(kt * 128 + j) * DBb + d;
            Ks[j][d] = kb[gidx];
            Vs[j][d] = vb[gidx];
        }
        __syncthreads();
        int jmax = min(128, qi - kt * 128 + 1);
        for (int j = 0; j < jmax; j++) {
            float sdot = 0.f;
#pragma unroll
            for (int d = 0; d < HDd; d++) sdot += qreg[d] * Ks[j][d];
            sdot *= scale;
            float mn = fmaxf(m, sdot);
            float c  = __expf(m - mn);
            float p  = __expf(sdot - mn);
            l = l * c + p;
#pragma unroll
            for (int d = 0; d < HDd; d++) o[d] = o[d] * c + p * Vs[j][d];
            m = mn;
        }
        __syncthreads();
    }
    float inv = 1.f / l;
    float* op = ob + rowbase + (size_t)qi * DBb;
#pragma unroll
    for (int d = 0; d < HDd; d++) op[d] = o[d] * inv;
}

/* ---------------- small element/row kernels ------------------------------ */
__global__ void sub_bias_kernel(const float* __restrict__ xin,
                                const float* __restrict__ b,
                                float* __restrict__ x)
{
    int n = blockIdx.y, d = blockIdx.x * 256 + threadIdx.x;
    x[(size_t)n * DIN_ + d] = xin[(size_t)n * DIN_ + d] - b[d];
}

__global__ void rowstats_kernel(const float* __restrict__ Dz,
                                const float* __restrict__ x,
                                float* __restrict__ s)
{
    int n = blockIdx.x, tid = threadIdx.x;
    const float* dzr = Dz + (size_t)n * DIN_;
    const float* xr  = x  + (size_t)n * DIN_;
    float ss = 0.f, dt = 0.f;
    for (int i = tid; i < DIN_; i += 256) {
        float d = dzr[i];
        ss += d * d;
        dt += d * xr[i];
    }
#pragma unroll
    for (int o = 16; o; o >>= 1) {
        ss += __shfl_down_sync(0xffffffffu, ss, o);
        dt += __shfl_down_sync(0xffffffffu, dt, o);
    }
    __shared__ float a1[8], a2[8];
    if ((tid & 31) == 0) { a1[tid >> 5] = ss; a2[tid >> 5] = dt; }
    __syncthreads();
    if (tid == 0) {
        float S = 0.f, T = 0.f;
#pragma unroll
        for (int i = 0; i < 8; i++) { S += a1[i]; T += a2[i]; }
        float nrm = sqrtf(S) + 1e-6f;
        s[n] = T / (nrm * nrm);
    }
}

__global__ void zpred_update_kernel(const float* __restrict__ zp_,
                                    const float* __restrict__ s,
                                    float* __restrict__ zpred, int first)
{
    int n = blockIdx.y;
    int w = blockIdx.x * 256 + threadIdx.x;
    size_t idx = (size_t)n * Ww + w;
    float v = s[n] * zp_[idx];
    zpred[idx] = first ? v : (zpred[idx] + v);
}

__global__ void x_update_kernel(const float* __restrict__ Dz,
                                const float* __restrict__ s,
                                float* __restrict__ x)
{
    int n = blockIdx.y;
    int d = blockIdx.x * 256 + threadIdx.x;
    size_t idx = (size_t)n * DIN_ + d;
    x[idx] -= s[n] * Dz[idx];
}

/* ---------------- top-32 per row (iterative argmax over smem row) -------- */
__global__ void topk_kernel(const float* __restrict__ z,
                            float* __restrict__ tv, int* __restrict__ ti)
{
    extern __shared__ float sh[];
    __shared__ float rv[256];
    __shared__ int   ri[256];
    int row = blockIdx.x, tid = threadIdx.x;
    const float* zr = z + (size_t)row * Ww;
    for (int i = tid; i < Ww; i += 256) sh[i] = zr[i];
    __syncthreads();
    for (int it = 0; it < TOPK; it++) {
        float bm = -1.f; int bi = 0;
        for (int i = tid; i < Ww; i += 256) {
            float v = sh[i];
            if (v > bm) { bm = v; bi = i; }
        }
        rv[tid] = bm; ri[tid] = bi;
        __syncthreads();
        for (int sred = 128; sred > 0; sred >>= 1) {
            if (tid < sred) {
                float v2 = rv[tid + sred]; int i2 = ri[tid + sred];
                if (v2 > rv[tid] || (v2 == rv[tid] && i2 < ri[tid])) {
                    rv[tid] = v2; ri[tid] = i2;
                }
            }
            __syncthreads();
        }
        if (tid == 0) {
            tv[row * TOPK + it] = rv[0];
            ti[row * TOPK + it] = ri[0];
            sh[ri[0]] = -2.f;
        }
        __syncthreads();
    }
}

/* ---------------- sparse rank-32 add into recon output ------------------- */
__global__ void sparse_add_kernel(const float* __restrict__ tv,
                                  const int* __restrict__ ti,
                                  const float* __restrict__ D,
                                  float* __restrict__ out)
{
    __shared__ float sv[TOPK];
    __shared__ int   si[TOPK];
    int row = blockIdx.x, tid = threadIdx.x;
    if (tid < TOPK) { sv[tid] = tv[row * TOPK + tid]; si[tid] = ti[row * TOPK + tid]; }
    __syncthreads();
    for (int d = tid; d < DIN_; d += 256) {
        float a = out[(size_t)row * DIN_ + d];
#pragma unroll
        for (int j = 0; j < TOPK; j++)
            a += sv[j] * D[(size_t)si[j] * DIN_ + d];
        out[(size_t)row * DIN_ + d] = a;
    }
}

/* ---------------- driver -------------------------------------------------- */
extern "C" void kernel_launch(void* const* d_in, const int* in_sizes, int n_in,
                              void* d_out, int out_size)
{
    const float* x_in = (const float*)d_in[0];
    const float* D    = (const float*)d_in[1];
    const float* b    = (const float*)d_in[2];
    const float* Wq   = (const float*)d_in[3];
    const float* bq   = (const float*)d_in[4];
    const float* Wk   = (const float*)d_in[5];
    const float* bk   = (const float*)d_in[6];
    const float* Wv   = (const float*)d_in[7];
    const float* bv   = (const float*)d_in[8];
    const float* Wo   = (const float*)d_in[9];
    const float* bo   = (const float*)d_in[10];
    float* out = (float*)d_out;

    float *px, *pz, *pzp, *pq, *pk, *pv, *po, *pdz, *ps, *ptv;
    int* pti;
    cudaGetSymbolAddress((void**)&px,  g_x);
    cudaGetSymbolAddress((void**)&pz,  g_z);
    cudaGetSymbolAddress((void**)&pzp, g_zpred);
    cudaGetSymbolAddress((void**)&pq,  g_q);
    cudaGetSymbolAddress((void**)&pk,  g_k);
    cudaGetSymbolAddress((void**)&pv,  g_v);
    cudaGetSymbolAddress((void**)&po,  g_o);
    cudaGetSymbolAddress((void**)&pdz, g_Dz);
    cudaGetSymbolAddress((void**)&ps,  g_s);
    cudaGetSymbolAddress((void**)&ptv, g_tv);
    cudaGetSymbolAddress((void**)&pti, g_ti);

    cudaFuncSetAttribute(topk_kernel,
                         cudaFuncAttributeMaxDynamicSharedMemorySize,
                         Ww * (int)sizeof(float));

    dim3 blk(256);

    /* x = x_input - b */
    sub_bias_kernel<<<dim3(DIN_ / 256, NROWS), blk>>>(x_in, b, px);

    for (int i = 0; i < NLAY; i++) {
        /* z_in = relu(LAM * x @ D^T) */
        gemm_tc<1><<<dim3(Ww / 128, NROWS / 128), blk, SMEM_GEMM>>>(
            px, D, nullptr, pz, Ww, DIN_, DIN_, DIN_, LAMBDA, 1, 0);

        /* fused q / k / v (k,v read shifted rows of z_in) */
        gemm_qkv<<<dim3((DBb + 127) / 128, NROWS / 128, 3), blk, SMEM_GEMM>>>(
            pz,
            Wq + (size_t)i * Ww * DBb, Wk + (size_t)i * Ww * DBb, Wv + (size_t)i * Ww * DBb,
            bq + (size_t)i * DBb, bk + (size_t)i * DBb, bv + (size_t)i * DBb,
            pq, pk, pv);

        attn_kernel<<<dim3(Ll / 128, Hh, Bb), dim3(128)>>>(pq, pk, pv, po);

        /* z_pred_ = relu(o @ Wo + bo)  (overwrites z_in buffer) */
        gemm_tc<0><<<dim3(Ww / 128, NROWS / 128), blk, SMEM_GEMM>>>(
            po, Wo + (size_t)i * DBb * Ww, bo + (size_t)i * Ww, pz,
            Ww, DBb, DBb, Ww, 1.f, 3, 0);

        /* Dz = z_pred_ @ D */
        gemm_tc<0><<<dim3(DIN_ / 128, NROWS / 128), blk, SMEM_GEMM>>>(
            pz, D, nullptr, pdz, DIN_, Ww, Ww, DIN_, 1.f, 0, 0);

        rowstats_kernel<<<NROWS, 256>>>(pdz, px, ps);
        zpred_update_kernel<<<dim3(Ww / 256, NROWS), blk>>>(pz, ps, pzp, i == 0);
        x_update_kernel<<<dim3(DIN_ / 256, NROWS), blk>>>(pdz, ps, px);
    }

    /* z_novel = relu(LAM * x @ D^T) */
    gemm_tc<1><<<dim3(Ww / 128, NROWS / 128), blk, SMEM_GEMM>>>(
        px, D, nullptr, pz, Ww, DIN_, DIN_, DIN_, LAMBDA, 1, 0);

    topk_kernel<<<NROWS, 256, Ww * (int)sizeof(float)>>>(pz, ptv, pti);

    /* out = z_pred @ D + b, then add top-32 sparse codes */
    gemm_tc<0><<<dim3(DIN_ / 128, NROWS / 128), blk, SMEM_GEMM>>>(
        pzp, D, b, out, DIN_, Ww, Ww, DIN_, 1.f, 2, 0);

    sparse_add_kernel<<<NROWS, 256>>>(ptv, pti, D, out);
}

// round 14
// speedup vs baseline: 5.2388x; 1.2527x over previous
#include <cuda_runtime.h>
#include <cuda_fp16.h>
#include <math.h>
#include <stdint.h>

#define Bb   4
#define Ll   1024
#define DIN_ 768
#define Ww   12288
#define Hh   8
#define NLAY 2
#define DBb  192
#define HDd  24
#define TOPK 32
#define NROWS (Bb*Ll)          /* 4096 */
#define LAMBDA (1.0f/(4.0f*768.0f))

/* fp16 GEMM smem: rows of 32 halves stored as 16 u32 words + 2 pad = 18 */
#define RS16 18
#define TW16 (128*RS16)
#define SMEM_GEMM (4*TW16*4)    /* A0,A1,B0,B1 = 36864 B */

/* ---------------- scratch (device globals; no allocation allowed) -------- */
__device__ float  g_x[NROWS*DIN_];
__device__ float  g_z[NROWS*Ww];
__device__ float  g_zpred[NROWS*Ww];
__device__ float  g_q[NROWS*DBb];
__device__ float  g_k[NROWS*DBb];
__device__ float  g_v[NROWS*DBb];
__device__ float  g_Dz[NROWS*DIN_];
__device__ float  g_s[NROWS];
__device__ float  g_tv[NROWS*TOPK];
__device__ int    g_ti[NROWS*TOPK];
/* half-resident operands */
__device__ __half g_xh[NROWS*DIN_];
__device__ __half g_zh[NROWS*Ww];
__device__ __half g_zph[NROWS*Ww];
__device__ __half g_oh[NROWS*DBb];
__device__ __half g_Dh[Ww*DIN_];           /* D     [Ww, DIN_]  (encode B)  */
__device__ __half g_DTh[DIN_*Ww];          /* D^T   [DIN_, Ww]  (Dz/recon B)*/
__device__ __half g_WqT[NLAY*DBb*Ww];      /* Wq^T  [DBb, Ww]               */
__device__ __half g_WkT[NLAY*DBb*Ww];
__device__ __half g_WvT[NLAY*DBb*Ww];
__device__ __half g_WoT[NLAY*Ww*DBb];      /* Wo^T  [Ww, DBb]               */

/* ---------------- helpers ------------------------------------------------ */
__device__ __forceinline__ void mma16(float* c,
                                      uint32_t a0, uint32_t a1, uint32_t a2, uint32_t a3,
                                      uint32_t b0, uint32_t b1)
{
    asm volatile(
        "mma.sync.aligned.m16n8k16.row.col.f32.f16.f16.f32 "
        "{%0,%1,%2,%3},{%4,%5,%6,%7},{%8,%9},{%0,%1,%2,%3};"
        : "+f"(c[0]), "+f"(c[1]), "+f"(c[2]), "+f"(c[3])
        : "r"(a0), "r"(a1), "r"(a2), "r"(a3), "r"(b0), "r"(b1));
}

/* ---------------- pipelined fp16 GEMM core (all-NT, half operands) --------
   C[M,N] = epilogue(alpha * A x B^T_layout)   A: [M,K] half, B: [N,K] half
   flags: bit0 relu, bit1 bias, bit2 write half Ch, bit3 skip fp32 C
   shiftA: row gm of A reads A[gm-1] (zeros when gm % Ll == 0)               */
__device__ __forceinline__ void gemm_core(
    int m0, int n0,
    const __half* __restrict__ A, const __half* __restrict__ B,
    const float* __restrict__ bias, float* __restrict__ C, __half* __restrict__ Ch,
    int N, int K, int lda, int ldb, float alpha, int flags, int shiftA)
{
    extern __shared__ uint32_t dsm[];
    uint32_t* const A0 = dsm;
    uint32_t* const A1 = dsm + TW16;
    uint32_t* const B0 = dsm + 2 * TW16;
    uint32_t* const B1 = dsm + 3 * TW16;

    const int tid  = threadIdx.x;
    const int warp = tid >> 5, lane = tid & 31;
    const int g    = lane >> 2, tg = lane & 3;
    const int wm0  = (warp & 1) * 64;
    const int wn0  = (warp >> 1) * 32;

    const int lr2 = tid >> 3;          /* 0..31 */
    const int lt  = tid & 7;           /* halves 4lt..4lt+3 = pairs 2lt,2lt+1 */
    const int ltc   = lt & 3;
    const int wbase = 8 * (lt >> 2) + (ltc & 1) * 4 + (ltc >> 1);

    float acc[4][4][4];
#pragma unroll
    for (int mf = 0; mf < 4; mf++)
#pragma unroll
        for (int nf = 0; nf < 4; nf++)
#pragma unroll
            for (int e = 0; e < 4; e++) acc[mf][nf][e] = 0.f;

    uint2 ra[4], rb[4];

    auto ldA = [&](int k0) {
#pragma unroll
        for (int i = 0; i < 4; i++) {
            int gm = m0 + lr2 + i * 32;
            uint2 av = make_uint2(0u, 0u);
            if (shiftA) {
                if ((gm & (Ll - 1)) != 0)
                    av = *reinterpret_cast<const uint2*>(&A[(size_t)(gm - 1) * lda + k0 + lt * 4]);
            } else {
                av = *reinterpret_cast<const uint2*>(&A[(size_t)gm * lda + k0 + lt * 4]);
            }
            ra[i] = av;
        }
    };
    auto ldB = [&](int k0) {
#pragma unroll
        for (int i = 0; i < 4; i++) {
            int gn = n0 + lr2 + i * 32;
            uint2 bv = make_uint2(0u, 0u);
            if (gn < N)
                bv = *reinterpret_cast<const uint2*>(&B[(size_t)gn * ldb + k0 + lt * 4]);
            rb[i] = bv;
        }
    };
    auto stA = [&](uint32_t* As) {
#pragma unroll
        for (int i = 0; i < 4; i++) {
            uint32_t* dst = &As[(lr2 + i * 32) * RS16 + wbase];
            dst[0] = ra[i].x;
            dst[2] = ra[i].y;
        }
    };
    auto stB = [&](uint32_t* Bs) {
#pragma unroll
        for (int i = 0; i < 4; i++) {
            uint32_t* dst = &Bs[(lr2 + i * 32) * RS16 + wbase];
            dst[0] = rb[i].x;
            dst[2] = rb[i].y;
        }
    };
    auto compute = [&](const uint32_t* As, const uint32_t* Bs) {
#pragma unroll
        for (int c = 0; c < 2; c++) {
            const int base = c * 8 + 2 * tg;
            uint2 Bv[4];
#pragma unroll
            for (int nf = 0; nf < 4; nf++)
                Bv[nf] = *reinterpret_cast<const uint2*>(&Bs[(wn0 + nf * 8 + g) * RS16 + base]);
            uint2 Alo[4], Ahi[4];
#pragma unroll
            for (int mf = 0; mf < 4; mf++) {
                int r0 = wm0 + mf * 16 + g;
                Alo[mf] = *reinterpret_cast<const uint2*>(&As[r0 * RS16 + base]);
                Ahi[mf] = *reinterpret_cast<const uint2*>(&As[(r0 + 8) * RS16 + base]);
            }
#pragma unroll
            for (int mf = 0; mf < 4; mf++)
#pragma unroll
                for (int nf = 0; nf < 4; nf++)
                    mma16(acc[mf][nf],
                          Alo[mf].x, Ahi[mf].x, Alo[mf].y, Ahi[mf].y,
                          Bv[nf].x, Bv[nf].y);
        }
    };

    const int NTILES = K >> 5;
    ldA(0); ldB(0);
    stA(A0); stB(B0);
    __syncthreads();
    for (int t = 0; t < NTILES; t++) {
        const bool cur = (t & 1) != 0;
        const bool more = (t + 1 < NTILES);
        if (more) { ldA((t + 1) << 5); ldB((t + 1) << 5); }
        compute(cur ? A1 : A0, cur ? B1 : B0);
        if (more) {
            stA(cur ? A0 : A1);
            stB(cur ? B0 : B1);
            __syncthreads();
        }
    }

    /* ---- epilogue ---- */
#pragma unroll
    for (int mf = 0; mf < 4; mf++) {
#pragma unroll
        for (int nf = 0; nf < 4; nf++) {
            int gm = m0 + wm0 + mf * 16 + g;
            int gn = n0 + wn0 + nf * 8 + 2 * tg;
            if (gn < N) {
                float bsum  = (flags & 2) ? bias[gn] : 0.f;
                float bsum1 = (flags & 2) ? bias[gn + 1] : 0.f;
                float v0 = acc[mf][nf][0] * alpha + bsum;
                float v1 = acc[mf][nf][1] * alpha + bsum1;
                float v2 = acc[mf][nf][2] * alpha + bsum;
                float v3 = acc[mf][nf][3] * alpha + bsum1;
                if (flags & 1) {
                    v0 = fmaxf(v0, 0.f); v1 = fmaxf(v1, 0.f);
                    v2 = fmaxf(v2, 0.f); v3 = fmaxf(v3, 0.f);
                }
                if (!(flags & 8)) {
                    *reinterpret_cast<float2*>(&C[(size_t)gm * N + gn])       = make_float2(v0, v1);
                    *reinterpret_cast<float2*>(&C[(size_t)(gm + 8) * N + gn]) = make_float2(v2, v3);
                }
                if (flags & 4) {
                    *reinterpret_cast<__half2*>(&Ch[(size_t)gm * N + gn]) =
                        __floats2half2_rn(v0, v1);
                    *reinterpret_cast<__half2*>(&Ch[(size_t)(gm + 8) * N + gn]) =
                        __floats2half2_rn(v2, v3);
                }
            }
        }
    }
}

__global__ __launch_bounds__(256, 2)
void gemm_tc(const __half* __restrict__ A, const __half* __restrict__ B,
             const float* __restrict__ bias, float* __restrict__ C,
             __half* __restrict__ Ch,
             int N, int K, int lda, int ldb,
             float alpha, int flags, int shiftA)
{
    gemm_core(blockIdx.y * 128, blockIdx.x * 128,
              A, B, bias, C, Ch, N, K, lda, ldb, alpha, flags, shiftA);
}

/* fused q/k/v: blockIdx.z selects the matrix; k,v read shifted A rows */
__global__ __launch_bounds__(256, 2)
void gemm_qkv(const __half* __restrict__ zh,
              const __half* __restrict__ WqT, const __half* __restrict__ WkT,
              const __half* __restrict__ WvT,
              const float* __restrict__ bq, const float* __restrict__ bk,
              const float* __restrict__ bv,
              float* __restrict__ q, float* __restrict__ k, float* __restrict__ v)
{
    const __half* Bp; const float* bp; float* Cp; int shift;
    if (blockIdx.z == 0)      { Bp = WqT; bp = bq; Cp = q; shift = 0; }
    else if (blockIdx.z == 1) { Bp = WkT; bp = bk; Cp = k; shift = 1; }
    else                      { Bp = WvT; bp = bv; Cp = v; shift = 1; }
    gemm_core(blockIdx.y * 128, blockIdx.x * 128,
              zh, Bp, bp, Cp, nullptr, DBb, Ww, Ww, Ww, 1.f, 2, shift);
}

/* ---------------- conversion kernels ------------------------------------- */
__global__ void cvt_kernel(const float* __restrict__ src, __half* __restrict__ dst)
{
    size_t i = (size_t)blockIdx.x * 256 + threadIdx.x;
    dst[i] = __float2half(src[i]);
}

/* [R,C] fp32 -> [C,R] half, R,C multiples of 32 */
__global__ void cvtT_kernel(const float* __restrict__ src, __half* __restrict__ dst,
                            int R, int C)
{
    __shared__ float t[32][33];
    int c0 = blockIdx.x * 32, r0 = blockIdx.y * 32;
    int tx = threadIdx.x & 31, ty = threadIdx.x >> 5;   /* 8 rows per iter */
#pragma unroll
    for (int j = 0; j < 4; j++)
        t[ty + 8 * j][tx] = src[(size_t)(r0 + ty + 8 * j) * C + c0 + tx];
    __syncthreads();
#pragma unroll
    for (int j = 0; j < 4; j++)
        dst[(size_t)(c0 + ty + 8 * j) * R + r0 + tx] = __float2half(t[tx][ty + 8 * j]);
}

/* ---------------- causal flash attention (HD=24) ------------------------- */
__global__ __launch_bounds__(128)
void attn_kernel(const float* __restrict__ qb, const float* __restrict__ kb,
                 const float* __restrict__ vb, __half* __restrict__ ob)
{
    const int qt  = blockIdx.x, h = blockIdx.y, bz = blockIdx.z;
    const int tid = threadIdx.x;
    const int qi  = qt * 128 + tid;
    const size_t rowbase = ((size_t)bz * Ll) * DBb + (size_t)h * HDd;

    float qreg[HDd];
    const float* qp = qb + rowbase + (size_t)qi * DBb;
#pragma unroll
    for (int d = 0; d < HDd; d++) qreg[d] = qp[d];

    const float scale = rsqrtf((float)HDd);
    float m = -1e30f, l = 0.f, o[HDd];
#pragma unroll
    for (int d = 0; d < HDd; d++) o[d] = 0.f;

    __shared__ float Ks[128][HDd + 1];
    __shared__ float Vs[128][HDd + 1];

    for (int kt = 0; kt <= qt; kt++) {
        for (int e = tid; e < 128 * HDd; e += 128) {
            int j = e / HDd, d = e - j * HDd;
            size_t gidx = rowbase + (size_t)(kt * 128 + j) * DBb + d;
            Ks[j][d] = kb[gidx];
            Vs[j][d] = vb[gidx];
        }
        __syncthreads();
        int jmax = min(128, qi - kt * 128 + 1);
        for (int j = 0; j < jmax; j++) {
            float sdot = 0.f;
#pragma unroll
            for (int d = 0; d < HDd; d++) sdot += qreg[d] * Ks[j][d];
            sdot *= scale;
            float mn = fmaxf(m, sdot);
            float c  = __expf(m - mn);
            float p  = __expf(sdot - mn);
            l = l * c + p;
#pragma unroll
            for (int d = 0; d < HDd; d++) o[d] = o[d] * c + p * Vs[j][d];
            m = mn;
        }
        __syncthreads();
    }
    float inv = 1.f / l;
    __half* op = ob + rowbase + (size_t)qi * DBb;
#pragma unroll
    for (int d = 0; d < HDd; d += 2)
        *reinterpret_cast<__half2*>(&op[d]) = __floats2half2_rn(o[d] * inv, o[d + 1] * inv);
}

/* ---------------- small element/row kernels ------------------------------ */
__global__ void sub_bias_kernel(const float* __restrict__ xin,
                                const float* __restrict__ b,
                                float* __restrict__ x, __half* __restrict__ xh)
{
    int n = blockIdx.y, d = blockIdx.x * 256 + threadIdx.x;
    float v = xin[(size_t)n * DIN_ + d] - b[d];
    x[(size_t)n * DIN_ + d]  = v;
    xh[(size_t)n * DIN_ + d] = __float2half(v);
}

__global__ void rowstats_kernel(const float* __restrict__ Dz,
                                const float* __restrict__ x,
                                float* __restrict__ s)
{
    int n = blockIdx.x, tid = threadIdx.x;
    const float* dzr = Dz + (size_t)n * DIN_;
    const float* xr  = x  + (size_t)n * DIN_;
    float ss = 0.f, dt = 0.f;
    for (int i = tid; i < DIN_; i += 256) {
        float d = dzr[i];
        ss += d * d;
        dt += d * xr[i];
    }
#pragma unroll
    for (int o = 16; o; o >>= 1) {
        ss += __shfl_down_sync(0xffffffffu, ss, o);
        dt += __shfl_down_sync(0xffffffffu, dt, o);
    }
    __shared__ float a1[8], a2[8];
    if ((tid & 31) == 0) { a1[tid >> 5] = ss; a2[tid >> 5] = dt; }
    __syncthreads();
    if (tid == 0) {
        float S = 0.f, T = 0.f;
#pragma unroll
        for (int i = 0; i < 8; i++) { S += a1[i]; T += a2[i]; }
        float nrm = sqrtf(S) + 1e-6f;
        s[n] = T / (nrm * nrm);
    }
}

__global__ void zpred_update_kernel(const float* __restrict__ zp_,
                                    const float* __restrict__ s,
                                    float* __restrict__ zpred,
                                    __half* __restrict__ zpredh, int first)
{
    int n = blockIdx.y;
    int w = blockIdx.x * 256 + threadIdx.x;
    size_t idx = (size_t)n * Ww + w;
    float v = s[n] * zp_[idx];
    float nv = first ? v : (zpred[idx] + v);
    zpred[idx]  = nv;
    zpredh[idx] = __float2half(nv);
}

__global__ void x_update_kernel(const float* __restrict__ Dz,
                                const float* __restrict__ s,
                                float* __restrict__ x, __half* __restrict__ xh)
{
    int n = blockIdx.y;
    int d = blockIdx.x * 256 + threadIdx.x;
    size_t idx = (size_t)n * DIN_ + d;
    float nv = x[idx] - s[n] * Dz[idx];
    x[idx]  = nv;
    xh[idx] = __float2half(nv);
}

/* ---------------- top-32 per row (iterative argmax over smem row) -------- */
__global__ void topk_kernel(const float* __restrict__ z,
                            float* __restrict__ tv, int* __restrict__ ti)
{
    extern __shared__ float sh[];
    __shared__ float rv[256];
    __shared__ int   ri[256];
    int row = blockIdx.x, tid = threadIdx.x;
    const float* zr = z + (size_t)row * Ww;
    for (int i = tid; i < Ww; i += 256) sh[i] = zr[i];
    __syncthreads();
    for (int it = 0; it < TOPK; it++) {
        float bm = -1.f; int bi = 0;
        for (int i = tid; i < Ww; i += 256) {
            float v = sh[i];
            if (v > bm) { bm = v; bi = i; }
        }
        rv[tid] = bm; ri[tid] = bi;
        __syncthreads();
        for (int sred = 128; sred > 0; sred >>= 1) {
            if (tid < sred) {
                float v2 = rv[tid + sred]; int i2 = ri[tid + sred];
                if (v2 > rv[tid] || (v2 == rv[tid] && i2 < ri[tid])) {
                    rv[tid] = v2; ri[tid] = i2;
                }
            }
            __syncthreads();
        }
        if (tid == 0) {
            tv[row * TOPK + it] = rv[0];
            ti[row * TOPK + it] = ri[0];
            sh[ri[0]] = -2.f;
        }
        __syncthreads();
    }
}

/* ---------------- sparse rank-32 add into recon output ------------------- */
__global__ void sparse_add_kernel(const float* __restrict__ tv,
                                  const int* __restrict__ ti,
                                  const float* __restrict__ D,
                                  float* __restrict__ out)
{
    __shared__ float sv[TOPK];
    __shared__ int   si[TOPK];
    int row = blockIdx.x, tid = threadIdx.x;
    if (tid < TOPK) { sv[tid] = tv[row * TOPK + tid]; si[tid] = ti[row * TOPK + tid]; }
    __syncthreads();
    for (int d = tid; d < DIN_; d += 256) {
        float a = out[(size_t)row * DIN_ + d];
#pragma unroll
        for (int j = 0; j < TOPK; j++)
            a += sv[j] * D[(size_t)si[j] * DIN_ + d];
        out[(size_t)row * DIN_ + d] = a;
    }
}

/* ---------------- driver -------------------------------------------------- */
extern "C" void kernel_launch(void* const* d_in, const int* in_sizes, int n_in,
                              void* d_out, int out_size)
{
    const float* x_in = (const float*)d_in[0];
    const float* D    = (const float*)d_in[1];
    const float* b    = (const float*)d_in[2];
    const float* Wq   = (const float*)d_in[3];
    const float* bq   = (const float*)d_in[4];
    const float* Wk   = (const float*)d_in[5];
    const float* bk   = (const float*)d_in[6];
    const float* Wv   = (const float*)d_in[7];
    const float* bv   = (const float*)d_in[8];
    const float* Wo   = (const float*)d_in[9];
    const float* bo   = (const float*)d_in[10];
    float* out = (float*)d_out;

    float  *px, *pz, *pzp, *pq, *pk, *pv, *pdz, *ps, *ptv;
    int    *pti;
    __half *pxh, *pzh, *pzph, *poh, *pDh, *pDTh, *pWqT, *pWkT, *pWvT, *pWoT;
    cudaGetSymbolAddress((void**)&px,   g_x);
    cudaGetSymbolAddress((void**)&pz,   g_z);
    cudaGetSymbolAddress((void**)&pzp,  g_zpred);
    cudaGetSymbolAddress((void**)&pq,   g_q);
    cudaGetSymbolAddress((void**)&pk,   g_k);
    cudaGetSymbolAddress((void**)&pv,   g_v);
    cudaGetSymbolAddress((void**)&pdz,  g_Dz);
    cudaGetSymbolAddress((void**)&ps,   g_s);
    cudaGetSymbolAddress((void**)&ptv,  g_tv);
    cudaGetSymbolAddress((void**)&pti,  g_ti);
    cudaGetSymbolAddress((void**)&pxh,  g_xh);
    cudaGetSymbolAddress((void**)&pzh,  g_zh);
    cudaGetSymbolAddress((void**)&pzph, g_zph);
    cudaGetSymbolAddress((void**)&poh,  g_oh);
    cudaGetSymbolAddress((void**)&pDh,  g_Dh);
    cudaGetSymbolAddress((void**)&pDTh, g_DTh);
    cudaGetSymbolAddress((void**)&pWqT, g_WqT);
    cudaGetSymbolAddress((void**)&pWkT, g_WkT);
    cudaGetSymbolAddress((void**)&pWvT, g_WvT);
    cudaGetSymbolAddress((void**)&pWoT, g_WoT);

    cudaFuncSetAttribute(topk_kernel,
                         cudaFuncAttributeMaxDynamicSharedMemorySize,
                         Ww * (int)sizeof(float));

    dim3 blk(256);

    /* ---- per-launch weight conversions (graph-capturable) ---- */
    cvt_kernel<<<(Ww * DIN_) / 256, blk>>>(D, pDh);
    cvtT_kernel<<<dim3(DIN_ / 32, Ww / 32), blk>>>(D, pDTh, Ww, DIN_);
    for (int i = 0; i < NLAY; i++) {
        cvtT_kernel<<<dim3(DBb / 32, Ww / 32), blk>>>(Wq + (size_t)i * Ww * DBb,
                                                      pWqT + (size_t)i * DBb * Ww, Ww, DBb);
        cvtT_kernel<<<dim3(DBb / 32, Ww / 32), blk>>>(Wk + (size_t)i * Ww * DBb,
                                                      pWkT + (size_t)i * DBb * Ww, Ww, DBb);
        cvtT_kernel<<<dim3(DBb / 32, Ww / 32), blk>>>(Wv + (size_t)i * Ww * DBb,
                                                      pWvT + (size_t)i * DBb * Ww, Ww, DBb);
        cvtT_kernel<<<dim3(Ww / 32, DBb / 32), blk>>>(Wo + (size_t)i * DBb * Ww,
                                                      pWoT + (size_t)i * Ww * DBb, DBb, Ww);
    }

    /* x = x_input - b  (fp32 + half) */
    sub_bias_kernel<<<dim3(DIN_ / 256, NROWS), blk>>>(x_in, b, px, pxh);

    for (int i = 0; i < NLAY; i++) {
        /* z_in = relu(LAM * x @ D^T)  -> half only */
        gemm_tc<<<dim3(Ww / 128, NROWS / 128), blk, SMEM_GEMM>>>(
            pxh, pDh, nullptr, nullptr, pzh, Ww, DIN_, DIN_, DIN_, LAMBDA, 1 | 4 | 8, 0);

        /* fused q / k / v */
        gemm_qkv<<<dim3((DBb + 127) / 128, NROWS / 128, 3), blk, SMEM_GEMM>>>(
            pzh,
            pWqT + (size_t)i * DBb * Ww, pWkT + (size_t)i * DBb * Ww, pWvT + (size_t)i * DBb * Ww,
            bq + (size_t)i * DBb, bk + (size_t)i * DBb, bv + (size_t)i * DBb,
            pq, pk, pv);

        attn_kernel<<<dim3(Ll / 128, Hh, Bb), dim3(128)>>>(pq, pk, pv, poh);

        /* z_pred_ = relu(o @ Wo + bo)  -> fp32 (pz) + half (pzh) */
        gemm_tc<<<dim3(Ww / 128, NROWS / 128), blk, SMEM_GEMM>>>(
            poh, pWoT + (size_t)i * Ww * DBb, bo + (size_t)i * Ww, pz, pzh,
            Ww, DBb, DBb, DBb, 1.f, 1 | 2 | 4, 0);

        /* Dz = z_pred_ @ D */
        gemm_tc<<<dim3(DIN_ / 128, NROWS / 128), blk, SMEM_GEMM>>>(
            pzh, pDTh, nullptr, pdz, nullptr, DIN_, Ww, Ww, Ww, 1.f, 0, 0);

        rowstats_kernel<<<NROWS, 256>>>(pdz, px, ps);
        zpred_update_kernel<<<dim3(Ww / 256, NROWS), blk>>>(pz, ps, pzp, pzph, i == 0);
        x_update_kernel<<<dim3(DIN_ / 256, NROWS), blk>>>(pdz, ps, px, pxh);
    }

    /* z_novel = relu(LAM * x @ D^T)  -> fp32 (topk input) */
    gemm_tc<<<dim3(Ww / 128, NROWS / 128), blk, SMEM_GEMM>>>(
        pxh, pDh, nullptr, pz, nullptr, Ww, DIN_, DIN_, DIN_, LAMBDA, 1, 0);

    topk_kernel<<<NROWS, 256, Ww * (int)sizeof(float)>>>(pz, ptv, pti);

    /* out = z_pred @ D + b, then add top-32 sparse codes */
    gemm_tc<<<dim3(DIN_ / 128, NROWS / 128), blk, SMEM_GEMM>>>(
        pzph, pDTh, b, out, nullptr, DIN_, Ww, Ww, Ww, 1.f, 2, 0);

    sparse_add_kernel<<<NROWS, 256>>>(ptv, pti, D, out);
}

// round 15
// speedup vs baseline: 5.3566x; 1.0225x over previous
#include <cuda_runtime.h>
#include <cuda_fp16.h>
#include <math.h>
#include <stdint.h>

#define Bb   4
#define Ll   1024
#define DIN_ 768
#define Ww   12288
#define Hh   8
#define NLAY 2
#define DBb  192
#define HDd  24
#define TOPK 32
#define NROWS (Bb*Ll)          /* 4096 */
#define LAMBDA (1.0f/(4.0f*768.0f))

/* fp16 GEMM smem: rows of 32 halves stored as 16 u32 words + 2 pad = 18 */
#define RS16 18
#define TW16 (128*RS16)
#define SMEM_GEMM (4*TW16*4)    /* A0,A1,B0,B1 = 36864 B */

/* ---------------- scratch (device globals; no allocation allowed) -------- */
__device__ float  g_x[NROWS*DIN_];
__device__ float  g_z[NROWS*Ww];
__device__ float  g_zpred[NROWS*Ww];
__device__ float  g_q[NROWS*DBb];
__device__ float  g_k[NROWS*DBb];
__device__ float  g_v[NROWS*DBb];
__device__ float  g_Dz[NROWS*DIN_];
__device__ float  g_s[NROWS];
__device__ float  g_tv[NROWS*TOPK];
__device__ int    g_ti[NROWS*TOPK];
/* half-resident operands */
__device__ __half g_xh[NROWS*DIN_];
__device__ __half g_zh[NROWS*Ww];
__device__ __half g_zph[NROWS*Ww];
__device__ __half g_oh[NROWS*DBb];
__device__ __half g_Dh[Ww*DIN_];           /* D     [Ww, DIN_]  (encode B)  */
__device__ __half g_DTh[DIN_*Ww];          /* D^T   [DIN_, Ww]  (Dz/recon B)*/
__device__ __half g_WqT[NLAY*DBb*Ww];      /* Wq^T  [DBb, Ww]               */
__device__ __half g_WkT[NLAY*DBb*Ww];
__device__ __half g_WvT[NLAY*DBb*Ww];
__device__ __half g_WoT[NLAY*Ww*DBb];      /* Wo^T  [Ww, DBb]               */

/* ---------------- helpers ------------------------------------------------ */
__device__ __forceinline__ void mma16(float* c,
                                      uint32_t a0, uint32_t a1, uint32_t a2, uint32_t a3,
                                      uint32_t b0, uint32_t b1)
{
    asm volatile(
        "mma.sync.aligned.m16n8k16.row.col.f32.f16.f16.f32 "
        "{%0,%1,%2,%3},{%4,%5,%6,%7},{%8,%9},{%0,%1,%2,%3};"
        : "+f"(c[0]), "+f"(c[1]), "+f"(c[2]), "+f"(c[3])
        : "r"(a0), "r"(a1), "r"(a2), "r"(a3), "r"(b0), "r"(b1));
}

/* ---------------- pipelined fp16 GEMM core (all-NT, half operands) --------
   C[M,N] = epilogue(alpha * A x B^T_layout)   A: [M,K] half, B: [N,K] half
   flags: bit0 relu, bit1 bias, bit2 write half Ch, bit3 skip fp32 C
   shiftA: row gm of A reads A[gm-1] (zeros when gm % Ll == 0)               */
__device__ __forceinline__ void gemm_core(
    int m0, int n0,
    const __half* __restrict__ A, const __half* __restrict__ B,
    const float* __restrict__ bias, float* __restrict__ C, __half* __restrict__ Ch,
    int N, int K, int lda, int ldb, float alpha, int flags, int shiftA)
{
    extern __shared__ uint32_t dsm[];
    uint32_t* const A0 = dsm;
    uint32_t* const A1 = dsm + TW16;
    uint32_t* const B0 = dsm + 2 * TW16;
    uint32_t* const B1 = dsm + 3 * TW16;

    const int tid  = threadIdx.x;
    const int warp = tid >> 5, lane = tid & 31;
    const int g    = lane >> 2, tg = lane & 3;
    const int wm0  = (warp & 1) * 64;
    const int wn0  = (warp >> 1) * 32;

    const int lr2 = tid >> 3;          /* 0..31 */
    const int lt  = tid & 7;           /* halves 4lt..4lt+3 = pairs 2lt,2lt+1 */
    const int ltc   = lt & 3;
    const int wbase = 8 * (lt >> 2) + (ltc & 1) * 4 + (ltc >> 1);

    float acc[4][4][4];
#pragma unroll
    for (int mf = 0; mf < 4; mf++)
#pragma unroll
        for (int nf = 0; nf < 4; nf++)
#pragma unroll
            for (int e = 0; e < 4; e++) acc[mf][nf][e] = 0.f;

    uint2 ra[4], rb[4];

    auto ldA = [&](int k0) {
#pragma unroll
        for (int i = 0; i < 4; i++) {
            int gm = m0 + lr2 + i * 32;
            uint2 av = make_uint2(0u, 0u);
            if (shiftA) {
                if ((gm & (Ll - 1)) != 0)
                    av = *reinterpret_cast<const uint2*>(&A[(size_t)(gm - 1) * lda + k0 + lt * 4]);
            } else {
                av = *reinterpret_cast<const uint2*>(&A[(size_t)gm * lda + k0 + lt * 4]);
            }
            ra[i] = av;
        }
    };
    auto ldB = [&](int k0) {
#pragma unroll
        for (int i = 0; i < 4; i++) {
            int gn = n0 + lr2 + i * 32;
            uint2 bv = make_uint2(0u, 0u);
            if (gn < N)
                bv = *reinterpret_cast<const uint2*>(&B[(size_t)gn * ldb + k0 + lt * 4]);
            rb[i] = bv;
        }
    };
    auto stA = [&](uint32_t* As) {
#pragma unroll
        for (int i = 0; i < 4; i++) {
            uint32_t* dst = &As[(lr2 + i * 32) * RS16 + wbase];
            dst[0] = ra[i].x;
            dst[2] = ra[i].y;
        }
    };
    auto stB = [&](uint32_t* Bs) {
#pragma unroll
        for (int i = 0; i < 4; i++) {
            uint32_t* dst = &Bs[(lr2 + i * 32) * RS16 + wbase];
            dst[0] = rb[i].x;
            dst[2] = rb[i].y;
        }
    };
    auto compute = [&](const uint32_t* As, const uint32_t* Bs) {
#pragma unroll
        for (int c = 0; c < 2; c++) {
            const int base = c * 8 + 2 * tg;
            uint2 Bv[4];
#pragma unroll
            for (int nf = 0; nf < 4; nf++)
                Bv[nf] = *reinterpret_cast<const uint2*>(&Bs[(wn0 + nf * 8 + g) * RS16 + base]);
            uint2 Alo[4], Ahi[4];
#pragma unroll
            for (int mf = 0; mf < 4; mf++) {
                int r0 = wm0 + mf * 16 + g;
                Alo[mf] = *reinterpret_cast<const uint2*>(&As[r0 * RS16 + base]);
                Ahi[mf] = *reinterpret_cast<const uint2*>(&As[(r0 + 8) * RS16 + base]);
            }
#pragma unroll
            for (int mf = 0; mf < 4; mf++)
#pragma unroll
                for (int nf = 0; nf < 4; nf++)
                    mma16(acc[mf][nf],
                          Alo[mf].x, Ahi[mf].x, Alo[mf].y, Ahi[mf].y,
                          Bv[nf].x, Bv[nf].y);
        }
    };

    const int NTILES = K >> 5;
    ldA(0); ldB(0);
    stA(A0); stB(B0);
    __syncthreads();
    for (int t = 0; t < NTILES; t++) {
        const bool cur = (t & 1) != 0;
        const bool more = (t + 1 < NTILES);
        if (more) { ldA((t + 1) << 5); ldB((t + 1) << 5); }
        compute(cur ? A1 : A0, cur ? B1 : B0);
        if (more) {
            stA(cur ? A0 : A1);
            stB(cur ? B0 : B1);
            __syncthreads();
        }
    }

    /* ---- epilogue ---- */
#pragma unroll
    for (int mf = 0; mf < 4; mf++) {
#pragma unroll
        for (int nf = 0; nf < 4; nf++) {
            int gm = m0 + wm0 + mf * 16 + g;
            int gn = n0 + wn0 + nf * 8 + 2 * tg;
            if (gn < N) {
                float bsum  = (flags & 2) ? bias[gn] : 0.f;
                float bsum1 = (flags & 2) ? bias[gn + 1] : 0.f;
                float v0 = acc[mf][nf][0] * alpha + bsum;
                float v1 = acc[mf][nf][1] * alpha + bsum1;
                float v2 = acc[mf][nf][2] * alpha + bsum;
                float v3 = acc[mf][nf][3] * alpha + bsum1;
                if (flags & 1) {
                    v0 = fmaxf(v0, 0.f); v1 = fmaxf(v1, 0.f);
                    v2 = fmaxf(v2, 0.f); v3 = fmaxf(v3, 0.f);
                }
                if (!(flags & 8)) {
                    *reinterpret_cast<float2*>(&C[(size_t)gm * N + gn])       = make_float2(v0, v1);
                    *reinterpret_cast<float2*>(&C[(size_t)(gm + 8) * N + gn]) = make_float2(v2, v3);
                }
                if (flags & 4) {
                    *reinterpret_cast<__half2*>(&Ch[(size_t)gm * N + gn]) =
                        __floats2half2_rn(v0, v1);
                    *reinterpret_cast<__half2*>(&Ch[(size_t)(gm + 8) * N + gn]) =
                        __floats2half2_rn(v2, v3);
                }
            }
        }
    }
}

__global__ __launch_bounds__(256, 2)
void gemm_tc(const __half* __restrict__ A, const __half* __restrict__ B,
             const float* __restrict__ bias, float* __restrict__ C,
             __half* __restrict__ Ch,
             int N, int K, int lda, int ldb,
             float alpha, int flags, int shiftA)
{
    gemm_core(blockIdx.y * 128, blockIdx.x * 128,
              A, B, bias, C, Ch, N, K, lda, ldb, alpha, flags, shiftA);
}

/* fused q/k/v: blockIdx.z selects the matrix; k,v read shifted A rows */
__global__ __launch_bounds__(256, 2)
void gemm_qkv(const __half* __restrict__ zh,
              const __half* __restrict__ WqT, const __half* __restrict__ WkT,
              const __half* __restrict__ WvT,
              const float* __restrict__ bq, const float* __restrict__ bk,
              const float* __restrict__ bv,
              float* __restrict__ q, float* __restrict__ k, float* __restrict__ v)
{
    const __half* Bp; const float* bp; float* Cp; int shift;
    if (blockIdx.z == 0)      { Bp = WqT; bp = bq; Cp = q; shift = 0; }
    else if (blockIdx.z == 1) { Bp = WkT; bp = bk; Cp = k; shift = 1; }
    else                      { Bp = WvT; bp = bv; Cp = v; shift = 1; }
    gemm_core(blockIdx.y * 128, blockIdx.x * 128,
              zh, Bp, bp, Cp, nullptr, DBb, Ww, Ww, Ww, 1.f, 2, shift);
}

/* ---------------- conversion kernels ------------------------------------- */
__global__ void cvt_kernel(const float* __restrict__ src, __half* __restrict__ dst)
{
    size_t i = (size_t)blockIdx.x * 256 + threadIdx.x;
    dst[i] = __float2half(src[i]);
}

/* [R,C] fp32 -> [C,R] half, R,C multiples of 32 */
__global__ void cvtT_kernel(const float* __restrict__ src, __half* __restrict__ dst,
                            int R, int C)
{
    __shared__ float t[32][33];
    int c0 = blockIdx.x * 32, r0 = blockIdx.y * 32;
    int tx = threadIdx.x & 31, ty = threadIdx.x >> 5;
#pragma unroll
    for (int j = 0; j < 4; j++)
        t[ty + 8 * j][tx] = src[(size_t)(r0 + ty + 8 * j) * C + c0 + tx];
    __syncthreads();
#pragma unroll
    for (int j = 0; j < 4; j++)
        dst[(size_t)(c0 + ty + 8 * j) * R + r0 + tx] = __float2half(t[tx][ty + 8 * j]);
}

/* ---------------- causal flash attention v2 (HD=24, j-parity split) ------ */
__global__ __launch_bounds__(256)
void attn_kernel(const float* __restrict__ qb, const float* __restrict__ kb,
                 const float* __restrict__ vb, __half* __restrict__ ob)
{
    const int qt  = blockIdx.x, h = blockIdx.y, bz = blockIdx.z;
    const int tid = threadIdx.x;
    const int ql  = tid & 127;          /* q row within tile */
    const int par = tid >> 7;           /* 0: even j, 1: odd j */
    const int qi  = qt * 128 + ql;
    const size_t rowbase = ((size_t)bz * Ll) * DBb + (size_t)h * HDd;

    float qreg[HDd];
    const float* qp = qb + rowbase + (size_t)qi * DBb;
#pragma unroll
    for (int d = 0; d < HDd; d++) qreg[d] = qp[d];

    const float scale = rsqrtf((float)HDd);
    float m = -1e30f, l = 0.f, o[HDd];
#pragma unroll
    for (int d = 0; d < HDd; d++) o[d] = 0.f;

    __shared__ float Ks[128][HDd + 1];
    __shared__ float Vs[128][HDd + 1];
    __shared__ float Ms[128], Ls[128];
    __shared__ float Os[128][HDd];

    for (int kt = 0; kt <= qt; kt++) {
        for (int e = tid; e < 128 * HDd; e += 256) {
            int j = e / HDd, d = e - j * HDd;
            size_t gidx = rowbase + (size_t)(kt * 128 + j) * DBb + d;
            Ks[j][d] = kb[gidx];
            Vs[j][d] = vb[gidx];
        }
        __syncthreads();
        int jmax = min(128, qi - kt * 128 + 1);
        for (int j = par; j < jmax; j += 2) {
            float sdot = 0.f;
#pragma unroll
            for (int d = 0; d < HDd; d++) sdot += qreg[d] * Ks[j][d];
            sdot *= scale;
            float mn = fmaxf(m, sdot);
            float c  = __expf(m - mn);
            float p  = __expf(sdot - mn);
            l = l * c + p;
#pragma unroll
            for (int d = 0; d < HDd; d++) o[d] = o[d] * c + p * Vs[j][d];
            m = mn;
        }
        __syncthreads();
    }

    /* merge the two parity partials */
    if (par == 1) {
        Ms[ql] = m; Ls[ql] = l;
#pragma unroll
        for (int d = 0; d < HDd; d++) Os[ql][d] = o[d];
    }
    __syncthreads();
    if (par == 0) {
        float m2 = Ms[ql], l2 = Ls[ql];
        float mn = fmaxf(m, m2);
        float c1 = __expf(m - mn);
        float c2 = __expf(m2 - mn);
        float inv = 1.f / (l * c1 + l2 * c2);
        __half* op = ob + rowbase + (size_t)qi * DBb;
#pragma unroll
        for (int d = 0; d < HDd; d += 2) {
            float v0 = (o[d]     * c1 + Os[ql][d]     * c2) * inv;
            float v1 = (o[d + 1] * c1 + Os[ql][d + 1] * c2) * inv;
            *reinterpret_cast<__half2*>(&op[d]) = __floats2half2_rn(v0, v1);
        }
    }
}

/* ---------------- small element/row kernels ------------------------------ */
__global__ void sub_bias_kernel(const float* __restrict__ xin,
                                const float* __restrict__ b,
                                float* __restrict__ x, __half* __restrict__ xh)
{
    int n = blockIdx.y, d = blockIdx.x * 256 + threadIdx.x;
    float v = xin[(size_t)n * DIN_ + d] - b[d];
    x[(size_t)n * DIN_ + d]  = v;
    xh[(size_t)n * DIN_ + d] = __float2half(v);
}

__global__ void rowstats_kernel(const float* __restrict__ Dz,
                                const float* __restrict__ x,
                                float* __restrict__ s)
{
    int n = blockIdx.x, tid = threadIdx.x;
    const float* dzr = Dz + (size_t)n * DIN_;
    const float* xr  = x  + (size_t)n * DIN_;
    float ss = 0.f, dt = 0.f;
    for (int i = tid; i < DIN_; i += 256) {
        float d = dzr[i];
        ss += d * d;
        dt += d * xr[i];
    }
#pragma unroll
    for (int o = 16; o; o >>= 1) {
        ss += __shfl_down_sync(0xffffffffu, ss, o);
        dt += __shfl_down_sync(0xffffffffu, dt, o);
    }
    __shared__ float a1[8], a2[8];
    if ((tid & 31) == 0) { a1[tid >> 5] = ss; a2[tid >> 5] = dt; }
    __syncthreads();
    if (tid == 0) {
        float S = 0.f, T = 0.f;
#pragma unroll
        for (int i = 0; i < 8; i++) { S += a1[i]; T += a2[i]; }
        float nrm = sqrtf(S) + 1e-6f;
        s[n] = T / (nrm * nrm);
    }
}

__global__ void zpred_update_kernel(const float* __restrict__ zp_,
                                    const float* __restrict__ s,
                                    float* __restrict__ zpred,
                                    __half* __restrict__ zpredh, int first)
{
    int n = blockIdx.y;
    int w = blockIdx.x * 256 + threadIdx.x;
    size_t idx = (size_t)n * Ww + w;
    float v = s[n] * zp_[idx];
    float nv = first ? v : (zpred[idx] + v);
    zpred[idx]  = nv;
    zpredh[idx] = __float2half(nv);
}

__global__ void x_update_kernel(const float* __restrict__ Dz,
                                const float* __restrict__ s,
                                float* __restrict__ x, __half* __restrict__ xh)
{
    int n = blockIdx.y;
    int d = blockIdx.x * 256 + threadIdx.x;
    size_t idx = (size_t)n * DIN_ + d;
    float nv = x[idx] - s[n] * Dz[idx];
    x[idx]  = nv;
    xh[idx] = __float2half(nv);
}

/* ---------------- top-32 per row: exact radix-select ----------------------
   relu output >= 0, so uint bit order == float order. 4x8-bit histogram
   levels find the exact 32nd-largest bit pattern T and the number of
   boundary ties to keep; one ordered ballot/scan pass collects all v > T
   plus the lowest-index ties (matching jax top_k tie semantics).          */
__global__ __launch_bounds__(256)
void topk_kernel(const float* __restrict__ z,
                 float* __restrict__ tv, int* __restrict__ ti)
{
    extern __shared__ uint32_t sh[];            /* Ww uints */
    __shared__ int      hist[256];
    __shared__ uint32_t s_prefix;
    __shared__ int      s_need;
    __shared__ int      s_bg, s_be;
    __shared__ int      wsg[8], wse[8];

    const int row = blockIdx.x, tid = threadIdx.x;
    const int lane = tid & 31, wid = tid >> 5;
    const unsigned lmask = (1u << lane) - 1u;
    const float* zr = z + (size_t)row * Ww;

    for (int i = tid; i < Ww; i += 256) sh[i] = __float_as_uint(zr[i]);
    __syncthreads();

    uint32_t prefix = 0; int need = TOPK;
#pragma unroll
    for (int shift = 24; shift >= 0; shift -= 8) {
        hist[tid] = 0;
        __syncthreads();
        uint32_t maskhi = (shift == 24) ? 0u : (0xFFFFFFFFu << (shift + 8));
        for (int i = tid; i < Ww; i += 256) {
            uint32_t bbits = sh[i];
            if ((bbits & maskhi) == prefix)
                atomicAdd(&hist[(bbits >> shift) & 0xFF], 1);
        }
        __syncthreads();
        if (tid == 0) {
            int acc = 0, bin = 255;
            for (; bin > 0; bin--) {
                if (acc + hist[bin] >= need) break;
                acc += hist[bin];
            }
            s_need   = need - acc;
            s_prefix = prefix | ((uint32_t)bin << shift);
        }
        __syncthreads();
        prefix = s_prefix; need = s_need;
    }
    const uint32_t T = prefix;
    const int g_total = TOPK - need;     /* count of elements strictly > T  */

    if (tid == 0) { s_bg = 0; s_be = 0; }
    __syncthreads();

    for (int base = 0; base < Ww; base += 256) {
        uint32_t bbits = sh[base + tid];
        bool fg = (bbits > T);
        bool fe = (bbits == T);
        unsigned mg = __ballot_sync(0xffffffffu, fg);
        unsigned me = __ballot_sync(0xffffffffu, fe);
        if (lane == 0) { wsg[wid] = __popc(mg); wse[wid] = __popc(me); }
        __syncthreads();
        int og = 0, oe = 0;
        for (int w = 0; w < wid; w++) { og += wsg[w]; oe += wse[w]; }
        if (fg) {
            int slot = s_bg + og + __popc(mg & lmask);
            tv[row * TOPK + slot] = __uint_as_float(bbits);
            ti[row * TOPK + slot] = base + tid;
        }
        if (fe) {
            int r = s_be + oe + __popc(me & lmask);
            if (r < need) {
                int slot = g_total + r;
                tv[row * TOPK + slot] = __uint_as_float(bbits);
                ti[row * TOPK + slot] = base + tid;
            }
        }
        __syncthreads();
        if (tid == 0) {
            int tg = 0, te = 0;
#pragma unroll
            for (int w = 0; w < 8; w++) { tg += wsg[w]; te += wse[w]; }
            s_bg += tg; s_be += te;
        }
        __syncthreads();
    }
}

/* ---------------- sparse rank-32 add into recon output ------------------- */
__global__ void sparse_add_kernel(const float* __restrict__ tv,
                                  const int* __restrict__ ti,
                                  const float* __restrict__ D,
                                  float* __restrict__ out)
{
    __shared__ float sv[TOPK];
    __shared__ int   si[TOPK];
    int row = blockIdx.x, tid = threadIdx.x;
    if (tid < TOPK) { sv[tid] = tv[row * TOPK + tid]; si[tid] = ti[row * TOPK + tid]; }
    __syncthreads();
    for (int d = tid; d < DIN_; d += 256) {
        float a = out[(size_t)row * DIN_ + d];
#pragma unroll
        for (int j = 0; j < TOPK; j++)
            a += sv[j] * D[(size_t)si[j] * DIN_ + d];
        out[(size_t)row * DIN_ + d] = a;
    }
}

/* ---------------- driver -------------------------------------------------- */
extern "C" void kernel_launch(void* const* d_in, const int* in_sizes, int n_in,
                              void* d_out, int out_size)
{
    const float* x_in = (const float*)d_in[0];
    const float* D    = (const float*)d_in[1];
    const float* b    = (const float*)d_in[2];
    const float* Wq   = (const float*)d_in[3];
    const float* bq   = (const float*)d_in[4];
    const float* Wk   = (const float*)d_in[5];
    const float* bk   = (const float*)d_in[6];
    const float* Wv   = (const float*)d_in[7];
    const float* bv   = (const float*)d_in[8];
    const float* Wo   = (const float*)d_in[9];
    const float* bo   = (const float*)d_in[10];
    float* out = (float*)d_out;

    float  *px, *pz, *pzp, *pq, *pk, *pv, *pdz, *ps, *ptv;
    int    *pti;
    __half *pxh, *pzh, *pzph, *poh, *pDh, *pDTh, *pWqT, *pWkT, *pWvT, *pWoT;
    cudaGetSymbolAddress((void**)&px,   g_x);
    cudaGetSymbolAddress((void**)&pz,   g_z);
    cudaGetSymbolAddress((void**)&pzp,  g_zpred);
    cudaGetSymbolAddress((void**)&pq,   g_q);
    cudaGetSymbolAddress((void**)&pk,   g_k);
    cudaGetSymbolAddress((void**)&pv,   g_v);
    cudaGetSymbolAddress((void**)&pdz,  g_Dz);
    cudaGetSymbolAddress((void**)&ps,   g_s);
    cudaGetSymbolAddress((void**)&ptv,  g_tv);
    cudaGetSymbolAddress((void**)&pti,  g_ti);
    cudaGetSymbolAddress((void**)&pxh,  g_xh);
    cudaGetSymbolAddress((void**)&pzh,  g_zh);
    cudaGetSymbolAddress((void**)&pzph, g_zph);
    cudaGetSymbolAddress((void**)&poh,  g_oh);
    cudaGetSymbolAddress((void**)&pDh,  g_Dh);
    cudaGetSymbolAddress((void**)&pDTh, g_DTh);
    cudaGetSymbolAddress((void**)&pWqT, g_WqT);
    cudaGetSymbolAddress((void**)&pWkT, g_WkT);
    cudaGetSymbolAddress((void**)&pWvT, g_WvT);
    cudaGetSymbolAddress((void**)&pWoT, g_WoT);

    cudaFuncSetAttribute(topk_kernel,
                         cudaFuncAttributeMaxDynamicSharedMemorySize,
                         Ww * (int)sizeof(float));

    dim3 blk(256);

    /* ---- per-launch weight conversions (graph-capturable) ---- */
    cvt_kernel<<<(Ww * DIN_) / 256, blk>>>(D, pDh);
    cvtT_kernel<<<dim3(DIN_ / 32, Ww / 32), blk>>>(D, pDTh, Ww, DIN_);
    for (int i = 0; i < NLAY; i++) {
        cvtT_kernel<<<dim3(DBb / 32, Ww / 32), blk>>>(Wq + (size_t)i * Ww * DBb,
                                                      pWqT + (size_t)i * DBb * Ww, Ww, DBb);
        cvtT_kernel<<<dim3(DBb / 32, Ww / 32), blk>>>(Wk + (size_t)i * Ww * DBb,
                                                      pWkT + (size_t)i * DBb * Ww, Ww, DBb);
        cvtT_kernel<<<dim3(DBb / 32, Ww / 32), blk>>>(Wv + (size_t)i * Ww * DBb,
                                                      pWvT + (size_t)i * DBb * Ww, Ww, DBb);
        cvtT_kernel<<<dim3(Ww / 32, DBb / 32), blk>>>(Wo + (size_t)i * DBb * Ww,
                                                      pWoT + (size_t)i * Ww * DBb, DBb, Ww);
    }

    /* x = x_input - b  (fp32 + half) */
    sub_bias_kernel<<<dim3(DIN_ / 256, NROWS), blk>>>(x_in, b, px, pxh);

    for (int i = 0; i < NLAY; i++) {
        /* z_in = relu(LAM * x @ D^T)  -> half only */
        gemm_tc<<<dim3(Ww / 128, NROWS / 128), blk, SMEM_GEMM>>>(
            pxh, pDh, nullptr, nullptr, pzh, Ww, DIN_, DIN_, DIN_, LAMBDA, 1 | 4 | 8, 0);

        /* fused q / k / v */
        gemm_qkv<<<dim3((DBb + 127) / 128, NROWS / 128, 3), blk, SMEM_GEMM>>>(
            pzh,
            pWqT + (size_t)i * DBb * Ww, pWkT + (size_t)i * DBb * Ww, pWvT + (size_t)i * DBb * Ww,
            bq + (size_t)i * DBb, bk + (size_t)i * DBb, bv + (size_t)i * DBb,
            pq, pk, pv);

        attn_kernel<<<dim3(Ll / 128, Hh, Bb), dim3(256)>>>(pq, pk, pv, poh);

        /* z_pred_ = relu(o @ Wo + bo)  -> fp32 (pz) + half (pzh) */
        gemm_tc<<<dim3(Ww / 128, NROWS / 128), blk, SMEM_GEMM>>>(
            poh, pWoT + (size_t)i * Ww * DBb, bo + (size_t)i * Ww, pz, pzh,
            Ww, DBb, DBb, DBb, 1.f, 1 | 2 | 4, 0);

        /* Dz = z_pred_ @ D */
        gemm_tc<<<dim3(DIN_ / 128, NROWS / 128), blk, SMEM_GEMM>>>(
            pzh, pDTh, nullptr, pdz, nullptr, DIN_, Ww, Ww, Ww, 1.f, 0, 0);

        rowstats_kernel<<<NROWS, 256>>>(pdz, px, ps);
        zpred_update_kernel<<<dim3(Ww / 256, NROWS), blk>>>(pz, ps, pzp, pzph, i == 0);
        x_update_kernel<<<dim3(DIN_ / 256, NROWS), blk>>>(pdz, ps, px, pxh);
    }

    /* z_novel = relu(LAM * x @ D^T)  -> fp32 (topk input) */
    gemm_tc<<<dim3(Ww / 128, NROWS / 128), blk, SMEM_GEMM>>>(
        pxh, pDh, nullptr, pz, nullptr, Ww, DIN_, DIN_, DIN_, LAMBDA, 1, 0);

    topk_kernel<<<NROWS, 256, Ww * (int)sizeof(float)>>>(pz, ptv, pti);

    /* out = z_pred @ D + b, then add top-32 sparse codes */
    gemm_tc<<<dim3(DIN_ / 128, NROWS / 128), blk, SMEM_GEMM>>>(
        pzph, pDTh, b, out, nullptr, DIN_, Ww, Ww, Ww, 1.f, 2, 0);

    sparse_add_kernel<<<NROWS, 256>>>(ptv, pti, D, out);
}

// round 17
// speedup vs baseline: 6.3537x; 1.1862x over previous
#include <cuda_runtime.h>
#include <cuda_fp16.h>
#include <math.h>
#include <stdint.h>

#define Bb   4
#define Ll   1024
#define DIN_ 768
#define Ww   12288
#define Hh   8
#define NLAY 2
#define DBb  192
#define HDd  24
#define TOPK 32
#define NROWS (Bb*Ll)          /* 4096 */
#define LAMBDA (1.0f/(4.0f*768.0f))

/* fp16 GEMM smem: rows of 32 halves stored as 16 u32 words + 2 pad = 18 */
#define RS16 18
#define TW16 (128*RS16)
#define SMEM_GEMM (4*TW16*4)    /* A0,A1,B0,B1 = 36864 B */

/* ---------------- scratch (device globals; no allocation allowed) -------- */
__device__ float  g_x[NROWS*DIN_];
__device__ float  g_z[NROWS*Ww];
__device__ float  g_q[NROWS*DBb];
__device__ float  g_k[NROWS*DBb];
__device__ float  g_v[NROWS*DBb];
__device__ float  g_Dz[NROWS*DIN_];
__device__ float  g_s[NROWS];
__device__ float  g_tv[NROWS*TOPK];
__device__ int    g_ti[NROWS*TOPK];
/* half-resident operands */
__device__ __half g_xh[NROWS*DIN_];
__device__ __half g_zh[NROWS*Ww];
__device__ __half g_oh[NROWS*DBb];
__device__ __half g_Dh[Ww*DIN_];           /* D     [Ww, DIN_]  (encode B)  */
__device__ __half g_DTh[DIN_*Ww];          /* D^T   [DIN_, Ww]  (Dz B)      */
__device__ __half g_WqT[NLAY*DBb*Ww];      /* Wq^T  [DBb, Ww]               */
__device__ __half g_WkT[NLAY*DBb*Ww];
__device__ __half g_WvT[NLAY*DBb*Ww];
__device__ __half g_WoT[NLAY*Ww*DBb];      /* Wo^T  [Ww, DBb]               */

/* ---------------- helpers ------------------------------------------------ */
__device__ __forceinline__ void mma16(float* c,
                                      uint32_t a0, uint32_t a1, uint32_t a2, uint32_t a3,
                                      uint32_t b0, uint32_t b1)
{
    asm volatile(
        "mma.sync.aligned.m16n8k16.row.col.f32.f16.f16.f32 "
        "{%0,%1,%2,%3},{%4,%5,%6,%7},{%8,%9},{%0,%1,%2,%3};"
        : "+f"(c[0]), "+f"(c[1]), "+f"(c[2]), "+f"(c[3])
        : "r"(a0), "r"(a1), "r"(a2), "r"(a3), "r"(b0), "r"(b1));
}

/* ---------------- pipelined fp16 GEMM core (all-NT, half operands) --------
   C[M,N] = epilogue(alpha * A x B^T_layout)   A: [M,K] half, B: [N,K] half
   flags: bit0 relu, bit1 bias, bit2 write half Ch, bit3 skip fp32 C
   shiftA: row gm of A reads A[gm-1] (zeros when gm % Ll == 0)               */
__device__ __forceinline__ void gemm_core(
    int m0, int n0,
    const __half* __restrict__ A, const __half* __restrict__ B,
    const float* __restrict__ bias, float* __restrict__ C, __half* __restrict__ Ch,
    int N, int K, int lda, int ldb, float alpha, int flags, int shiftA)
{
    extern __shared__ uint32_t dsm[];
    uint32_t* const A0 = dsm;
    uint32_t* const A1 = dsm + TW16;
    uint32_t* const B0 = dsm + 2 * TW16;
    uint32_t* const B1 = dsm + 3 * TW16;

    const int tid  = threadIdx.x;
    const int warp = tid >> 5, lane = tid & 31;
    const int g    = lane >> 2, tg = lane & 3;
    const int wm0  = (warp & 1) * 64;
    const int wn0  = (warp >> 1) * 32;

    const int lr2 = tid >> 3;          /* 0..31 */
    const int lt  = tid & 7;           /* halves 4lt..4lt+3 = pairs 2lt,2lt+1 */
    const int ltc   = lt & 3;
    const int wbase = 8 * (lt >> 2) + (ltc & 1) * 4 + (ltc >> 1);

    float acc[4][4][4];
#pragma unroll
    for (int mf = 0; mf < 4; mf++)
#pragma unroll
        for (int nf = 0; nf < 4; nf++)
#pragma unroll
            for (int e = 0; e < 4; e++) acc[mf][nf][e] = 0.f;

    uint2 ra[4], rb[4];

    auto ldA = [&](int k0) {
#pragma unroll
        for (int i = 0; i < 4; i++) {
            int gm = m0 + lr2 + i * 32;
            uint2 av = make_uint2(0u, 0u);
            if (shiftA) {
                if ((gm & (Ll - 1)) != 0)
                    av = *reinterpret_cast<const uint2*>(&A[(size_t)(gm - 1) * lda + k0 + lt * 4]);
            } else {
                av = *reinterpret_cast<const uint2*>(&A[(size_t)gm * lda + k0 + lt * 4]);
            }
            ra[i] = av;
        }
    };
    auto ldB = [&](int k0) {
#pragma unroll
        for (int i = 0; i < 4; i++) {
            int gn = n0 + lr2 + i * 32;
            uint2 bv = make_uint2(0u, 0u);
            if (gn < N)
                bv = *reinterpret_cast<const uint2*>(&B[(size_t)gn * ldb + k0 + lt * 4]);
            rb[i] = bv;
        }
    };
    auto stA = [&](uint32_t* As) {
#pragma unroll
        for (int i = 0; i < 4; i++) {
            uint32_t* dst = &As[(lr2 + i * 32) * RS16 + wbase];
            dst[0] = ra[i].x;
            dst[2] = ra[i].y;
        }
    };
    auto stB = [&](uint32_t* Bs) {
#pragma unroll
        for (int i = 0; i < 4; i++) {
            uint32_t* dst = &Bs[(lr2 + i * 32) * RS16 + wbase];
            dst[0] = rb[i].x;
            dst[2] = rb[i].y;
        }
    };
    auto compute = [&](const uint32_t* As, const uint32_t* Bs) {
#pragma unroll
        for (int c = 0; c < 2; c++) {
            const int base = c * 8 + 2 * tg;
            uint2 Bv[4];
#pragma unroll
            for (int nf = 0; nf < 4; nf++)
                Bv[nf] = *reinterpret_cast<const uint2*>(&Bs[(wn0 + nf * 8 + g) * RS16 + base]);
            uint2 Alo[4], Ahi[4];
#pragma unroll
            for (int mf = 0; mf < 4; mf++) {
                int r0 = wm0 + mf * 16 + g;
                Alo[mf] = *reinterpret_cast<const uint2*>(&As[r0 * RS16 + base]);
                Ahi[mf] = *reinterpret_cast<const uint2*>(&As[(r0 + 8) * RS16 + base]);
            }
#pragma unroll
            for (int mf = 0; mf < 4; mf++)
#pragma unroll
                for (int nf = 0; nf < 4; nf++)
                    mma16(acc[mf][nf],
                          Alo[mf].x, Ahi[mf].x, Alo[mf].y, Ahi[mf].y,
                          Bv[nf].x, Bv[nf].y);
        }
    };

    const int NTILES = K >> 5;
    ldA(0); ldB(0);
    stA(A0); stB(B0);
    __syncthreads();
    for (int t = 0; t < NTILES; t++) {
        const bool cur = (t & 1) != 0;
        const bool more = (t + 1 < NTILES);
        if (more) { ldA((t + 1) << 5); ldB((t + 1) << 5); }
        compute(cur ? A1 : A0, cur ? B1 : B0);
        if (more) {
            stA(cur ? A0 : A1);
            stB(cur ? B0 : B1);
            __syncthreads();
        }
    }

    /* ---- epilogue ---- */
#pragma unroll
    for (int mf = 0; mf < 4; mf++) {
#pragma unroll
        for (int nf = 0; nf < 4; nf++) {
            int gm = m0 + wm0 + mf * 16 + g;
            int gn = n0 + wn0 + nf * 8 + 2 * tg;
            if (gn < N) {
                float bsum  = (flags & 2) ? bias[gn] : 0.f;
                float bsum1 = (flags & 2) ? bias[gn + 1] : 0.f;
                float v0 = acc[mf][nf][0] * alpha + bsum;
                float v1 = acc[mf][nf][1] * alpha + bsum1;
                float v2 = acc[mf][nf][2] * alpha + bsum;
                float v3 = acc[mf][nf][3] * alpha + bsum1;
                if (flags & 1) {
                    v0 = fmaxf(v0, 0.f); v1 = fmaxf(v1, 0.f);
                    v2 = fmaxf(v2, 0.f); v3 = fmaxf(v3, 0.f);
                }
                if (!(flags & 8)) {
                    *reinterpret_cast<float2*>(&C[(size_t)gm * N + gn])       = make_float2(v0, v1);
                    *reinterpret_cast<float2*>(&C[(size_t)(gm + 8) * N + gn]) = make_float2(v2, v3);
                }
                if (flags & 4) {
                    *reinterpret_cast<__half2*>(&Ch[(size_t)gm * N + gn]) =
                        __floats2half2_rn(v0, v1);
                    *reinterpret_cast<__half2*>(&Ch[(size_t)(gm + 8) * N + gn]) =
                        __floats2half2_rn(v2, v3);
                }
            }
        }
    }
}

__global__ __launch_bounds__(256, 2)
void gemm_tc(const __half* __restrict__ A, const __half* __restrict__ B,
             const float* __restrict__ bias, float* __restrict__ C,
             __half* __restrict__ Ch,
             int N, int K, int lda, int ldb,
             float alpha, int flags, int shiftA)
{
    gemm_core(blockIdx.y * 128, blockIdx.x * 128,
              A, B, bias, C, Ch, N, K, lda, ldb, alpha, flags, shiftA);
}

/* fused q/k/v: blockIdx.z selects the matrix; k,v read shifted A rows */
__global__ __launch_bounds__(256, 2)
void gemm_qkv(const __half* __restrict__ zh,
              const __half* __restrict__ WqT, const __half* __restrict__ WkT,
              const __half* __restrict__ WvT,
              const float* __restrict__ bq, const float* __restrict__ bk,
              const float* __restrict__ bv,
              float* __restrict__ q, float* __restrict__ k, float* __restrict__ v)
{
    const __half* Bp; const float* bp; float* Cp; int shift;
    if (blockIdx.z == 0)      { Bp = WqT; bp = bq; Cp = q; shift = 0; }
    else if (blockIdx.z == 1) { Bp = WkT; bp = bk; Cp = k; shift = 1; }
    else                      { Bp = WvT; bp = bv; Cp = v; shift = 1; }
    gemm_core(blockIdx.y * 128, blockIdx.x * 128,
              zh, Bp, bp, Cp, nullptr, DBb, Ww, Ww, Ww, 1.f, 2, shift);
}

/* ---------------- conversion kernels ------------------------------------- */
__global__ void cvt_kernel(const float* __restrict__ src, __half* __restrict__ dst)
{
    size_t i = (size_t)blockIdx.x * 256 + threadIdx.x;
    dst[i] = __float2half(src[i]);
}

/* [R,C] fp32 -> [C,R] half, R,C multiples of 32 */
__global__ void cvtT_kernel(const float* __restrict__ src, __half* __restrict__ dst,
                            int R, int C)
{
    __shared__ float t[32][33];
    int c0 = blockIdx.x * 32, r0 = blockIdx.y * 32;
    int tx = threadIdx.x & 31, ty = threadIdx.x >> 5;
#pragma unroll
    for (int j = 0; j < 4; j++)
        t[ty + 8 * j][tx] = src[(size_t)(r0 + ty + 8 * j) * C + c0 + tx];
    __syncthreads();
#pragma unroll
    for (int j = 0; j < 4; j++)
        dst[(size_t)(c0 + ty + 8 * j) * R + r0 + tx] = __float2half(t[tx][ty + 8 * j]);
}

/* ---------------- causal flash attention v2 (HD=24, j-parity split) ------ */
__global__ __launch_bounds__(256)
void attn_kernel(const float* __restrict__ qb, const float* __restrict__ kb,
                 const float* __restrict__ vb, __half* __restrict__ ob)
{
    const int qt  = blockIdx.x, h = blockIdx.y, bz = blockIdx.z;
    const int tid = threadIdx.x;
    const int ql  = tid & 127;
    const int par = tid >> 7;
    const int qi  = qt * 128 + ql;
    const size_t rowbase = ((size_t)bz * Ll) * DBb + (size_t)h * HDd;

    float qreg[HDd];
    const float* qp = qb + rowbase + (size_t)qi * DBb;
#pragma unroll
    for (int d = 0; d < HDd; d++) qreg[d] = qp[d];

    const float scale = rsqrtf((float)HDd);
    float m = -1e30f, l = 0.f, o[HDd];
#pragma unroll
    for (int d = 0; d < HDd; d++) o[d] = 0.f;

    __shared__ float Ks[128][HDd + 1];
    __shared__ float Vs[128][HDd + 1];
    __shared__ float Ms[128], Ls[128];
    __shared__ float Os[128][HDd];

    for (int kt = 0; kt <= qt; kt++) {
        for (int e = tid; e < 128 * HDd; e += 256) {
            int j = e / HDd, d = e - j * HDd;
            size_t gidx = rowbase + (size_t)(kt * 128 + j) * DBb + d;
            Ks[j][d] = kb[gidx];
            Vs[j][d] = vb[gidx];
        }
        __syncthreads();
        int jmax = min(128, qi - kt * 128 + 1);
        for (int j = par; j < jmax; j += 2) {
            float sdot = 0.f;
#pragma unroll
            for (int d = 0; d < HDd; d++) sdot += qreg[d] * Ks[j][d];
            sdot *= scale;
            float mn = fmaxf(m, sdot);
            float c  = __expf(m - mn);
            float p  = __expf(sdot - mn);
            l = l * c + p;
#pragma unroll
            for (int d = 0; d < HDd; d++) o[d] = o[d] * c + p * Vs[j][d];
            m = mn;
        }
        __syncthreads();
    }

    if (par == 1) {
        Ms[ql] = m; Ls[ql] = l;
#pragma unroll
        for (int d = 0; d < HDd; d++) Os[ql][d] = o[d];
    }
    __syncthreads();
    if (par == 0) {
        float m2 = Ms[ql], l2 = Ls[ql];
        float mn = fmaxf(m, m2);
        float c1 = __expf(m - mn);
        float c2 = __expf(m2 - mn);
        float inv = 1.f / (l * c1 + l2 * c2);
        __half* op = ob + rowbase + (size_t)qi * DBb;
#pragma unroll
        for (int d = 0; d < HDd; d += 2) {
            float v0 = (o[d]     * c1 + Os[ql][d]     * c2) * inv;
            float v1 = (o[d + 1] * c1 + Os[ql][d + 1] * c2) * inv;
            *reinterpret_cast<__half2*>(&op[d]) = __floats2half2_rn(v0, v1);
        }
    }
}

/* ---------------- small element/row kernels ------------------------------ */
__global__ void sub_bias_kernel(const float* __restrict__ xin,
                                const float* __restrict__ b,
                                float* __restrict__ x, __half* __restrict__ xh)
{
    int n = blockIdx.y, d = blockIdx.x * 256 + threadIdx.x;
    float v = xin[(size_t)n * DIN_ + d] - b[d];
    x[(size_t)n * DIN_ + d]  = v;
    xh[(size_t)n * DIN_ + d] = __float2half(v);
}

__global__ void rowstats_kernel(const float* __restrict__ Dz,
                                const float* __restrict__ x,
                                float* __restrict__ s)
{
    int n = blockIdx.x, tid = threadIdx.x;
    const float* dzr = Dz + (size_t)n * DIN_;
    const float* xr  = x  + (size_t)n * DIN_;
    float ss = 0.f, dt = 0.f;
    for (int i = tid; i < DIN_; i += 256) {
        float d = dzr[i];
        ss += d * d;
        dt += d * xr[i];
    }
#pragma unroll
    for (int o = 16; o; o >>= 1) {
        ss += __shfl_down_sync(0xffffffffu, ss, o);
        dt += __shfl_down_sync(0xffffffffu, dt, o);
    }
    __shared__ float a1[8], a2[8];
    if ((tid & 31) == 0) { a1[tid >> 5] = ss; a2[tid >> 5] = dt; }
    __syncthreads();
    if (tid == 0) {
        float S = 0.f, T = 0.f;
#pragma unroll
        for (int i = 0; i < 8; i++) { S += a1[i]; T += a2[i]; }
        float nrm = sqrtf(S) + 1e-6f;
        s[n] = T / (nrm * nrm);
    }
}

__global__ void x_update_kernel(const float* __restrict__ Dz,
                                const float* __restrict__ s,
                                float* __restrict__ x, __half* __restrict__ xh)
{
    int n = blockIdx.y;
    int d = blockIdx.x * 256 + threadIdx.x;
    size_t idx = (size_t)n * DIN_ + d;
    float nv = x[idx] - s[n] * Dz[idx];
    x[idx]  = nv;
    xh[idx] = __float2half(nv);
}

/* ---------------- top-32 per row: exact radix-select ---------------------- */
__global__ __launch_bounds__(256)
void topk_kernel(const float* __restrict__ z,
                 float* __restrict__ tv, int* __restrict__ ti)
{
    extern __shared__ uint32_t sh[];            /* Ww uints */
    __shared__ int      hist[256];
    __shared__ uint32_t s_prefix;
    __shared__ int      s_need;
    __shared__ int      s_bg, s_be;
    __shared__ int      wsg[8], wse[8];

    const int row = blockIdx.x, tid = threadIdx.x;
    const int lane = tid & 31, wid = tid >> 5;
    const unsigned lmask = (1u << lane) - 1u;
    const float* zr = z + (size_t)row * Ww;

    for (int i = tid; i < Ww; i += 256) sh[i] = __float_as_uint(zr[i]);
    __syncthreads();

    uint32_t prefix = 0; int need = TOPK;
#pragma unroll
    for (int shift = 24; shift >= 0; shift -= 8) {
        hist[tid] = 0;
        __syncthreads();
        uint32_t maskhi = (shift == 24) ? 0u : (0xFFFFFFFFu << (shift + 8));
        for (int i = tid; i < Ww; i += 256) {
            uint32_t bbits = sh[i];
            if ((bbits & maskhi) == prefix)
                atomicAdd(&hist[(bbits >> shift) & 0xFF], 1);
        }
        __syncthreads();
        if (tid == 0) {
            int acc = 0, bin = 255;
            for (; bin > 0; bin--) {
                if (acc + hist[bin] >= need) break;
                acc += hist[bin];
            }
            s_need   = need - acc;
            s_prefix = prefix | ((uint32_t)bin << shift);
        }
        __syncthreads();
        prefix = s_prefix; need = s_need;
    }
    const uint32_t T = prefix;
    const int g_total = TOPK - need;

    if (tid == 0) { s_bg = 0; s_be = 0; }
    __syncthreads();

    for (int base = 0; base < Ww; base += 256) {
        uint32_t bbits = sh[base + tid];
        bool fg = (bbits > T);
        bool fe = (bbits == T);
        unsigned mg = __ballot_sync(0xffffffffu, fg);
        unsigned me = __ballot_sync(0xffffffffu, fe);
        if (lane == 0) { wsg[wid] = __popc(mg); wse[wid] = __popc(me); }
        __syncthreads();
        int og = 0, oe = 0;
        for (int w = 0; w < wid; w++) { og += wsg[w]; oe += wse[w]; }
        if (fg) {
            int slot = s_bg + og + __popc(mg & lmask);
            tv[row * TOPK + slot] = __uint_as_float(bbits);
            ti[row * TOPK + slot] = base + tid;
        }
        if (fe) {
            int r = s_be + oe + __popc(me & lmask);
            if (r < need) {
                int slot = g_total + r;
                tv[row * TOPK + slot] = __uint_as_float(bbits);
                ti[row * TOPK + slot] = base + tid;
            }
        }
        __syncthreads();
        if (tid == 0) {
            int tg = 0, te = 0;
#pragma unroll
            for (int w = 0; w < 8; w++) { tg += wsg[w]; te += wse[w]; }
            s_bg += tg; s_be += te;
        }
        __syncthreads();
    }
}

/* ---------------- final combine: out = x_in - x_final + rank32(D) ---------
   Identity: z_pred @ D = sum_i s_i * Dz_i = x0 - x_final, so
   out = (z_novel + z_pred) @ D + b = x_input - x_final + z_novel @ D.       */
__global__ void final_kernel(const float* __restrict__ x_in,
                             const float* __restrict__ x,
                             const float* __restrict__ tv,
                             const int* __restrict__ ti,
                             const float* __restrict__ D,
                             float* __restrict__ out)
{
    __shared__ float sv[TOPK];
    __shared__ int   si[TOPK];
    int row = blockIdx.x, tid = threadIdx.x;
    if (tid < TOPK) { sv[tid] = tv[row * TOPK + tid]; si[tid] = ti[row * TOPK + tid]; }
    __syncthreads();
    for (int d = tid; d < DIN_; d += 256) {
        float a = x_in[(size_t)row * DIN_ + d] - x[(size_t)row * DIN_ + d];
#pragma unroll
        for (int j = 0; j < TOPK; j++)
            a += sv[j] * D[(size_t)si[j] * DIN_ + d];
        out[(size_t)row * DIN_ + d] = a;
    }
}

/* ---------------- driver -------------------------------------------------- */
extern "C" void kernel_launch(void* const* d_in, const int* in_sizes, int n_in,
                              void* d_out, int out_size)
{
    const float* x_in = (const float*)d_in[0];
    const float* D    = (const float*)d_in[1];
    const float* b    = (const float*)d_in[2];
    const float* Wq   = (const float*)d_in[3];
    const float* bq   = (const float*)d_in[4];
    const float* Wk   = (const float*)d_in[5];
    const float* bk   = (const float*)d_in[6];
    const float* Wv   = (const float*)d_in[7];
    const float* bv   = (const float*)d_in[8];
    const float* Wo   = (const float*)d_in[9];
    const float* bo   = (const float*)d_in[10];
    float* out = (float*)d_out;

    float  *px, *pz, *pq, *pk, *pv, *pdz, *ps, *ptv;
    int    *pti;
    __half *pxh, *pzh, *poh, *pDh, *pDTh, *pWqT, *pWkT, *pWvT, *pWoT;
    cudaGetSymbolAddress((void**)&px,   g_x);
    cudaGetSymbolAddress((void**)&pz,   g_z);
    cudaGetSymbolAddress((void**)&pq,   g_q);
    cudaGetSymbolAddress((void**)&pk,   g_k);
    cudaGetSymbolAddress((void**)&pv,   g_v);
    cudaGetSymbolAddress((void**)&pdz,  g_Dz);
    cudaGetSymbolAddress((void**)&ps,   g_s);
    cudaGetSymbolAddress((void**)&ptv,  g_tv);
    cudaGetSymbolAddress((void**)&pti,  g_ti);
    cudaGetSymbolAddress((void**)&pxh,  g_xh);
    cudaGetSymbolAddress((void**)&pzh,  g_zh);
    cudaGetSymbolAddress((void**)&poh,  g_oh);
    cudaGetSymbolAddress((void**)&pDh,  g_Dh);
    cudaGetSymbolAddress((void**)&pDTh, g_DTh);
    cudaGetSymbolAddress((void**)&pWqT, g_WqT);
    cudaGetSymbolAddress((void**)&pWkT, g_WkT);
    cudaGetSymbolAddress((void**)&pWvT, g_WvT);
    cudaGetSymbolAddress((void**)&pWoT, g_WoT);

    cudaFuncSetAttribute(topk_kernel,
                         cudaFuncAttributeMaxDynamicSharedMemorySize,
                         Ww * (int)sizeof(float));

    dim3 blk(256);

    /* ---- per-launch weight conversions (graph-capturable) ---- */
    cvt_kernel<<<(Ww * DIN_) / 256, blk>>>(D, pDh);
    cvtT_kernel<<<dim3(DIN_ / 32, Ww / 32), blk>>>(D, pDTh, Ww, DIN_);
    for (int i = 0; i < NLAY; i++) {
        cvtT_kernel<<<dim3(DBb / 32, Ww / 32), blk>>>(Wq + (size_t)i * Ww * DBb,
                                                      pWqT + (size_t)i * DBb * Ww, Ww, DBb);
        cvtT_kernel<<<dim3(DBb / 32, Ww / 32), blk>>>(Wk + (size_t)i * Ww * DBb,
                                                      pWkT + (size_t)i * DBb * Ww, Ww, DBb);
        cvtT_kernel<<<dim3(DBb / 32, Ww / 32), blk>>>(Wv + (size_t)i * Ww * DBb,
                                                      pWvT + (size_t)i * DBb * Ww, Ww, DBb);
        cvtT_kernel<<<dim3(Ww / 32, DBb / 32), blk>>>(Wo + (size_t)i * DBb * Ww,
                                                      pWoT + (size_t)i * Ww * DBb, DBb, Ww);
    }

    /* x = x_input - b  (fp32 + half) */
    sub_bias_kernel<<<dim3(DIN_ / 256, NROWS), blk>>>(x_in, b, px, pxh);

    for (int i = 0; i < NLAY; i++) {
        /* z_in = relu(LAM * x @ D^T)  -> half only */
        gemm_tc<<<dim3(Ww / 128, NROWS / 128), blk, SMEM_GEMM>>>(
            pxh, pDh, nullptr, nullptr, pzh, Ww, DIN_, DIN_, DIN_, LAMBDA, 1 | 4 | 8, 0);

        /* fused q / k / v */
        gemm_qkv<<<dim3((DBb + 127) / 128, NROWS / 128, 3), blk, SMEM_GEMM>>>(
            pzh,
            pWqT + (size_t)i * DBb * Ww, pWkT + (size_t)i * DBb * Ww, pWvT + (size_t)i * DBb * Ww,
            bq + (size_t)i * DBb, bk + (size_t)i * DBb, bv + (size_t)i * DBb,
            pq, pk, pv);

        attn_kernel<<<dim3(Ll / 128, Hh, Bb), dim3(256)>>>(pq, pk, pv, poh);

        /* z_pred_ = relu(o @ Wo + bo)  -> half only (only Dz consumes it) */
        gemm_tc<<<dim3(Ww / 128, NROWS / 128), blk, SMEM_GEMM>>>(
            poh, pWoT + (size_t)i * Ww * DBb, bo + (size_t)i * Ww, nullptr, pzh,
            Ww, DBb, DBb, DBb, 1.f, 1 | 2 | 4 | 8, 0);

        /* Dz = z_pred_ @ D */
        gemm_tc<<<dim3(DIN_ / 128, NROWS / 128), blk, SMEM_GEMM>>>(
            pzh, pDTh, nullptr, pdz, nullptr, DIN_, Ww, Ww, Ww, 1.f, 0, 0);

        rowstats_kernel<<<NROWS, 256>>>(pdz, px, ps);
        x_update_kernel<<<dim3(DIN_ / 256, NROWS), blk>>>(pdz, ps, px, pxh);
    }

    /* z_novel = relu(LAM * x @ D^T)  -> fp32 (topk input) */
    gemm_tc<<<dim3(Ww / 128, NROWS / 128), blk, SMEM_GEMM>>>(
        pxh, pDh, nullptr, pz, nullptr, Ww, DIN_, DIN_, DIN_, LAMBDA, 1, 0);

    topk_kernel<<<NROWS, 256, Ww * (int)sizeof(float)>>>(pz, ptv, pti);

    /* out = x_input - x_final + rank-32 sparse codes (recon GEMM eliminated) */
    final_kernel<<<NROWS, 256>>>(x_in, px, ptv, pti, D, out);
}